// round 6
// baseline (speedup 1.0000x reference)
#include <cuda_runtime.h>
#include <math.h>

#define DEV_INLINE __device__ __forceinline__

static const int D    = 128;
static const int LSEQ = 256;
static const int DK   = 16;
static const int DI   = 512;

// ------------------------- scratch (device globals) -------------------------
__device__ float g_side[12800000];   // side = A_in @ ego
__device__ float g_q [1048576];
__device__ float g_k [1048576];
__device__ float g_v [1048576];
__device__ float g_o [1048576];
__device__ float g_x1[1048576];
__device__ float g_x2[1048576];
__device__ float g_h [4194304];      // 8192 x 512

enum { BQ = 0, BK = 1, BV = 2, BO = 3, BX1 = 5, BX2 = 6, BH = 7 };

DEV_INLINE float* bufptr(int id) {
    switch (id) {
        case BQ:  return g_q;
        case BK:  return g_k;
        case BV:  return g_v;
        case BO:  return g_o;
        case BX1: return g_x1;
        case BX2: return g_x2;
        case BH:  return g_h;
    }
    return nullptr;
}

// ------------------------- f32x2 helpers -------------------------
DEV_INLINE unsigned long long pack2(float lo, float hi) {
    unsigned long long r;
    asm("mov.b64 %0, {%1, %2};" : "=l"(r) : "f"(lo), "f"(hi));
    return r;
}
DEV_INLINE void unpack2(unsigned long long v, float& lo, float& hi) {
    asm("mov.b64 {%0, %1}, %2;" : "=f"(lo), "=f"(hi) : "l"(v));
}
DEV_INLINE void ffma2(unsigned long long& d, unsigned long long a, unsigned long long b) {
    asm("fma.rn.f32x2 %0, %1, %2, %0;" : "+l"(d) : "l"(a), "l"(b));
}
DEV_INLINE void fmul2(unsigned long long& d, unsigned long long a, unsigned long long b) {
    asm("mul.rn.f32x2 %0, %1, %2;" : "=l"(d) : "l"(a), "l"(b));
}
DEV_INLINE void fadd2(unsigned long long& d, unsigned long long a, unsigned long long b) {
    asm("add.rn.f32x2 %0, %1, %2;" : "=l"(d) : "l"(a), "l"(b));
}

// ------------------------------ zero side ------------------------------
__global__ void zero_side_kernel(int n4) {
    float4* p = reinterpret_cast<float4*>(g_side);
    int i = blockIdx.x * blockDim.x + threadIdx.x;
    int stride = gridDim.x * blockDim.x;
    float4 z = make_float4(0.f, 0.f, 0.f, 0.f);
    for (; i < n4; i += stride) p[i] = z;
}

// ------------------------------ SpMM (COO, rows sorted) ------------------------------
static const int EPW = 256;

DEV_INLINE void spmm_flush(int row, int lane, float4 acc) {
    float* p = &g_side[(size_t)row * 128 + lane * 4];
    atomicAdd(p + 0, acc.x);
    atomicAdd(p + 1, acc.y);
    atomicAdd(p + 2, acc.z);
    atomicAdd(p + 3, acc.w);
}

__global__ void __launch_bounds__(256) spmm_kernel(
    const float* __restrict__ ego, const float* __restrict__ vals,
    const int* __restrict__ rows, const int* __restrict__ cols, int nnz)
{
    int warp = (blockIdx.x * blockDim.x + threadIdx.x) >> 5;
    int lane = threadIdx.x & 31;
    long e0 = (long)warp * EPW;
    if (e0 >= nnz) return;
    long e1 = e0 + EPW; if (e1 > nnz) e1 = nnz;

    const float4* ego4 = reinterpret_cast<const float4*>(ego);
    float4 acc = make_float4(0.f, 0.f, 0.f, 0.f);
    int cur = rows[e0];
    for (long e = e0; e < e1; e++) {
        int r = rows[e];
        if (r != cur) {
            spmm_flush(cur, lane, acc);
            acc = make_float4(0.f, 0.f, 0.f, 0.f);
            cur = r;
        }
        float v  = vals[e];
        float4 g = ego4[(size_t)cols[e] * 32 + lane];
        acc.x += v * g.x; acc.y += v * g.y; acc.z += v * g.z; acc.w += v * g.w;
    }
    spmm_flush(cur, lane, acc);
}

// ------------------------------ fused aggregator (dup-A scheme) ------------------------------
// out = leaky((ego+side)@W1+b1) + leaky((ego*side)@W2+b2), one pass.
// 256 thr, tile 64x128, K chunks of 16; A/P staged duplicated for packless FFMA2.
__global__ void __launch_bounds__(256) agg_fused_kernel(
    const float* __restrict__ ego,
    const float* __restrict__ W1, const float* __restrict__ b1,
    const float* __restrict__ W2, const float* __restrict__ b2,
    float* __restrict__ out, int M)
{
    __shared__ __align__(16) float W1s[16][128];
    __shared__ __align__(16) float W2s[16][128];
    __shared__ __align__(16) float As[16][128];   // dup: [k][2r],(a,a)
    __shared__ __align__(16) float Ps[16][128];

    int tid  = threadIdx.x;
    int lane = tid & 31, wy = tid >> 5;
    int c0   = lane * 4;
    int r0   = wy * 8;
    int row0 = blockIdx.x * 64;

    unsigned long long acc1[8][2], acc2[8][2];
    {
        float4 bv1 = *(const float4*)&b1[c0];
        float4 bv2 = *(const float4*)&b2[c0];
        unsigned long long p10 = pack2(bv1.x, bv1.y), p11 = pack2(bv1.z, bv1.w);
        unsigned long long p20 = pack2(bv2.x, bv2.y), p21 = pack2(bv2.z, bv2.w);
        #pragma unroll
        for (int r = 0; r < 8; r++) {
            acc1[r][0] = p10; acc1[r][1] = p11;
            acc2[r][0] = p20; acc2[r][1] = p21;
        }
    }

    for (int k0 = 0; k0 < 128; k0 += 16) {
        // stage W1/W2 [16][128]
        #pragma unroll
        for (int i = 0; i < 2; i++) {
            int idx = tid + i * 256;
            int k = idx >> 5, cg = idx & 31;
            *(float4*)&W1s[k][cg * 4] = *(const float4*)&W1[(size_t)(k0 + k) * 128 + cg * 4];
            *(float4*)&W2s[k][cg * 4] = *(const float4*)&W2[(size_t)(k0 + k) * 128 + cg * 4];
        }
        // stage A/P duplicated (computing e+sd, e*sd on the fly)
        {
            int r = tid & 63, kg = tid >> 6;   // kg 0..3 covers k 0..15
            int rr = row0 + r;
            float4 e = make_float4(0.f, 0.f, 0.f, 0.f);
            float4 sd = make_float4(0.f, 0.f, 0.f, 0.f);
            if (rr < M) {
                e  = *(const float4*)&ego   [(size_t)rr * 128 + k0 + kg * 4];
                sd = *(const float4*)&g_side[(size_t)rr * 128 + k0 + kg * 4];
            }
            float sv[4] = {e.x + sd.x, e.y + sd.y, e.z + sd.z, e.w + sd.w};
            float pv[4] = {e.x * sd.x, e.y * sd.y, e.z * sd.z, e.w * sd.w};
            #pragma unroll
            for (int j = 0; j < 4; j++) {
                *(float2*)&As[kg * 4 + j][2 * r] = make_float2(sv[j], sv[j]);
                *(float2*)&Ps[kg * 4 + j][2 * r] = make_float2(pv[j], pv[j]);
            }
        }
        __syncthreads();

        #pragma unroll 4
        for (int k = 0; k < 16; k++) {
            ulonglong2 w1p = *(const ulonglong2*)&W1s[k][c0];
            ulonglong2 w2p = *(const ulonglong2*)&W2s[k][c0];
            const ulonglong2* ap = (const ulonglong2*)&As[k][2 * r0];
            const ulonglong2* pp = (const ulonglong2*)&Ps[k][2 * r0];
            ulonglong2 a01 = ap[0], a23 = ap[1], a45 = ap[2], a67 = ap[3];
            ulonglong2 p01 = pp[0], p23 = pp[1], p45 = pp[2], p67 = pp[3];
            unsigned long long ad[8] = {a01.x, a01.y, a23.x, a23.y, a45.x, a45.y, a67.x, a67.y};
            unsigned long long pd[8] = {p01.x, p01.y, p23.x, p23.y, p45.x, p45.y, p67.x, p67.y};
            #pragma unroll
            for (int r = 0; r < 8; r++) {
                ffma2(acc1[r][0], ad[r], w1p.x);
                ffma2(acc1[r][1], ad[r], w1p.y);
                ffma2(acc2[r][0], pd[r], w2p.x);
                ffma2(acc2[r][1], pd[r], w2p.y);
            }
        }
        __syncthreads();
    }

    #pragma unroll
    for (int r = 0; r < 8; r++) {
        int rr = row0 + r0 + r;
        if (rr >= M) continue;
        float x0, x1, x2, x3, y0, y1, y2, y3;
        unpack2(acc1[r][0], x0, x1); unpack2(acc1[r][1], x2, x3);
        unpack2(acc2[r][0], y0, y1); unpack2(acc2[r][1], y2, y3);
        x0 = (x0 > 0.f) ? x0 : 0.01f * x0;  y0 = (y0 > 0.f) ? y0 : 0.01f * y0;
        x1 = (x1 > 0.f) ? x1 : 0.01f * x1;  y1 = (y1 > 0.f) ? y1 : 0.01f * y1;
        x2 = (x2 > 0.f) ? x2 : 0.01f * x2;  y2 = (y2 > 0.f) ? y2 : 0.01f * y2;
        x3 = (x3 > 0.f) ? x3 : 0.01f * x3;  y3 = (y3 > 0.f) ? y3 : 0.01f * y3;
        *(float4*)&out[(size_t)rr * 128 + c0] =
            make_float4(x0 + y0, x1 + y1, x2 + y2, x3 + y3);
    }
}

// ------------------------------ dup-A f32x2 GEMM core ------------------------------
// modes: 0 store(+bias), 1 relu(+bias), 5 +bias +residual +LayerNorm
// K chunks of 32; A staged duplicated so the inner loop has no register packing.
template<int K, int NOUT, int MT>
DEV_INLINE void gemm_core(const float* __restrict__ A, int astride,
                          const float* __restrict__ W,
                          const float* __restrict__ bias, const float* __restrict__ R,
                          const float* __restrict__ lnG, const float* __restrict__ lnB,
                          float* __restrict__ C, int M, int mode)
{
    constexpr int NTHR = MT * 4;
    __shared__ __align__(16) float Ws[32][128];
    __shared__ __align__(16) float As[32][2 * MT];   // duplicated

    int tid  = threadIdx.x;
    int lane = tid & 31, wy = tid >> 5;
    int c0   = lane * 4;
    int r0   = wy * 8;
    int row0 = blockIdx.x * MT;
    int cb   = (NOUT > 128) ? (blockIdx.y * 128) : 0;

    unsigned long long acc[8][2];
    {
        float4 bv = *(const float4*)&bias[cb + c0];
        unsigned long long b0 = pack2(bv.x, bv.y), b1 = pack2(bv.z, bv.w);
        #pragma unroll
        for (int r = 0; r < 8; r++) { acc[r][0] = b0; acc[r][1] = b1; }
    }

    for (int k0 = 0; k0 < K; k0 += 32) {
        // stage W [32][128]
        #pragma unroll
        for (int i = 0; i < 1024 / NTHR; i++) {
            int idx = tid + i * NTHR;
            int k = idx >> 5, cg = idx & 31;
            *(float4*)&Ws[k][cg * 4] =
                *(const float4*)&W[(size_t)(k0 + k) * NOUT + cb + cg * 4];
        }
        // stage A duplicated [32][2*MT]
        #pragma unroll
        for (int i = 0; i < (8 * MT) / NTHR; i++) {
            int idx = tid + i * NTHR;
            int r = idx % MT, kg = idx / MT;   // kg 0..7 covers k 0..31
            int rr = row0 + r;
            float4 av = make_float4(0.f, 0.f, 0.f, 0.f);
            if (rr < M) av = *(const float4*)&A[(size_t)rr * astride + k0 + kg * 4];
            *(float2*)&As[kg * 4 + 0][2 * r] = make_float2(av.x, av.x);
            *(float2*)&As[kg * 4 + 1][2 * r] = make_float2(av.y, av.y);
            *(float2*)&As[kg * 4 + 2][2 * r] = make_float2(av.z, av.z);
            *(float2*)&As[kg * 4 + 3][2 * r] = make_float2(av.w, av.w);
        }
        __syncthreads();

        #pragma unroll 4
        for (int k = 0; k < 32; k++) {
            ulonglong2 wp = *(const ulonglong2*)&Ws[k][c0];
            const ulonglong2* ap = (const ulonglong2*)&As[k][2 * r0];
            ulonglong2 a01 = ap[0], a23 = ap[1], a45 = ap[2], a67 = ap[3];
            unsigned long long ad[8] = {a01.x, a01.y, a23.x, a23.y,
                                        a45.x, a45.y, a67.x, a67.y};
            #pragma unroll
            for (int r = 0; r < 8; r++) {
                ffma2(acc[r][0], ad[r], wp.x);
                ffma2(acc[r][1], ad[r], wp.y);
            }
        }
        __syncthreads();
    }

    float4 g4 = make_float4(1.f, 1.f, 1.f, 1.f);
    float4 be4 = make_float4(0.f, 0.f, 0.f, 0.f);
    if (mode == 5) {
        g4  = *(const float4*)&lnG[c0];
        be4 = *(const float4*)&lnB[c0];
    }

    #pragma unroll
    for (int r = 0; r < 8; r++) {
        int rr = row0 + r0 + r;
        if (rr >= M) continue;
        size_t off = (size_t)rr * NOUT + cb + c0;
        float x0, x1, x2, x3;
        unpack2(acc[r][0], x0, x1);
        unpack2(acc[r][1], x2, x3);
        if (mode == 1) {
            x0 = fmaxf(x0, 0.f); x1 = fmaxf(x1, 0.f);
            x2 = fmaxf(x2, 0.f); x3 = fmaxf(x3, 0.f);
        } else if (mode == 5) {
            float4 rv = *(const float4*)&R[off];
            x0 += rv.x; x1 += rv.y; x2 += rv.z; x3 += rv.w;
            float s  = x0 + x1 + x2 + x3;
            float sq = x0 * x0 + x1 * x1 + x2 * x2 + x3 * x3;
            #pragma unroll
            for (int o = 16; o > 0; o >>= 1) {
                s  += __shfl_xor_sync(0xffffffff, s,  o);
                sq += __shfl_xor_sync(0xffffffff, sq, o);
            }
            float m   = s * (1.f / 128.f);
            float var = sq * (1.f / 128.f) - m * m;
            float rstd = rsqrtf(var + 1e-5f);
            x0 = (x0 - m) * rstd * g4.x + be4.x;
            x1 = (x1 - m) * rstd * g4.y + be4.y;
            x2 = (x2 - m) * rstd * g4.z + be4.z;
            x3 = (x3 - m) * rstd * g4.w + be4.w;
        }
        *(float4*)&C[off] = make_float4(x0, x1, x2, x3);
    }
}

template<int K, int NOUT, int MT>
__global__ void __launch_bounds__(MT * 4) gemm_kernel(
    const float* __restrict__ Aext, int Aid, int astride,
    const float* __restrict__ W, const float* __restrict__ bias,
    int Rid, const float* __restrict__ Rext,
    const float* __restrict__ lnG, const float* __restrict__ lnB,
    float* __restrict__ Cext, int Cid, int M, int mode)
{
    const float* A = Aext ? Aext : bufptr(Aid);
    float*       C = Cext ? Cext : bufptr(Cid);
    const float* R = nullptr;
    if (mode == 5) R = Rext ? Rext : bufptr(Rid);
    gemm_core<K, NOUT, MT>(A, astride, W, bias, R, lnG, lnB, C, M, mode);
}

// qkv fused: grid.y selects {q, k, v}
__global__ void __launch_bounds__(256) qkv_kernel(
    const float* __restrict__ Aext, int Aid,
    const float* __restrict__ wq, const float* __restrict__ bq,
    const float* __restrict__ wk, const float* __restrict__ bk,
    const float* __restrict__ wv, const float* __restrict__ bv, int M)
{
    int sel = blockIdx.y;
    const float* W = (sel == 0) ? wq : ((sel == 1) ? wk : wv);
    const float* b = (sel == 0) ? bq : ((sel == 1) ? bk : bv);
    const float* A = Aext ? Aext : bufptr(Aid);
    gemm_core<128, 128, 64>(A, 128, W, b, nullptr, nullptr, nullptr, bufptr(BQ + sel), M, 0);
}

// ------------------------------ attention (f32x2) ------------------------------
__global__ void __launch_bounds__(256) attn_kernel(int unused)
{
    __shared__ __align__(16) float Ks[LSEQ * DK];
    __shared__ __align__(16) float Vs[LSEQ * DK];
    int b = blockIdx.x >> 3;
    int h = blockIdx.x & 7;
    int tid = threadIdx.x;           // query index l
    int base = (b * LSEQ) * D + h * DK;

    for (int idx = tid; idx < LSEQ * DK; idx += 256) {
        int m = idx >> 4, j = idx & 15;
        Ks[idx] = g_k[base + m * D + j];
        Vs[idx] = g_v[base + m * D + j];
    }
    __syncthreads();

    unsigned long long q2[8];
    {
        const unsigned long long* qp = reinterpret_cast<const unsigned long long*>(g_q + base + tid * D);
        #pragma unroll
        for (int j = 0; j < 8; j++) q2[j] = qp[j];
    }

    unsigned long long acc[8];
    const unsigned long long z2 = pack2(0.f, 0.f);
    #pragma unroll
    for (int j = 0; j < 8; j++) acc[j] = z2;
    float mx = -3.0e38f, sum = 0.f;

    const unsigned long long* Ks2 = reinterpret_cast<const unsigned long long*>(Ks);
    const unsigned long long* Vs2 = reinterpret_cast<const unsigned long long*>(Vs);

    for (int m = 0; m < LSEQ; m++) {
        unsigned long long d2 = z2;
        #pragma unroll
        for (int j = 0; j < 8; j++)
            ffma2(d2, q2[j], Ks2[m * 8 + j]);
        float lo, hi;
        unpack2(d2, lo, hi);
        float s = (lo + hi) * 0.25f;  // 1/sqrt(16)

        if (s <= mx) {
            float pe = __expf(s - mx);
            sum += pe;
            unsigned long long pe2 = pack2(pe, pe);
            #pragma unroll
            for (int j = 0; j < 8; j++)
                ffma2(acc[j], Vs2[m * 8 + j], pe2);
        } else {
            float corr = __expf(mx - s);
            sum = sum * corr + 1.f;
            unsigned long long c2 = pack2(corr, corr);
            #pragma unroll
            for (int j = 0; j < 8; j++) {
                unsigned long long t;
                fmul2(t, acc[j], c2);
                fadd2(acc[j], t, Vs2[m * 8 + j]);
            }
            mx = s;
        }
    }

    float inv = 1.f / sum;
    float* op = g_o + base + tid * D;
    #pragma unroll
    for (int j = 0; j < 8; j++) {
        float lo, hi;
        unpack2(acc[j], lo, hi);
        op[j * 2 + 0] = lo * inv;
        op[j * 2 + 1] = hi * inv;
    }
}

// ------------------------------ launch ------------------------------
extern "C" void kernel_launch(void* const* d_in, const int* in_sizes, int n_in,
                              void* d_out, int out_size)
{
    const float* ego    = (const float*)d_in[0];
    const float* vals   = (const float*)d_in[1];
    const float* W1     = (const float*)d_in[2];
    const float* b1     = (const float*)d_in[3];
    const float* W2     = (const float*)d_in[4];
    const float* b2     = (const float*)d_in[5];
    const float* enc_in = (const float*)d_in[6];
    const float* wq     = (const float*)d_in[7];
    const float* bq     = (const float*)d_in[8];
    const float* wk     = (const float*)d_in[9];
    const float* bk     = (const float*)d_in[10];
    const float* wv     = (const float*)d_in[11];
    const float* bv     = (const float*)d_in[12];
    const float* wo     = (const float*)d_in[13];
    const float* bo     = (const float*)d_in[14];
    const float* ln1_g  = (const float*)d_in[15];
    const float* ln1_b  = (const float*)d_in[16];
    const float* cw1    = (const float*)d_in[17];
    const float* cb1    = (const float*)d_in[18];
    const float* cw2    = (const float*)d_in[19];
    const float* cb2    = (const float*)d_in[20];
    const float* ln2_g  = (const float*)d_in[21];
    const float* ln2_b  = (const float*)d_in[22];
    const int*   rows   = (const int*)d_in[23];
    const int*   cols   = (const int*)d_in[24];
    float* out = (float*)d_out;

    int Nego = in_sizes[0] / 128;       // 100000
    int nnz  = in_sizes[1];             // 2000000
    int Mt   = in_sizes[6] / 128;       // 8192 = B*L
    int B    = Mt / LSEQ;               // 32
    int NL   = in_sizes[7] / (128 * 128);

    // ---- graph side ----
    zero_side_kernel<<<1024, 256>>>((Nego * 128) / 4);
    int nwarps = (nnz + EPW - 1) / EPW;
    int spmm_blocks = (nwarps * 32 + 255) / 256;
    spmm_kernel<<<spmm_blocks, 256>>>(ego, vals, rows, cols, nnz);
    agg_fused_kernel<<<(Nego + 63) / 64, 256>>>(ego, W1, b1, W2, b2, out, Nego);

    // ---- transformer encoder ----
    const float* xin_ext = enc_in;
    int xin_id = -1;
    int gb64 = Mt / 64;   // 128
    int gb32 = Mt / 32;   // 256

    for (int i = 0; i < NL; i++) {
        const float* wq_ = wq + (size_t)i * D * D;  const float* bq_ = bq + i * D;
        const float* wk_ = wk + (size_t)i * D * D;  const float* bk_ = bk + i * D;
        const float* wv_ = wv + (size_t)i * D * D;  const float* bv_ = bv + i * D;
        const float* wo_ = wo + (size_t)i * D * D;  const float* bo_ = bo + i * D;
        const float* g1_ = ln1_g + i * D;            const float* be1_ = ln1_b + i * D;
        const float* c1_ = cw1 + (size_t)i * D * DI; const float* cb1_ = cb1 + i * DI;
        const float* c2_ = cw2 + (size_t)i * DI * D; const float* cb2_ = cb2 + i * D;
        const float* g2_ = ln2_g + i * D;            const float* be2_ = ln2_b + i * D;

        // QKV fused (grid.y = 3)
        qkv_kernel<<<dim3(gb64, 3), 256>>>(xin_ext, xin_id, wq_, bq_, wk_, bk_, wv_, bv_, Mt);
        attn_kernel<<<B * 8, 256>>>(0);
        // wo GEMM + residual + LN1 -> BX1  (MT=32 -> 256 CTAs fills chip)
        gemm_kernel<128, 128, 32><<<gb32, 128>>>(nullptr, BO, 128, wo_, bo_, xin_id, xin_ext,
                                                 g1_, be1_, nullptr, BX1, Mt, 5);
        // FFN1 relu -> BH  (MT=64, grid.y=4 -> 512 CTAs)
        gemm_kernel<128, 512, 64><<<dim3(gb64, 4), 256>>>(nullptr, BX1, 128, c1_, cb1_, -1, nullptr,
                                                          nullptr, nullptr, nullptr, BH, Mt, 1);
        // FFN2 + residual(BX1) + LN2 -> BX2 (or final out)  (MT=32 -> 256 CTAs)
        bool last = (i == NL - 1);
        gemm_kernel<512, 128, 32><<<gb32, 128>>>(nullptr, BH, 512, c2_, cb2_, BX1, nullptr,
                                                 g2_, be2_,
                                                 last ? (out + (size_t)in_sizes[0]) : nullptr,
                                                 BX2, Mt, 5);
        xin_ext = nullptr;
        xin_id = BX2;
    }
}

// round 8
// speedup vs baseline: 1.1332x; 1.1332x over previous
#include <cuda_runtime.h>
#include <math.h>

#define DEV_INLINE __device__ __forceinline__

static const int D    = 128;
static const int LSEQ = 256;
static const int DK   = 16;
static const int DI   = 512;

// ------------------------- scratch (device globals) -------------------------
__device__ float g_side[12800000];   // side = A_in @ ego
__device__ float g_q [1048576];
__device__ float g_k [1048576];
__device__ float g_v [1048576];
__device__ float g_o [1048576];
__device__ float g_x1[1048576];
__device__ float g_x2[1048576];
__device__ float g_h [4194304];      // 8192 x 512

enum { BQ = 0, BK = 1, BV = 2, BO = 3, BX1 = 5, BX2 = 6, BH = 7 };

DEV_INLINE float* bufptr(int id) {
    switch (id) {
        case BQ:  return g_q;
        case BK:  return g_k;
        case BV:  return g_v;
        case BO:  return g_o;
        case BX1: return g_x1;
        case BX2: return g_x2;
        case BH:  return g_h;
    }
    return nullptr;
}

// ------------------------- f32x2 helpers -------------------------
DEV_INLINE unsigned long long pack2(float lo, float hi) {
    unsigned long long r;
    asm("mov.b64 %0, {%1, %2};" : "=l"(r) : "f"(lo), "f"(hi));
    return r;
}
DEV_INLINE void unpack2(unsigned long long v, float& lo, float& hi) {
    asm("mov.b64 {%0, %1}, %2;" : "=f"(lo), "=f"(hi) : "l"(v));
}
DEV_INLINE void ffma2(unsigned long long& d, unsigned long long a, unsigned long long b) {
    asm("fma.rn.f32x2 %0, %1, %2, %0;" : "+l"(d) : "l"(a), "l"(b));
}
DEV_INLINE void fmul2(unsigned long long& d, unsigned long long a, unsigned long long b) {
    asm("mul.rn.f32x2 %0, %1, %2;" : "=l"(d) : "l"(a), "l"(b));
}
DEV_INLINE void fadd2(unsigned long long& d, unsigned long long a, unsigned long long b) {
    asm("add.rn.f32x2 %0, %1, %2;" : "=l"(d) : "l"(a), "l"(b));
}

// ------------------------------ zero side ------------------------------
__global__ void zero_side_kernel(int n4) {
    float4* p = reinterpret_cast<float4*>(g_side);
    int i = blockIdx.x * blockDim.x + threadIdx.x;
    int stride = gridDim.x * blockDim.x;
    float4 z = make_float4(0.f, 0.f, 0.f, 0.f);
    for (; i < n4; i += stride) p[i] = z;
}

// ------------------------------ SpMM (COO, rows sorted) ------------------------------
static const int EPW = 256;

DEV_INLINE void spmm_flush(int row, int lane, float4 acc) {
    float* p = &g_side[(size_t)row * 128 + lane * 4];
    atomicAdd(p + 0, acc.x);
    atomicAdd(p + 1, acc.y);
    atomicAdd(p + 2, acc.z);
    atomicAdd(p + 3, acc.w);
}

__global__ void __launch_bounds__(256) spmm_kernel(
    const float* __restrict__ ego, const float* __restrict__ vals,
    const int* __restrict__ rows, const int* __restrict__ cols, int nnz)
{
    int warp = (blockIdx.x * blockDim.x + threadIdx.x) >> 5;
    int lane = threadIdx.x & 31;
    long e0 = (long)warp * EPW;
    if (e0 >= nnz) return;
    long e1 = e0 + EPW; if (e1 > nnz) e1 = nnz;

    const float4* ego4 = reinterpret_cast<const float4*>(ego);
    float4 acc = make_float4(0.f, 0.f, 0.f, 0.f);
    int cur = rows[e0];
    for (long e = e0; e < e1; e++) {
        int r = rows[e];
        if (r != cur) {
            spmm_flush(cur, lane, acc);
            acc = make_float4(0.f, 0.f, 0.f, 0.f);
            cur = r;
        }
        float v  = vals[e];
        float4 g = ego4[(size_t)cols[e] * 32 + lane];
        acc.x += v * g.x; acc.y += v * g.y; acc.z += v * g.z; acc.w += v * g.w;
    }
    spmm_flush(cur, lane, acc);
}

// ------------------------------ fused aggregator (pipelined) ------------------------------
// out = leaky((ego+side)@W1+b1) + leaky((ego*side)@W2+b2).
// 256 thr, tile 64x128, K chunks of 16; next chunk LDG'd into regs during compute.
__global__ void __launch_bounds__(256) agg_fused_kernel(
    const float* __restrict__ ego,
    const float* __restrict__ W1, const float* __restrict__ b1,
    const float* __restrict__ W2, const float* __restrict__ b2,
    float* __restrict__ out, int M)
{
    __shared__ __align__(16) float W1s[16][128];
    __shared__ __align__(16) float W2s[16][128];
    __shared__ __align__(16) float As[16][64];
    __shared__ __align__(16) float Ps[16][64];

    int tid  = threadIdx.x;
    int lane = tid & 31, wy = tid >> 5;
    int c0   = lane * 4;
    int r0   = wy * 8;
    int row0 = blockIdx.x * 64;

    // staging register buffers
    float4 w1b[2], w2b[2], eb, sb;
    int wk[2], wc[2];
    {
        #pragma unroll
        for (int i = 0; i < 2; i++) {
            int idx = tid + i * 256;
            wk[i] = idx >> 5; wc[i] = idx & 31;
        }
    }
    int ar = tid & 63, akg = tid >> 6;   // A: r, k-group (covers 16 k as 4 groups of 4)
    int arr = row0 + ar;
    bool avalid = arr < M;

    auto ldW = [&](int k0) {
        #pragma unroll
        for (int i = 0; i < 2; i++) {
            w1b[i] = *(const float4*)&W1[(size_t)(k0 + wk[i]) * 128 + wc[i] * 4];
            w2b[i] = *(const float4*)&W2[(size_t)(k0 + wk[i]) * 128 + wc[i] * 4];
        }
    };
    auto ldA = [&](int k0) {
        eb = make_float4(0.f, 0.f, 0.f, 0.f);
        sb = make_float4(0.f, 0.f, 0.f, 0.f);
        if (avalid) {
            eb = *(const float4*)&ego   [(size_t)arr * 128 + k0 + akg * 4];
            sb = *(const float4*)&g_side[(size_t)arr * 128 + k0 + akg * 4];
        }
    };
    auto stAll = [&]() {
        #pragma unroll
        for (int i = 0; i < 2; i++) {
            *(float4*)&W1s[wk[i]][wc[i] * 4] = w1b[i];
            *(float4*)&W2s[wk[i]][wc[i] * 4] = w2b[i];
        }
        float sv[4] = {eb.x + sb.x, eb.y + sb.y, eb.z + sb.z, eb.w + sb.w};
        float pv[4] = {eb.x * sb.x, eb.y * sb.y, eb.z * sb.z, eb.w * sb.w};
        #pragma unroll
        for (int j = 0; j < 4; j++) {
            As[akg * 4 + j][ar] = sv[j];
            Ps[akg * 4 + j][ar] = pv[j];
        }
    };

    unsigned long long acc1[4][4], acc2[4][4];
    {
        float4 bv1 = *(const float4*)&b1[c0];
        float4 bv2 = *(const float4*)&b2[c0];
        float a1[4] = {bv1.x, bv1.y, bv1.z, bv1.w};
        float a2[4] = {bv2.x, bv2.y, bv2.z, bv2.w};
        #pragma unroll
        for (int c = 0; c < 4; c++) {
            unsigned long long p1 = pack2(a1[c], a1[c]);
            unsigned long long p2 = pack2(a2[c], a2[c]);
            #pragma unroll
            for (int p = 0; p < 4; p++) { acc1[p][c] = p1; acc2[p][c] = p2; }
        }
    }

    ldW(0); ldA(0);
    #pragma unroll 1
    for (int cch = 0; cch < 8; cch++) {
        stAll();
        __syncthreads();
        if (cch < 7) { ldW((cch + 1) * 16); ldA((cch + 1) * 16); }

        #pragma unroll 4
        for (int k = 0; k < 16; k++) {
            float4 w14 = *(const float4*)&W1s[k][c0];
            float4 w24 = *(const float4*)&W2s[k][c0];
            unsigned long long wp1[4], wp2[4];
            wp1[0] = pack2(w14.x, w14.x); wp1[1] = pack2(w14.y, w14.y);
            wp1[2] = pack2(w14.z, w14.z); wp1[3] = pack2(w14.w, w14.w);
            wp2[0] = pack2(w24.x, w24.x); wp2[1] = pack2(w24.y, w24.y);
            wp2[2] = pack2(w24.z, w24.z); wp2[3] = pack2(w24.w, w24.w);
            const unsigned long long* as2 = reinterpret_cast<const unsigned long long*>(&As[k][r0]);
            const unsigned long long* ps2 = reinterpret_cast<const unsigned long long*>(&Ps[k][r0]);
            unsigned long long a_s[4] = {as2[0], as2[1], as2[2], as2[3]};
            unsigned long long a_p[4] = {ps2[0], ps2[1], ps2[2], ps2[3]};
            #pragma unroll
            for (int p = 0; p < 4; p++) {
                #pragma unroll
                for (int c = 0; c < 4; c++) {
                    ffma2(acc1[p][c], a_s[p], wp1[c]);
                    ffma2(acc2[p][c], a_p[p], wp2[c]);
                }
            }
        }
        __syncthreads();
    }

    #pragma unroll
    for (int p = 0; p < 4; p++) {
        float v1[2][4], v2[2][4];
        #pragma unroll
        for (int c = 0; c < 4; c++) {
            unpack2(acc1[p][c], v1[0][c], v1[1][c]);
            unpack2(acc2[p][c], v2[0][c], v2[1][c]);
        }
        #pragma unroll
        for (int h = 0; h < 2; h++) {
            int rr = row0 + r0 + 2 * p + h;
            if (rr >= M) continue;
            float o[4];
            #pragma unroll
            for (int c = 0; c < 4; c++) {
                float x = v1[h][c]; x = (x > 0.f) ? x : 0.01f * x;
                float y = v2[h][c]; y = (y > 0.f) ? y : 0.01f * y;
                o[c] = x + y;
            }
            *(float4*)&out[(size_t)rr * 128 + c0] = make_float4(o[0], o[1], o[2], o[3]);
        }
    }
}

// ------------------------------ pipelined f32x2 GEMM core ------------------------------
// modes: 0 store(+bias), 1 relu(+bias), 5 +bias +residual +LayerNorm
// K chunks of 32; next chunk prefetched into registers during compute.
template<int K, int NOUT, int MT>
DEV_INLINE void gemm_core(const float* __restrict__ A, const float* __restrict__ W,
                          const float* __restrict__ bias, const float* __restrict__ R,
                          const float* __restrict__ lnG, const float* __restrict__ lnB,
                          float* __restrict__ C, int M, int mode)
{
    constexpr int NTHR = MT * 4;
    constexpr int NW = 1024 / NTHR;      // float4s of W chunk per thread
    constexpr int NA = (8 * MT) / NTHR;  // float4s of A chunk per thread
    constexpr int NC = K / 32;

    __shared__ __align__(16) float Ws[32][128];
    __shared__ __align__(16) float As[32][MT];   // [k][r] transposed

    int tid  = threadIdx.x;
    int lane = tid & 31, wy = tid >> 5;
    int c0   = lane * 4;
    int r0   = wy * 8;
    int row0 = blockIdx.x * MT;
    int cb   = (NOUT > 128) ? (blockIdx.y * 128) : 0;

    float4 wb[NW], ab[NA];

    auto ldW = [&](int k0) {
        #pragma unroll
        for (int i = 0; i < NW; i++) {
            int idx = tid + i * NTHR;
            int k = idx >> 5, cg = idx & 31;
            wb[i] = *(const float4*)&W[(size_t)(k0 + k) * NOUT + cb + cg * 4];
        }
    };
    auto ldA = [&](int k0) {
        #pragma unroll
        for (int i = 0; i < NA; i++) {
            int idx = tid + i * NTHR;
            int r = idx & (MT - 1), kg = idx / MT;
            int rr = row0 + r;
            ab[i] = make_float4(0.f, 0.f, 0.f, 0.f);
            if (rr < M) ab[i] = *(const float4*)&A[(size_t)rr * K + k0 + kg * 4];
        }
    };
    auto stAll = [&]() {
        #pragma unroll
        for (int i = 0; i < NW; i++) {
            int idx = tid + i * NTHR;
            int k = idx >> 5, cg = idx & 31;
            *(float4*)&Ws[k][cg * 4] = wb[i];
        }
        #pragma unroll
        for (int i = 0; i < NA; i++) {
            int idx = tid + i * NTHR;
            int r = idx & (MT - 1), kg = idx / MT;
            As[kg * 4 + 0][r] = ab[i].x;
            As[kg * 4 + 1][r] = ab[i].y;
            As[kg * 4 + 2][r] = ab[i].z;
            As[kg * 4 + 3][r] = ab[i].w;
        }
    };

    unsigned long long acc[4][4];
    {
        float4 bv = *(const float4*)&bias[cb + c0];
        float bb[4] = {bv.x, bv.y, bv.z, bv.w};
        #pragma unroll
        for (int c = 0; c < 4; c++) {
            unsigned long long b2 = pack2(bb[c], bb[c]);
            #pragma unroll
            for (int p = 0; p < 4; p++) acc[p][c] = b2;
        }
    }

    ldW(0); ldA(0);
    #pragma unroll 1
    for (int cch = 0; cch < NC; cch++) {
        stAll();
        __syncthreads();
        if (cch < NC - 1) { ldW((cch + 1) * 32); ldA((cch + 1) * 32); }

        #pragma unroll 4
        for (int k = 0; k < 32; k++) {
            float4 w4 = *(const float4*)&Ws[k][c0];
            unsigned long long wp[4];
            wp[0] = pack2(w4.x, w4.x);
            wp[1] = pack2(w4.y, w4.y);
            wp[2] = pack2(w4.z, w4.z);
            wp[3] = pack2(w4.w, w4.w);
            const unsigned long long* ap =
                reinterpret_cast<const unsigned long long*>(&As[k][r0]);
            unsigned long long a2[4] = {ap[0], ap[1], ap[2], ap[3]};
            #pragma unroll
            for (int p = 0; p < 4; p++)
                #pragma unroll
                for (int c = 0; c < 4; c++)
                    ffma2(acc[p][c], a2[p], wp[c]);
        }
        __syncthreads();
    }

    float4 g4 = make_float4(1.f, 1.f, 1.f, 1.f);
    float4 be4 = make_float4(0.f, 0.f, 0.f, 0.f);
    if (mode == 5) {
        g4  = *(const float4*)&lnG[c0];
        be4 = *(const float4*)&lnB[c0];
    }

    #pragma unroll
    for (int p = 0; p < 4; p++) {
        float vv[2][4];
        #pragma unroll
        for (int c = 0; c < 4; c++) unpack2(acc[p][c], vv[0][c], vv[1][c]);
        #pragma unroll
        for (int h = 0; h < 2; h++) {
            int rr = row0 + r0 + 2 * p + h;
            if (rr >= M) continue;
            size_t off = (size_t)rr * NOUT + cb + c0;
            float x0 = vv[h][0], x1 = vv[h][1], x2 = vv[h][2], x3 = vv[h][3];
            if (mode == 1) {
                x0 = fmaxf(x0, 0.f); x1 = fmaxf(x1, 0.f);
                x2 = fmaxf(x2, 0.f); x3 = fmaxf(x3, 0.f);
            } else if (mode == 5) {
                float4 rv = *(const float4*)&R[off];
                x0 += rv.x; x1 += rv.y; x2 += rv.z; x3 += rv.w;
                float s  = x0 + x1 + x2 + x3;
                float sq = x0 * x0 + x1 * x1 + x2 * x2 + x3 * x3;
                #pragma unroll
                for (int o = 16; o > 0; o >>= 1) {
                    s  += __shfl_xor_sync(0xffffffff, s,  o);
                    sq += __shfl_xor_sync(0xffffffff, sq, o);
                }
                float m   = s * (1.f / 128.f);
                float var = sq * (1.f / 128.f) - m * m;
                float rstd = rsqrtf(var + 1e-5f);
                x0 = (x0 - m) * rstd * g4.x + be4.x;
                x1 = (x1 - m) * rstd * g4.y + be4.y;
                x2 = (x2 - m) * rstd * g4.z + be4.z;
                x3 = (x3 - m) * rstd * g4.w + be4.w;
            }
            *(float4*)&C[off] = make_float4(x0, x1, x2, x3);
        }
    }
}

template<int K, int NOUT, int MT>
__global__ void __launch_bounds__(MT * 4) gemm2_kernel(
    const float* __restrict__ Aext, int Aid,
    const float* __restrict__ W, const float* __restrict__ bias,
    int Rid, const float* __restrict__ Rext,
    const float* __restrict__ lnG, const float* __restrict__ lnB,
    float* __restrict__ Cext, int Cid, int M, int mode)
{
    const float* A = Aext ? Aext : bufptr(Aid);
    float*       C = Cext ? Cext : bufptr(Cid);
    const float* R = nullptr;
    if (mode == 5) R = Rext ? Rext : bufptr(Rid);
    gemm_core<K, NOUT, MT>(A, W, bias, R, lnG, lnB, C, M, mode);
}

// qkv fused: grid.y selects {q, k, v}; MT=64 (measured best)
__global__ void __launch_bounds__(256) qkv_kernel(
    const float* __restrict__ Aext, int Aid,
    const float* __restrict__ wq, const float* __restrict__ bq,
    const float* __restrict__ wk, const float* __restrict__ bk,
    const float* __restrict__ wv, const float* __restrict__ bv, int M)
{
    int sel = blockIdx.y;
    const float* W = (sel == 0) ? wq : ((sel == 1) ? wk : wv);
    const float* b = (sel == 0) ? bq : ((sel == 1) ? bk : bv);
    const float* A = Aext ? Aext : bufptr(Aid);
    gemm_core<128, 128, 64>(A, W, b, nullptr, nullptr, nullptr, bufptr(BQ + sel), M, 0);
}

// ------------------------------ attention (f32x2) ------------------------------
__global__ void __launch_bounds__(256) attn_kernel(int unused)
{
    __shared__ __align__(16) float Ks[LSEQ * DK];
    __shared__ __align__(16) float Vs[LSEQ * DK];
    int b = blockIdx.x >> 3;
    int h = blockIdx.x & 7;
    int tid = threadIdx.x;
    int base = (b * LSEQ) * D + h * DK;

    for (int idx = tid; idx < LSEQ * DK; idx += 256) {
        int m = idx >> 4, j = idx & 15;
        Ks[idx] = g_k[base + m * D + j];
        Vs[idx] = g_v[base + m * D + j];
    }
    __syncthreads();

    unsigned long long q2[8];
    {
        const unsigned long long* qp = reinterpret_cast<const unsigned long long*>(g_q + base + tid * D);
        #pragma unroll
        for (int j = 0; j < 8; j++) q2[j] = qp[j];
    }

    unsigned long long acc[8];
    const unsigned long long z2 = pack2(0.f, 0.f);
    #pragma unroll
    for (int j = 0; j < 8; j++) acc[j] = z2;
    float mx = -3.0e38f, sum = 0.f;

    const unsigned long long* Ks2 = reinterpret_cast<const unsigned long long*>(Ks);
    const unsigned long long* Vs2 = reinterpret_cast<const unsigned long long*>(Vs);

    for (int m = 0; m < LSEQ; m++) {
        unsigned long long d2 = z2;
        #pragma unroll
        for (int j = 0; j < 8; j++)
            ffma2(d2, q2[j], Ks2[m * 8 + j]);
        float lo, hi;
        unpack2(d2, lo, hi);
        float s = (lo + hi) * 0.25f;

        if (s <= mx) {
            float pe = __expf(s - mx);
            sum += pe;
            unsigned long long pe2 = pack2(pe, pe);
            #pragma unroll
            for (int j = 0; j < 8; j++)
                ffma2(acc[j], Vs2[m * 8 + j], pe2);
        } else {
            float corr = __expf(mx - s);
            sum = sum * corr + 1.f;
            unsigned long long c2 = pack2(corr, corr);
            #pragma unroll
            for (int j = 0; j < 8; j++) {
                unsigned long long t;
                fmul2(t, acc[j], c2);
                fadd2(acc[j], t, Vs2[m * 8 + j]);
            }
            mx = s;
        }
    }

    float inv = 1.f / sum;
    float* op = g_o + base + tid * D;
    #pragma unroll
    for (int j = 0; j < 8; j++) {
        float lo, hi;
        unpack2(acc[j], lo, hi);
        op[j * 2 + 0] = lo * inv;
        op[j * 2 + 1] = hi * inv;
    }
}

// ------------------------------ launch ------------------------------
extern "C" void kernel_launch(void* const* d_in, const int* in_sizes, int n_in,
                              void* d_out, int out_size)
{
    const float* ego    = (const float*)d_in[0];
    const float* vals   = (const float*)d_in[1];
    const float* W1     = (const float*)d_in[2];
    const float* b1     = (const float*)d_in[3];
    const float* W2     = (const float*)d_in[4];
    const float* b2     = (const float*)d_in[5];
    const float* enc_in = (const float*)d_in[6];
    const float* wq     = (const float*)d_in[7];
    const float* bq     = (const float*)d_in[8];
    const float* wk     = (const float*)d_in[9];
    const float* bk     = (const float*)d_in[10];
    const float* wv     = (const float*)d_in[11];
    const float* bv     = (const float*)d_in[12];
    const float* wo     = (const float*)d_in[13];
    const float* bo     = (const float*)d_in[14];
    const float* ln1_g  = (const float*)d_in[15];
    const float* ln1_b  = (const float*)d_in[16];
    const float* cw1    = (const float*)d_in[17];
    const float* cb1    = (const float*)d_in[18];
    const float* cw2    = (const float*)d_in[19];
    const float* cb2    = (const float*)d_in[20];
    const float* ln2_g  = (const float*)d_in[21];
    const float* ln2_b  = (const float*)d_in[22];
    const int*   rows   = (const int*)d_in[23];
    const int*   cols   = (const int*)d_in[24];
    float* out = (float*)d_out;

    int Nego = in_sizes[0] / 128;       // 100000
    int nnz  = in_sizes[1];             // 2000000
    int Mt   = in_sizes[6] / 128;       // 8192
    int B    = Mt / LSEQ;               // 32
    int NL   = in_sizes[7] / (128 * 128);

    // ---- graph side ----
    zero_side_kernel<<<1024, 256>>>((Nego * 128) / 4);
    int nwarps = (nnz + EPW - 1) / EPW;
    int spmm_blocks = (nwarps * 32 + 255) / 256;
    spmm_kernel<<<spmm_blocks, 256>>>(ego, vals, rows, cols, nnz);
    agg_fused_kernel<<<(Nego + 63) / 64, 256>>>(ego, W1, b1, W2, b2, out, Nego);

    // ---- transformer encoder ----
    const float* xin_ext = enc_in;
    int xin_id = -1;
    int gb64 = Mt / 64;   // 128
    int gb32 = Mt / 32;   // 256

    for (int i = 0; i < NL; i++) {
        const float* wq_ = wq + (size_t)i * D * D;  const float* bq_ = bq + i * D;
        const float* wk_ = wk + (size_t)i * D * D;  const float* bk_ = bk + i * D;
        const float* wv_ = wv + (size_t)i * D * D;  const float* bv_ = bv + i * D;
        const float* wo_ = wo + (size_t)i * D * D;  const float* bo_ = bo + i * D;
        const float* g1_ = ln1_g + i * D;            const float* be1_ = ln1_b + i * D;
        const float* c1_ = cw1 + (size_t)i * D * DI; const float* cb1_ = cb1 + i * DI;
        const float* c2_ = cw2 + (size_t)i * DI * D; const float* cb2_ = cb2 + i * D;
        const float* g2_ = ln2_g + i * D;            const float* be2_ = ln2_b + i * D;

        qkv_kernel<<<dim3(gb64, 3), 256>>>(xin_ext, xin_id, wq_, bq_, wk_, bk_, wv_, bv_, Mt);
        attn_kernel<<<B * 8, 256>>>(0);
        // wo GEMM + residual + LN1 -> BX1
        gemm2_kernel<128, 128, 32><<<gb32, 128>>>(nullptr, BO, wo_, bo_, xin_id, xin_ext,
                                                  g1_, be1_, nullptr, BX1, Mt, 5);
        // FFN1 relu -> BH (MT=64, grid.y=4)
        gemm2_kernel<128, 512, 64><<<dim3(gb64, 4), 256>>>(nullptr, BX1, c1_, cb1_, -1, nullptr,
                                                           nullptr, nullptr, nullptr, BH, Mt, 1);
        // FFN2 + residual(BX1) + LN2 -> BX2 (or final out)
        bool last = (i == NL - 1);
        gemm2_kernel<512, 128, 32><<<gb32, 128>>>(nullptr, BH, c2_, cb2_, BX1, nullptr,
                                                  g2_, be2_,
                                                  last ? (out + (size_t)in_sizes[0]) : nullptr,
                                                  BX2, Mt, 5);
        xin_ext = nullptr;
        xin_id = BX2;
    }
}

// round 9
// speedup vs baseline: 1.3491x; 1.1905x over previous
#include <cuda_runtime.h>
#include <cuda_bf16.h>
#include <math.h>

#define DEV_INLINE __device__ __forceinline__

static const int D    = 128;
static const int LSEQ = 256;
static const int DK   = 16;
static const int DI   = 512;

// ------------------------- scratch (device globals) -------------------------
__device__ float g_side[12800000];   // side = A_in @ ego
__device__ float g_q [1048576];
__device__ float g_k [1048576];
__device__ float g_v [1048576];
__device__ float g_o [1048576];
__device__ float g_x1[1048576];
__device__ float g_x2[1048576];
__device__ float g_h [4194304];      // 8192 x 512
__device__ __align__(16) __nv_bfloat16 g_wbf[1048576];  // weight bf16 hi/lo images, [n][k]

enum { BQ = 0, BK = 1, BV = 2, BO = 3, BX1 = 5, BX2 = 6, BH = 7 };

DEV_INLINE float* bufptr(int id) {
    switch (id) {
        case BQ:  return g_q;
        case BK:  return g_k;
        case BV:  return g_v;
        case BO:  return g_o;
        case BX1: return g_x1;
        case BX2: return g_x2;
        case BH:  return g_h;
    }
    return nullptr;
}

// ------------------------- f32x2 helpers (attention) -------------------------
DEV_INLINE unsigned long long pack2(float lo, float hi) {
    unsigned long long r;
    asm("mov.b64 %0, {%1, %2};" : "=l"(r) : "f"(lo), "f"(hi));
    return r;
}
DEV_INLINE void unpack2(unsigned long long v, float& lo, float& hi) {
    asm("mov.b64 {%0, %1}, %2;" : "=f"(lo), "=f"(hi) : "l"(v));
}
DEV_INLINE void ffma2(unsigned long long& d, unsigned long long a, unsigned long long b) {
    asm("fma.rn.f32x2 %0, %1, %2, %0;" : "+l"(d) : "l"(a), "l"(b));
}
DEV_INLINE void fmul2(unsigned long long& d, unsigned long long a, unsigned long long b) {
    asm("mul.rn.f32x2 %0, %1, %2;" : "=l"(d) : "l"(a), "l"(b));
}
DEV_INLINE void fadd2(unsigned long long& d, unsigned long long a, unsigned long long b) {
    asm("add.rn.f32x2 %0, %1, %2;" : "=l"(d) : "l"(a), "l"(b));
}

// ------------------------- mma helpers -------------------------
DEV_INLINE unsigned smem_u32(const void* p) {
    unsigned a;
    asm("{ .reg .u64 t; cvta.to.shared.u64 t, %1; cvt.u32.u64 %0, t; }" : "=r"(a) : "l"(p));
    return a;
}
DEV_INLINE void ldsm4(unsigned* r, unsigned addr) {
    asm volatile("ldmatrix.sync.aligned.m8n8.x4.shared.b16 {%0,%1,%2,%3}, [%4];"
        : "=r"(r[0]), "=r"(r[1]), "=r"(r[2]), "=r"(r[3]) : "r"(addr));
}
DEV_INLINE void mma_bf16(float* c, const unsigned* a, const unsigned* b) {
    asm volatile(
        "mma.sync.aligned.m16n8k16.row.col.f32.bf16.bf16.f32 "
        "{%0,%1,%2,%3}, {%4,%5,%6,%7}, {%8,%9}, {%0,%1,%2,%3};"
        : "+f"(c[0]), "+f"(c[1]), "+f"(c[2]), "+f"(c[3])
        : "r"(a[0]), "r"(a[1]), "r"(a[2]), "r"(a[3]), "r"(b[0]), "r"(b[1]));
}
DEV_INLINE void split2(float x, float y, unsigned& h, unsigned& l) {
    __nv_bfloat162 hv = __floats2bfloat162_rn(x, y);
    float lx = x - __bfloat162float(hv.x);
    float ly = y - __bfloat162float(hv.y);
    __nv_bfloat162 lv = __floats2bfloat162_rn(lx, ly);
    h = *reinterpret_cast<unsigned*>(&hv);
    l = *reinterpret_cast<unsigned*>(&lv);
}

// ------------------------------ zero side ------------------------------
__global__ void zero_side_kernel(int n4) {
    float4* p = reinterpret_cast<float4*>(g_side);
    int i = blockIdx.x * blockDim.x + threadIdx.x;
    int stride = gridDim.x * blockDim.x;
    float4 z = make_float4(0.f, 0.f, 0.f, 0.f);
    for (; i < n4; i += stride) p[i] = z;
}

// ------------------------------ SpMM (COO, rows sorted) ------------------------------
static const int EPW = 256;

DEV_INLINE void spmm_flush(int row, int lane, float4 acc) {
    float* p = &g_side[(size_t)row * 128 + lane * 4];
    atomicAdd(p + 0, acc.x);
    atomicAdd(p + 1, acc.y);
    atomicAdd(p + 2, acc.z);
    atomicAdd(p + 3, acc.w);
}

__global__ void __launch_bounds__(256) spmm_kernel(
    const float* __restrict__ ego, const float* __restrict__ vals,
    const int* __restrict__ rows, const int* __restrict__ cols, int nnz)
{
    int warp = (blockIdx.x * blockDim.x + threadIdx.x) >> 5;
    int lane = threadIdx.x & 31;
    long e0 = (long)warp * EPW;
    if (e0 >= nnz) return;
    long e1 = e0 + EPW; if (e1 > nnz) e1 = nnz;

    const float4* ego4 = reinterpret_cast<const float4*>(ego);
    float4 acc = make_float4(0.f, 0.f, 0.f, 0.f);
    int cur = rows[e0];
    for (long e = e0; e < e1; e++) {
        int r = rows[e];
        if (r != cur) {
            spmm_flush(cur, lane, acc);
            acc = make_float4(0.f, 0.f, 0.f, 0.f);
            cur = r;
        }
        float v  = vals[e];
        float4 g = ego4[(size_t)cols[e] * 32 + lane];
        acc.x += v * g.x; acc.y += v * g.y; acc.z += v * g.z; acc.w += v * g.w;
    }
    spmm_flush(cur, lane, acc);
}

// ------------------------------ prep: weight bf16 hi/lo images, [n][k] ------------------------------
// Image layout at offset off: hi block [N][K] bf16, lo block at off + N*K.
__global__ void __launch_bounds__(256) prep_w_kernel(
    const float* __restrict__ W1, const float* __restrict__ W2,
    const float* __restrict__ wq, const float* __restrict__ wk,
    const float* __restrict__ wv, const float* __restrict__ wo,
    const float* __restrict__ cw1, const float* __restrict__ cw2, int NL)
{
    int y = blockIdx.y;
    const float* src; unsigned off; int Kd, Nd;
    if (y < 2) { src = y ? W2 : W1; off = (unsigned)y * 32768u; Kd = 128; Nd = 128; }
    else {
        int i = (y - 2) / 6, j = (y - 2) % 6;
        unsigned base = 65536u + (unsigned)i * 393216u;
        if (j < 4) {
            const float* p = (j == 0) ? wq : (j == 1) ? wk : (j == 2) ? wv : wo;
            src = p + (size_t)i * 16384; off = base + (unsigned)j * 32768u; Kd = 128; Nd = 128;
        } else if (j == 4) {
            src = cw1 + (size_t)i * 65536; off = base + 131072u; Kd = 128; Nd = 512;
        } else {
            src = cw2 + (size_t)i * 65536; off = base + 262144u; Kd = 512; Nd = 128;
        }
    }
    int tot = Kd * Nd;
    for (int idx = blockIdx.x * 256 + threadIdx.x; idx < tot; idx += gridDim.x * 256) {
        int n = idx / Kd, k = idx - n * Kd;
        float w = src[(size_t)k * Nd + n];
        __nv_bfloat16 h = __float2bfloat16(w);
        float l = w - __bfloat162float(h);
        g_wbf[off + (size_t)n * Kd + k] = h;
        g_wbf[off + (size_t)tot + (size_t)n * Kd + k] = __float2bfloat16(l);
    }
}

// ------------------------------ bf16x3 mma GEMM core ------------------------------
// CTA 128 thr (4 warps x 16m), tile 64m x 128n, K-chunks of 32 (pad rows to 40 bf16).
// modes: 0 +bias store, 1 +bias relu, 3 +bias leaky store, 4 +bias leaky add-to-C, 5 +bias +res +LN
// aop: 0 A, 1 ego+side, 2 ego*side (A2 = g_side)
template<int K, int NOUT>
DEV_INLINE void mma_core(const float* __restrict__ A, int aop,
                         const __nv_bfloat16* __restrict__ Whi, int loN,
                         const float* __restrict__ bias, const float* __restrict__ R,
                         const float* __restrict__ lnG, const float* __restrict__ lnB,
                         float* __restrict__ C, int M, int mode, int cb)
{
    __shared__ __align__(16) __nv_bfloat16 Ah[64][40];
    __shared__ __align__(16) __nv_bfloat16 Al[64][40];
    __shared__ __align__(16) __nv_bfloat16 Bh[128][40];
    __shared__ __align__(16) __nv_bfloat16 Bl[128][40];

    int tid = threadIdx.x, lane = tid & 31, wy = tid >> 5;
    int row0 = blockIdx.x * 64;

    float c[16][4];
    #pragma unroll
    for (int t = 0; t < 16; t++)
        #pragma unroll
        for (int j = 0; j < 4; j++) c[t][j] = 0.f;

    // ldmatrix per-lane addresses
    int arow = wy * 16 + (lane & 7) + ((lane >> 3) & 1) * 8;
    int akc  = (lane >> 4) * 8;
    unsigned aAh = smem_u32(&Ah[arow][akc]);
    unsigned aAl = smem_u32(&Al[arow][akc]);
    int bn = (lane & 7) + ((lane >> 4) << 3);
    int bk = ((lane >> 3) & 1) * 8;
    unsigned aBh = smem_u32(&Bh[bn][bk]);
    unsigned aBl = smem_u32(&Bl[bn][bk]);

    for (int ch = 0; ch < K / 32; ch++) {
        int k0 = ch * 32;
        // stage B (copy prebuilt bf16 images)
        #pragma unroll
        for (int i = 0; i < 4; i++) {
            int idx = tid + i * 128;
            int n = idx >> 2, part = idx & 3;
            const uint4* sh = reinterpret_cast<const uint4*>(Whi + (size_t)(cb + n) * K + k0);
            const uint4* sl = reinterpret_cast<const uint4*>(Whi + loN + (size_t)(cb + n) * K + k0);
            *reinterpret_cast<uint4*>(&Bh[n][part * 8]) = sh[part];
            *reinterpret_cast<uint4*>(&Bl[n][part * 8]) = sl[part];
        }
        // stage A (fp32 -> bf16 hi/lo)
        #pragma unroll
        for (int i = 0; i < 4; i++) {
            int idx = tid + i * 128;
            int r = idx >> 3, kg = idx & 7;
            int rr = row0 + r;
            float4 av = make_float4(0.f, 0.f, 0.f, 0.f);
            if (rr < M) {
                av = *reinterpret_cast<const float4*>(&A[(size_t)rr * K + k0 + kg * 4]);
                if (aop) {
                    float4 a2 = *reinterpret_cast<const float4*>(&g_side[(size_t)rr * K + k0 + kg * 4]);
                    if (aop == 1) { av.x += a2.x; av.y += a2.y; av.z += a2.z; av.w += a2.w; }
                    else          { av.x *= a2.x; av.y *= a2.y; av.z *= a2.z; av.w *= a2.w; }
                }
            }
            unsigned h01, l01, h23, l23;
            split2(av.x, av.y, h01, l01);
            split2(av.z, av.w, h23, l23);
            *reinterpret_cast<uint2*>(&Ah[r][kg * 4]) = make_uint2(h01, h23);
            *reinterpret_cast<uint2*>(&Al[r][kg * 4]) = make_uint2(l01, l23);
        }
        __syncthreads();

        #pragma unroll
        for (int ks = 0; ks < 2; ks++) {
            unsigned ah[4], al[4];
            ldsm4(ah, aAh + ks * 32);
            ldsm4(al, aAl + ks * 32);
            #pragma unroll
            for (int np = 0; np < 8; np++) {
                unsigned bh[4], bl[4];
                ldsm4(bh, aBh + np * 1280 + ks * 32);
                ldsm4(bl, aBl + np * 1280 + ks * 32);
                mma_bf16(c[2 * np],     ah, bh);
                mma_bf16(c[2 * np],     ah, bl);
                mma_bf16(c[2 * np],     al, bh);
                mma_bf16(c[2 * np + 1], ah, bh + 2);
                mma_bf16(c[2 * np + 1], ah, bl + 2);
                mma_bf16(c[2 * np + 1], al, bh + 2);
            }
        }
        __syncthreads();
    }

    // epilogue. lane frag: rows r0g/r1g, cols colb + nt*8 (+1)
    int colb = cb + (lane & 3) * 2;
    int r0g = row0 + wy * 16 + (lane >> 2);
    int r1g = r0g + 8;
    bool v0 = r0g < M, v1 = r1g < M;

    if (mode == 5) {
        float s0 = 0.f, q0 = 0.f, s1 = 0.f, q1 = 0.f;
        #pragma unroll
        for (int nt = 0; nt < 16; nt++) {
            int col = colb + nt * 8;
            float2 bv = *reinterpret_cast<const float2*>(&bias[col]);
            float2 rA = v0 ? *reinterpret_cast<const float2*>(&R[(size_t)r0g * 128 + col]) : make_float2(0.f, 0.f);
            float2 rB = v1 ? *reinterpret_cast<const float2*>(&R[(size_t)r1g * 128 + col]) : make_float2(0.f, 0.f);
            c[nt][0] += bv.x + rA.x; c[nt][1] += bv.y + rA.y;
            c[nt][2] += bv.x + rB.x; c[nt][3] += bv.y + rB.y;
            s0 += c[nt][0] + c[nt][1]; q0 += c[nt][0] * c[nt][0] + c[nt][1] * c[nt][1];
            s1 += c[nt][2] + c[nt][3]; q1 += c[nt][2] * c[nt][2] + c[nt][3] * c[nt][3];
        }
        #pragma unroll
        for (int o = 1; o <= 2; o <<= 1) {
            s0 += __shfl_xor_sync(0xffffffff, s0, o);
            q0 += __shfl_xor_sync(0xffffffff, q0, o);
            s1 += __shfl_xor_sync(0xffffffff, s1, o);
            q1 += __shfl_xor_sync(0xffffffff, q1, o);
        }
        float m0 = s0 * (1.f / 128.f), var0 = q0 * (1.f / 128.f) - m0 * m0;
        float m1 = s1 * (1.f / 128.f), var1 = q1 * (1.f / 128.f) - m1 * m1;
        float rs0 = rsqrtf(var0 + 1e-5f), rs1 = rsqrtf(var1 + 1e-5f);
        #pragma unroll
        for (int nt = 0; nt < 16; nt++) {
            int col = colb + nt * 8;
            float2 g = *reinterpret_cast<const float2*>(&lnG[col]);
            float2 be = *reinterpret_cast<const float2*>(&lnB[col]);
            if (v0) {
                float2 o = make_float2((c[nt][0] - m0) * rs0 * g.x + be.x,
                                       (c[nt][1] - m0) * rs0 * g.y + be.y);
                *reinterpret_cast<float2*>(&C[(size_t)r0g * 128 + col]) = o;
            }
            if (v1) {
                float2 o = make_float2((c[nt][2] - m1) * rs1 * g.x + be.x,
                                       (c[nt][3] - m1) * rs1 * g.y + be.y);
                *reinterpret_cast<float2*>(&C[(size_t)r1g * 128 + col]) = o;
            }
        }
    } else {
        #pragma unroll
        for (int nt = 0; nt < 16; nt++) {
            int col = colb + nt * 8;
            float2 bv = *reinterpret_cast<const float2*>(&bias[col]);
            float x0 = c[nt][0] + bv.x, x1 = c[nt][1] + bv.y;
            float x2 = c[nt][2] + bv.x, x3 = c[nt][3] + bv.y;
            if (mode == 1) {
                x0 = fmaxf(x0, 0.f); x1 = fmaxf(x1, 0.f);
                x2 = fmaxf(x2, 0.f); x3 = fmaxf(x3, 0.f);
            } else if (mode == 3 || mode == 4) {
                x0 = (x0 > 0.f) ? x0 : 0.01f * x0;
                x1 = (x1 > 0.f) ? x1 : 0.01f * x1;
                x2 = (x2 > 0.f) ? x2 : 0.01f * x2;
                x3 = (x3 > 0.f) ? x3 : 0.01f * x3;
                if (mode == 4) {
                    if (v0) {
                        float2 cv = *reinterpret_cast<const float2*>(&C[(size_t)r0g * NOUT + col]);
                        x0 += cv.x; x1 += cv.y;
                    }
                    if (v1) {
                        float2 cv = *reinterpret_cast<const float2*>(&C[(size_t)r1g * NOUT + col]);
                        x2 += cv.x; x3 += cv.y;
                    }
                }
            }
            if (v0) *reinterpret_cast<float2*>(&C[(size_t)r0g * NOUT + col]) = make_float2(x0, x1);
            if (v1) *reinterpret_cast<float2*>(&C[(size_t)r1g * NOUT + col]) = make_float2(x2, x3);
        }
    }
}

template<int K, int NOUT>
__global__ void __launch_bounds__(128) mma_gemm_kernel(
    const float* __restrict__ Aext, int Aid, int aop,
    unsigned woff, int loN,
    const float* __restrict__ bias,
    int Rid, const float* __restrict__ Rext,
    const float* __restrict__ lnG, const float* __restrict__ lnB,
    float* __restrict__ Cext, int Cid, int M, int mode)
{
    const float* A = Aext ? Aext : bufptr(Aid);
    float*       C = Cext ? Cext : bufptr(Cid);
    const float* R = nullptr;
    if (mode == 5) R = Rext ? Rext : bufptr(Rid);
    int cb = (NOUT > 128) ? blockIdx.y * 128 : 0;
    mma_core<K, NOUT>(A, aop, g_wbf + woff, loN, bias, R, lnG, lnB, C, M, mode, cb);
}

// qkv fused: grid.y selects q/k/v
__global__ void __launch_bounds__(128) mma_qkv_kernel(
    const float* __restrict__ Aext, int Aid, unsigned wbase,
    const float* __restrict__ bq, const float* __restrict__ bk,
    const float* __restrict__ bv, int M)
{
    int sel = blockIdx.y;
    const float* bias = (sel == 0) ? bq : (sel == 1) ? bk : bv;
    const float* A = Aext ? Aext : bufptr(Aid);
    mma_core<128, 128>(A, 0, g_wbf + wbase + sel * 32768u, 16384,
                       bias, nullptr, nullptr, nullptr, bufptr(BQ + sel), M, 0, 0);
}

// ------------------------------ attention (f32x2) ------------------------------
__global__ void __launch_bounds__(256) attn_kernel(int unused)
{
    __shared__ __align__(16) float Ks[LSEQ * DK];
    __shared__ __align__(16) float Vs[LSEQ * DK];
    int b = blockIdx.x >> 3;
    int h = blockIdx.x & 7;
    int tid = threadIdx.x;
    int base = (b * LSEQ) * D + h * DK;

    for (int idx = tid; idx < LSEQ * DK; idx += 256) {
        int m = idx >> 4, j = idx & 15;
        Ks[idx] = g_k[base + m * D + j];
        Vs[idx] = g_v[base + m * D + j];
    }
    __syncthreads();

    unsigned long long q2[8];
    {
        const unsigned long long* qp = reinterpret_cast<const unsigned long long*>(g_q + base + tid * D);
        #pragma unroll
        for (int j = 0; j < 8; j++) q2[j] = qp[j];
    }

    unsigned long long acc[8];
    const unsigned long long z2 = pack2(0.f, 0.f);
    #pragma unroll
    for (int j = 0; j < 8; j++) acc[j] = z2;
    float mx = -3.0e38f, sum = 0.f;

    const unsigned long long* Ks2 = reinterpret_cast<const unsigned long long*>(Ks);
    const unsigned long long* Vs2 = reinterpret_cast<const unsigned long long*>(Vs);

    for (int m = 0; m < LSEQ; m++) {
        unsigned long long d2 = z2;
        #pragma unroll
        for (int j = 0; j < 8; j++)
            ffma2(d2, q2[j], Ks2[m * 8 + j]);
        float lo, hi;
        unpack2(d2, lo, hi);
        float s = (lo + hi) * 0.25f;

        if (s <= mx) {
            float pe = __expf(s - mx);
            sum += pe;
            unsigned long long pe2 = pack2(pe, pe);
            #pragma unroll
            for (int j = 0; j < 8; j++)
                ffma2(acc[j], Vs2[m * 8 + j], pe2);
        } else {
            float corr = __expf(mx - s);
            sum = sum * corr + 1.f;
            unsigned long long c2 = pack2(corr, corr);
            #pragma unroll
            for (int j = 0; j < 8; j++) {
                unsigned long long t;
                fmul2(t, acc[j], c2);
                fadd2(acc[j], t, Vs2[m * 8 + j]);
            }
            mx = s;
        }
    }

    float inv = 1.f / sum;
    float* op = g_o + base + tid * D;
    #pragma unroll
    for (int j = 0; j < 8; j++) {
        float lo, hi;
        unpack2(acc[j], lo, hi);
        op[j * 2 + 0] = lo * inv;
        op[j * 2 + 1] = hi * inv;
    }
}

// ------------------------------ launch ------------------------------
extern "C" void kernel_launch(void* const* d_in, const int* in_sizes, int n_in,
                              void* d_out, int out_size)
{
    const float* ego    = (const float*)d_in[0];
    const float* vals   = (const float*)d_in[1];
    const float* W1     = (const float*)d_in[2];
    const float* b1     = (const float*)d_in[3];
    const float* W2     = (const float*)d_in[4];
    const float* b2     = (const float*)d_in[5];
    const float* enc_in = (const float*)d_in[6];
    const float* wq     = (const float*)d_in[7];
    const float* bq     = (const float*)d_in[8];
    const float* wk     = (const float*)d_in[9];
    const float* bk     = (const float*)d_in[10];
    const float* wv     = (const float*)d_in[11];
    const float* bv     = (const float*)d_in[12];
    const float* wo     = (const float*)d_in[13];
    const float* bo     = (const float*)d_in[14];
    const float* ln1_g  = (const float*)d_in[15];
    const float* ln1_b  = (const float*)d_in[16];
    const float* cw1    = (const float*)d_in[17];
    const float* cb1    = (const float*)d_in[18];
    const float* cw2    = (const float*)d_in[19];
    const float* cb2    = (const float*)d_in[20];
    const float* ln2_g  = (const float*)d_in[21];
    const float* ln2_b  = (const float*)d_in[22];
    const int*   rows   = (const int*)d_in[23];
    const int*   cols   = (const int*)d_in[24];
    float* out = (float*)d_out;

    int Nego = in_sizes[0] / 128;       // 100000
    int nnz  = in_sizes[1];             // 2000000
    int Mt   = in_sizes[6] / 128;       // 8192
    int B    = Mt / LSEQ;               // 32
    int NL   = in_sizes[7] / (128 * 128);

    // ---- weight images ----
    prep_w_kernel<<<dim3(64, 2 + 6 * NL), 256>>>(W1, W2, wq, wk, wv, wo, cw1, cw2, NL);

    // ---- graph side ----
    zero_side_kernel<<<1024, 256>>>((Nego * 128) / 4);
    int nwarps = (nnz + EPW - 1) / EPW;
    int spmm_blocks = (nwarps * 32 + 255) / 256;
    spmm_kernel<<<spmm_blocks, 256>>>(ego, vals, rows, cols, nnz);

    int agg_blocks = (Nego + 63) / 64;
    // agg1: leaky((ego+side)@W1 + b1) -> out
    mma_gemm_kernel<128, 128><<<agg_blocks, 128>>>(ego, -1, 1, 0u, 16384, b1,
                                                   -1, nullptr, nullptr, nullptr,
                                                   out, -1, Nego, 3);
    // agg2: += leaky((ego*side)@W2 + b2)
    mma_gemm_kernel<128, 128><<<agg_blocks, 128>>>(ego, -1, 2, 32768u, 16384, b2,
                                                   -1, nullptr, nullptr, nullptr,
                                                   out, -1, Nego, 4);

    // ---- transformer encoder ----
    const float* xin_ext = enc_in;
    int xin_id = -1;
    int gb = Mt / 64;   // 128

    for (int i = 0; i < NL; i++) {
        unsigned lbase = 65536u + (unsigned)i * 393216u;
        const float* bq_ = bq + i * D;
        const float* bk_ = bk + i * D;
        const float* bv_ = bv + i * D;
        const float* bo_ = bo + i * D;
        const float* g1_ = ln1_g + i * D;  const float* be1_ = ln1_b + i * D;
        const float* cb1_ = cb1 + i * DI;
        const float* cb2_ = cb2 + i * D;
        const float* g2_ = ln2_g + i * D;  const float* be2_ = ln2_b + i * D;

        // QKV (grid.y = 3)
        mma_qkv_kernel<<<dim3(gb, 3), 128>>>(xin_ext, xin_id, lbase, bq_, bk_, bv_, Mt);
        attn_kernel<<<B * 8, 256>>>(0);
        // wo + residual + LN1 -> BX1
        mma_gemm_kernel<128, 128><<<gb, 128>>>(nullptr, BO, 0, lbase + 3u * 32768u, 16384, bo_,
                                               xin_id, xin_ext, g1_, be1_, nullptr, BX1, Mt, 5);
        // FFN1 relu -> BH  (grid.y = 4 over N=512)
        mma_gemm_kernel<128, 512><<<dim3(gb, 4), 128>>>(nullptr, BX1, 0, lbase + 131072u, 65536, cb1_,
                                                        -1, nullptr, nullptr, nullptr, nullptr, BH, Mt, 1);
        // FFN2 + residual(BX1) + LN2 -> BX2 (or final out)
        bool last = (i == NL - 1);
        mma_gemm_kernel<512, 128><<<gb, 128>>>(nullptr, BH, 0, lbase + 262144u, 65536, cb2_,
                                               BX1, nullptr, g2_, be2_,
                                               last ? (out + (size_t)in_sizes[0]) : nullptr,
                                               BX2, Mt, 5);
        xin_ext = nullptr;
        xin_id = BX2;
    }
}

// round 10
// speedup vs baseline: 1.3993x; 1.0371x over previous
#include <cuda_runtime.h>
#include <cuda_bf16.h>
#include <math.h>

#define DEV_INLINE __device__ __forceinline__

static const int D    = 128;
static const int LSEQ = 256;
static const int DK   = 16;
static const int DI   = 512;

// ------------------------- scratch (device globals) -------------------------
__device__ float g_side[12800000];   // side = A_in @ ego
__device__ float g_q [1048576];
__device__ float g_k [1048576];
__device__ float g_v [1048576];
__device__ float g_o [1048576];
__device__ float g_x1[1048576];
__device__ float g_x2[1048576];
__device__ float g_h [4194304];      // 8192 x 512
__device__ __align__(16) __nv_bfloat16 g_wbf[1048576];  // weight bf16 hi/lo images, [n][k]

enum { BQ = 0, BK = 1, BV = 2, BO = 3, BX1 = 5, BX2 = 6, BH = 7 };

DEV_INLINE float* bufptr(int id) {
    switch (id) {
        case BQ:  return g_q;
        case BK:  return g_k;
        case BV:  return g_v;
        case BO:  return g_o;
        case BX1: return g_x1;
        case BX2: return g_x2;
        case BH:  return g_h;
    }
    return nullptr;
}

// ------------------------- f32x2 helpers (attention) -------------------------
DEV_INLINE unsigned long long pack2(float lo, float hi) {
    unsigned long long r;
    asm("mov.b64 %0, {%1, %2};" : "=l"(r) : "f"(lo), "f"(hi));
    return r;
}
DEV_INLINE void unpack2(unsigned long long v, float& lo, float& hi) {
    asm("mov.b64 {%0, %1}, %2;" : "=f"(lo), "=f"(hi) : "l"(v));
}
DEV_INLINE void ffma2(unsigned long long& d, unsigned long long a, unsigned long long b) {
    asm("fma.rn.f32x2 %0, %1, %2, %0;" : "+l"(d) : "l"(a), "l"(b));
}
DEV_INLINE void fmul2(unsigned long long& d, unsigned long long a, unsigned long long b) {
    asm("mul.rn.f32x2 %0, %1, %2;" : "=l"(d) : "l"(a), "l"(b));
}
DEV_INLINE void fadd2(unsigned long long& d, unsigned long long a, unsigned long long b) {
    asm("add.rn.f32x2 %0, %1, %2;" : "=l"(d) : "l"(a), "l"(b));
}

// ------------------------- mma helpers -------------------------
DEV_INLINE unsigned smem_u32(const void* p) {
    unsigned a;
    asm("{ .reg .u64 t; cvta.to.shared.u64 t, %1; cvt.u32.u64 %0, t; }" : "=r"(a) : "l"(p));
    return a;
}
DEV_INLINE void ldsm4(unsigned* r, unsigned addr) {
    asm volatile("ldmatrix.sync.aligned.m8n8.x4.shared.b16 {%0,%1,%2,%3}, [%4];"
        : "=r"(r[0]), "=r"(r[1]), "=r"(r[2]), "=r"(r[3]) : "r"(addr));
}
DEV_INLINE void mma_bf16(float* c, const unsigned* a, const unsigned* b) {
    asm volatile(
        "mma.sync.aligned.m16n8k16.row.col.f32.bf16.bf16.f32 "
        "{%0,%1,%2,%3}, {%4,%5,%6,%7}, {%8,%9}, {%0,%1,%2,%3};"
        : "+f"(c[0]), "+f"(c[1]), "+f"(c[2]), "+f"(c[3])
        : "r"(a[0]), "r"(a[1]), "r"(a[2]), "r"(a[3]), "r"(b[0]), "r"(b[1]));
}
DEV_INLINE void split2(float x, float y, unsigned& h, unsigned& l) {
    __nv_bfloat162 hv = __floats2bfloat162_rn(x, y);
    float lx = x - __bfloat162float(hv.x);
    float ly = y - __bfloat162float(hv.y);
    __nv_bfloat162 lv = __floats2bfloat162_rn(lx, ly);
    h = *reinterpret_cast<unsigned*>(&hv);
    l = *reinterpret_cast<unsigned*>(&lv);
}

// ------------------------------ zero side ------------------------------
__global__ void zero_side_kernel(int n4) {
    float4* p = reinterpret_cast<float4*>(g_side);
    int i = blockIdx.x * blockDim.x + threadIdx.x;
    int stride = gridDim.x * blockDim.x;
    float4 z = make_float4(0.f, 0.f, 0.f, 0.f);
    for (; i < n4; i += stride) p[i] = z;
}

// ------------------------------ SpMM (COO, rows sorted) ------------------------------
static const int EPW = 256;

DEV_INLINE void spmm_flush(int row, int lane, float4 acc) {
    float* p = &g_side[(size_t)row * 128 + lane * 4];
    atomicAdd(p + 0, acc.x);
    atomicAdd(p + 1, acc.y);
    atomicAdd(p + 2, acc.z);
    atomicAdd(p + 3, acc.w);
}

__global__ void __launch_bounds__(256) spmm_kernel(
    const float* __restrict__ ego, const float* __restrict__ vals,
    const int* __restrict__ rows, const int* __restrict__ cols, int nnz)
{
    int warp = (blockIdx.x * blockDim.x + threadIdx.x) >> 5;
    int lane = threadIdx.x & 31;
    long e0 = (long)warp * EPW;
    if (e0 >= nnz) return;
    long e1 = e0 + EPW; if (e1 > nnz) e1 = nnz;

    const float4* ego4 = reinterpret_cast<const float4*>(ego);
    float4 acc = make_float4(0.f, 0.f, 0.f, 0.f);
    int cur = rows[e0];
    for (long e = e0; e < e1; e++) {
        int r = rows[e];
        if (r != cur) {
            spmm_flush(cur, lane, acc);
            acc = make_float4(0.f, 0.f, 0.f, 0.f);
            cur = r;
        }
        float v  = vals[e];
        float4 g = ego4[(size_t)cols[e] * 32 + lane];
        acc.x += v * g.x; acc.y += v * g.y; acc.z += v * g.z; acc.w += v * g.w;
    }
    spmm_flush(cur, lane, acc);
}

// ------------------------------ prep: weight bf16 hi/lo images, [n][k] ------------------------------
__global__ void __launch_bounds__(256) prep_w_kernel(
    const float* __restrict__ W1, const float* __restrict__ W2,
    const float* __restrict__ wq, const float* __restrict__ wk,
    const float* __restrict__ wv, const float* __restrict__ wo,
    const float* __restrict__ cw1, const float* __restrict__ cw2, int NL)
{
    int y = blockIdx.y;
    const float* src; unsigned off; int Kd, Nd;
    if (y < 2) { src = y ? W2 : W1; off = (unsigned)y * 32768u; Kd = 128; Nd = 128; }
    else {
        int i = (y - 2) / 6, j = (y - 2) % 6;
        unsigned base = 65536u + (unsigned)i * 393216u;
        if (j < 4) {
            const float* p = (j == 0) ? wq : (j == 1) ? wk : (j == 2) ? wv : wo;
            src = p + (size_t)i * 16384; off = base + (unsigned)j * 32768u; Kd = 128; Nd = 128;
        } else if (j == 4) {
            src = cw1 + (size_t)i * 65536; off = base + 131072u; Kd = 128; Nd = 512;
        } else {
            src = cw2 + (size_t)i * 65536; off = base + 262144u; Kd = 512; Nd = 128;
        }
    }
    int tot = Kd * Nd;
    for (int idx = blockIdx.x * 256 + threadIdx.x; idx < tot; idx += gridDim.x * 256) {
        int n = idx / Kd, k = idx - n * Kd;
        float w = src[(size_t)k * Nd + n];
        __nv_bfloat16 h = __float2bfloat16(w);
        float l = w - __bfloat162float(h);
        g_wbf[off + (size_t)n * Kd + k] = h;
        g_wbf[off + (size_t)tot + (size_t)n * Kd + k] = __float2bfloat16(l);
    }
}

// ------------------------------ bf16x3 mma GEMM core (256 thr, 8 warps 4m x 2n) ------------------------------
// tile 64m x 128n; warp (wm, wn) computes rows wm*16..+15, cols wn*64..+63.
// modes: 0 +bias store, 1 +bias relu, 3 +bias leaky store, 4 +bias leaky add-to-C, 5 +bias +res +LN
// aop: 0 A, 1 ego+side, 2 ego*side (A2 = g_side)
template<int K, int NOUT>
DEV_INLINE void mma_core(const float* __restrict__ A, int aop,
                         const __nv_bfloat16* __restrict__ Whi, int loN,
                         const float* __restrict__ bias, const float* __restrict__ R,
                         const float* __restrict__ lnG, const float* __restrict__ lnB,
                         float* __restrict__ C, int M, int mode, int cb)
{
    __shared__ __align__(16) __nv_bfloat16 Ah[64][40];
    __shared__ __align__(16) __nv_bfloat16 Al[64][40];
    __shared__ __align__(16) __nv_bfloat16 Bh[128][40];
    __shared__ __align__(16) __nv_bfloat16 Bl[128][40];
    __shared__ float Sred[2][64], Qred[2][64];

    int tid = threadIdx.x, lane = tid & 31, wy = tid >> 5;
    int wm = wy >> 1, wn = wy & 1;
    int row0 = blockIdx.x * 64;

    float c[8][4];
    #pragma unroll
    for (int t = 0; t < 8; t++)
        #pragma unroll
        for (int j = 0; j < 4; j++) c[t][j] = 0.f;

    // ldmatrix per-lane addresses
    int arow = wm * 16 + (lane & 7) + ((lane >> 3) & 1) * 8;
    int akc  = (lane >> 4) * 8;
    unsigned aAh = smem_u32(&Ah[arow][akc]);
    unsigned aAl = smem_u32(&Al[arow][akc]);
    int bn = wn * 64 + (lane & 7) + ((lane >> 4) << 3);
    int bk = ((lane >> 3) & 1) * 8;
    unsigned aBh = smem_u32(&Bh[bn][bk]);
    unsigned aBl = smem_u32(&Bl[bn][bk]);

    for (int ch = 0; ch < K / 32; ch++) {
        int k0 = ch * 32;
        // stage B (copy prebuilt bf16 images): 128n x 4 parts, 2 iters
        #pragma unroll
        for (int i = 0; i < 2; i++) {
            int idx = tid + i * 256;
            int n = idx >> 2, part = idx & 3;
            const uint4* sh = reinterpret_cast<const uint4*>(Whi + (size_t)(cb + n) * K + k0);
            const uint4* sl = reinterpret_cast<const uint4*>(Whi + loN + (size_t)(cb + n) * K + k0);
            *reinterpret_cast<uint4*>(&Bh[n][part * 8]) = sh[part];
            *reinterpret_cast<uint4*>(&Bl[n][part * 8]) = sl[part];
        }
        // stage A (fp32 -> bf16 hi/lo): 64r x 8kg, 2 iters
        #pragma unroll
        for (int i = 0; i < 2; i++) {
            int idx = tid + i * 256;
            int r = idx >> 3, kg = idx & 7;
            int rr = row0 + r;
            float4 av = make_float4(0.f, 0.f, 0.f, 0.f);
            if (rr < M) {
                av = *reinterpret_cast<const float4*>(&A[(size_t)rr * K + k0 + kg * 4]);
                if (aop) {
                    float4 a2 = *reinterpret_cast<const float4*>(&g_side[(size_t)rr * K + k0 + kg * 4]);
                    if (aop == 1) { av.x += a2.x; av.y += a2.y; av.z += a2.z; av.w += a2.w; }
                    else          { av.x *= a2.x; av.y *= a2.y; av.z *= a2.z; av.w *= a2.w; }
                }
            }
            unsigned h01, l01, h23, l23;
            split2(av.x, av.y, h01, l01);
            split2(av.z, av.w, h23, l23);
            *reinterpret_cast<uint2*>(&Ah[r][kg * 4]) = make_uint2(h01, h23);
            *reinterpret_cast<uint2*>(&Al[r][kg * 4]) = make_uint2(l01, l23);
        }
        __syncthreads();

        #pragma unroll
        for (int ks = 0; ks < 2; ks++) {
            unsigned ah[4], al[4];
            ldsm4(ah, aAh + ks * 32);
            ldsm4(al, aAl + ks * 32);
            #pragma unroll
            for (int np = 0; np < 4; np++) {
                unsigned bh[4], bl[4];
                ldsm4(bh, aBh + np * 1280 + ks * 32);
                ldsm4(bl, aBl + np * 1280 + ks * 32);
                mma_bf16(c[2 * np],     ah, bh);
                mma_bf16(c[2 * np],     ah, bl);
                mma_bf16(c[2 * np],     al, bh);
                mma_bf16(c[2 * np + 1], ah, bh + 2);
                mma_bf16(c[2 * np + 1], ah, bl + 2);
                mma_bf16(c[2 * np + 1], al, bh + 2);
            }
        }
        __syncthreads();
    }

    // epilogue. lane frag: rows r0g/r1g, cols colb + nt*8 (+1), nt 0..7
    int colb = cb + wn * 64 + (lane & 3) * 2;
    int lr0 = wm * 16 + (lane >> 2);      // local row
    int r0g = row0 + lr0;
    int r1g = r0g + 8;
    bool v0 = r0g < M, v1 = r1g < M;

    if (mode == 5) {
        float s0 = 0.f, q0 = 0.f, s1 = 0.f, q1 = 0.f;
        #pragma unroll
        for (int nt = 0; nt < 8; nt++) {
            int col = colb + nt * 8;
            float2 bv = *reinterpret_cast<const float2*>(&bias[col]);
            float2 rA = v0 ? *reinterpret_cast<const float2*>(&R[(size_t)r0g * 128 + col]) : make_float2(0.f, 0.f);
            float2 rB = v1 ? *reinterpret_cast<const float2*>(&R[(size_t)r1g * 128 + col]) : make_float2(0.f, 0.f);
            c[nt][0] += bv.x + rA.x; c[nt][1] += bv.y + rA.y;
            c[nt][2] += bv.x + rB.x; c[nt][3] += bv.y + rB.y;
            s0 += c[nt][0] + c[nt][1]; q0 += c[nt][0] * c[nt][0] + c[nt][1] * c[nt][1];
            s1 += c[nt][2] + c[nt][3]; q1 += c[nt][2] * c[nt][2] + c[nt][3] * c[nt][3];
        }
        #pragma unroll
        for (int o = 1; o <= 2; o <<= 1) {
            s0 += __shfl_xor_sync(0xffffffff, s0, o);
            q0 += __shfl_xor_sync(0xffffffff, q0, o);
            s1 += __shfl_xor_sync(0xffffffff, s1, o);
            q1 += __shfl_xor_sync(0xffffffff, q1, o);
        }
        if ((lane & 3) == 0) {
            Sred[wn][lr0] = s0; Qred[wn][lr0] = q0;
            Sred[wn][lr0 + 8] = s1; Qred[wn][lr0 + 8] = q1;
        }
        __syncthreads();
        float S0 = Sred[0][lr0] + Sred[1][lr0];
        float Q0 = Qred[0][lr0] + Qred[1][lr0];
        float S1 = Sred[0][lr0 + 8] + Sred[1][lr0 + 8];
        float Q1 = Qred[0][lr0 + 8] + Qred[1][lr0 + 8];
        float m0 = S0 * (1.f / 128.f), var0 = Q0 * (1.f / 128.f) - m0 * m0;
        float m1 = S1 * (1.f / 128.f), var1 = Q1 * (1.f / 128.f) - m1 * m1;
        float rs0 = rsqrtf(var0 + 1e-5f), rs1 = rsqrtf(var1 + 1e-5f);
        #pragma unroll
        for (int nt = 0; nt < 8; nt++) {
            int col = colb + nt * 8;
            float2 g = *reinterpret_cast<const float2*>(&lnG[col]);
            float2 be = *reinterpret_cast<const float2*>(&lnB[col]);
            if (v0) {
                float2 o = make_float2((c[nt][0] - m0) * rs0 * g.x + be.x,
                                       (c[nt][1] - m0) * rs0 * g.y + be.y);
                *reinterpret_cast<float2*>(&C[(size_t)r0g * 128 + col]) = o;
            }
            if (v1) {
                float2 o = make_float2((c[nt][2] - m1) * rs1 * g.x + be.x,
                                       (c[nt][3] - m1) * rs1 * g.y + be.y);
                *reinterpret_cast<float2*>(&C[(size_t)r1g * 128 + col]) = o;
            }
        }
    } else {
        #pragma unroll
        for (int nt = 0; nt < 8; nt++) {
            int col = colb + nt * 8;
            float2 bv = *reinterpret_cast<const float2*>(&bias[col]);
            float x0 = c[nt][0] + bv.x, x1 = c[nt][1] + bv.y;
            float x2 = c[nt][2] + bv.x, x3 = c[nt][3] + bv.y;
            if (mode == 1) {
                x0 = fmaxf(x0, 0.f); x1 = fmaxf(x1, 0.f);
                x2 = fmaxf(x2, 0.f); x3 = fmaxf(x3, 0.f);
            } else if (mode == 3 || mode == 4) {
                x0 = (x0 > 0.f) ? x0 : 0.01f * x0;
                x1 = (x1 > 0.f) ? x1 : 0.01f * x1;
                x2 = (x2 > 0.f) ? x2 : 0.01f * x2;
                x3 = (x3 > 0.f) ? x3 : 0.01f * x3;
                if (mode == 4) {
                    if (v0) {
                        float2 cv = *reinterpret_cast<const float2*>(&C[(size_t)r0g * NOUT + col]);
                        x0 += cv.x; x1 += cv.y;
                    }
                    if (v1) {
                        float2 cv = *reinterpret_cast<const float2*>(&C[(size_t)r1g * NOUT + col]);
                        x2 += cv.x; x3 += cv.y;
                    }
                }
            }
            if (v0) *reinterpret_cast<float2*>(&C[(size_t)r0g * NOUT + col]) = make_float2(x0, x1);
            if (v1) *reinterpret_cast<float2*>(&C[(size_t)r1g * NOUT + col]) = make_float2(x2, x3);
        }
    }
}

template<int K, int NOUT>
__global__ void __launch_bounds__(256) mma_gemm_kernel(
    const float* __restrict__ Aext, int Aid, int aop,
    unsigned woff, int loN,
    const float* __restrict__ bias,
    int Rid, const float* __restrict__ Rext,
    const float* __restrict__ lnG, const float* __restrict__ lnB,
    float* __restrict__ Cext, int Cid, int M, int mode)
{
    const float* A = Aext ? Aext : bufptr(Aid);
    float*       C = Cext ? Cext : bufptr(Cid);
    const float* R = nullptr;
    if (mode == 5) R = Rext ? Rext : bufptr(Rid);
    int cb = (NOUT > 128) ? blockIdx.y * 128 : 0;
    mma_core<K, NOUT>(A, aop, g_wbf + woff, loN, bias, R, lnG, lnB, C, M, mode, cb);
}

// qkv fused: grid.y selects q/k/v
__global__ void __launch_bounds__(256) mma_qkv_kernel(
    const float* __restrict__ Aext, int Aid, unsigned wbase,
    const float* __restrict__ bq, const float* __restrict__ bk,
    const float* __restrict__ bv, int M)
{
    int sel = blockIdx.y;
    const float* bias = (sel == 0) ? bq : (sel == 1) ? bk : bv;
    const float* A = Aext ? Aext : bufptr(Aid);
    mma_core<128, 128>(A, 0, g_wbf + wbase + sel * 32768u, 16384,
                       bias, nullptr, nullptr, nullptr, bufptr(BQ + sel), M, 0, 0);
}

// ------------------------------ attention (f32x2) ------------------------------
__global__ void __launch_bounds__(256) attn_kernel(int unused)
{
    __shared__ __align__(16) float Ks[LSEQ * DK];
    __shared__ __align__(16) float Vs[LSEQ * DK];
    int b = blockIdx.x >> 3;
    int h = blockIdx.x & 7;
    int tid = threadIdx.x;
    int base = (b * LSEQ) * D + h * DK;

    for (int idx = tid; idx < LSEQ * DK; idx += 256) {
        int m = idx >> 4, j = idx & 15;
        Ks[idx] = g_k[base + m * D + j];
        Vs[idx] = g_v[base + m * D + j];
    }
    __syncthreads();

    unsigned long long q2[8];
    {
        const unsigned long long* qp = reinterpret_cast<const unsigned long long*>(g_q + base + tid * D);
        #pragma unroll
        for (int j = 0; j < 8; j++) q2[j] = qp[j];
    }

    unsigned long long acc[8];
    const unsigned long long z2 = pack2(0.f, 0.f);
    #pragma unroll
    for (int j = 0; j < 8; j++) acc[j] = z2;
    float mx = -3.0e38f, sum = 0.f;

    const unsigned long long* Ks2 = reinterpret_cast<const unsigned long long*>(Ks);
    const unsigned long long* Vs2 = reinterpret_cast<const unsigned long long*>(Vs);

    for (int m = 0; m < LSEQ; m++) {
        unsigned long long d2 = z2;
        #pragma unroll
        for (int j = 0; j < 8; j++)
            ffma2(d2, q2[j], Ks2[m * 8 + j]);
        float lo, hi;
        unpack2(d2, lo, hi);
        float s = (lo + hi) * 0.25f;

        if (s <= mx) {
            float pe = __expf(s - mx);
            sum += pe;
            unsigned long long pe2 = pack2(pe, pe);
            #pragma unroll
            for (int j = 0; j < 8; j++)
                ffma2(acc[j], Vs2[m * 8 + j], pe2);
        } else {
            float corr = __expf(mx - s);
            sum = sum * corr + 1.f;
            unsigned long long c2 = pack2(corr, corr);
            #pragma unroll
            for (int j = 0; j < 8; j++) {
                unsigned long long t;
                fmul2(t, acc[j], c2);
                fadd2(acc[j], t, Vs2[m * 8 + j]);
            }
            mx = s;
        }
    }

    float inv = 1.f / sum;
    float* op = g_o + base + tid * D;
    #pragma unroll
    for (int j = 0; j < 8; j++) {
        float lo, hi;
        unpack2(acc[j], lo, hi);
        op[j * 2 + 0] = lo * inv;
        op[j * 2 + 1] = hi * inv;
    }
}

// ------------------------------ launch ------------------------------
extern "C" void kernel_launch(void* const* d_in, const int* in_sizes, int n_in,
                              void* d_out, int out_size)
{
    const float* ego    = (const float*)d_in[0];
    const float* vals   = (const float*)d_in[1];
    const float* W1     = (const float*)d_in[2];
    const float* b1     = (const float*)d_in[3];
    const float* W2     = (const float*)d_in[4];
    const float* b2     = (const float*)d_in[5];
    const float* enc_in = (const float*)d_in[6];
    const float* wq     = (const float*)d_in[7];
    const float* bq     = (const float*)d_in[8];
    const float* wk     = (const float*)d_in[9];
    const float* bk     = (const float*)d_in[10];
    const float* wv     = (const float*)d_in[11];
    const float* bv     = (const float*)d_in[12];
    const float* wo     = (const float*)d_in[13];
    const float* bo     = (const float*)d_in[14];
    const float* ln1_g  = (const float*)d_in[15];
    const float* ln1_b  = (const float*)d_in[16];
    const float* cw1    = (const float*)d_in[17];
    const float* cb1    = (const float*)d_in[18];
    const float* cw2    = (const float*)d_in[19];
    const float* cb2    = (const float*)d_in[20];
    const float* ln2_g  = (const float*)d_in[21];
    const float* ln2_b  = (const float*)d_in[22];
    const int*   rows   = (const int*)d_in[23];
    const int*   cols   = (const int*)d_in[24];
    float* out = (float*)d_out;

    int Nego = in_sizes[0] / 128;       // 100000
    int nnz  = in_sizes[1];             // 2000000
    int Mt   = in_sizes[6] / 128;       // 8192
    int B    = Mt / LSEQ;               // 32
    int NL   = in_sizes[7] / (128 * 128);

    // ---- weight images ----
    prep_w_kernel<<<dim3(64, 2 + 6 * NL), 256>>>(W1, W2, wq, wk, wv, wo, cw1, cw2, NL);

    // ---- graph side ----
    zero_side_kernel<<<1024, 256>>>((Nego * 128) / 4);
    int nwarps = (nnz + EPW - 1) / EPW;
    int spmm_blocks = (nwarps * 32 + 255) / 256;
    spmm_kernel<<<spmm_blocks, 256>>>(ego, vals, rows, cols, nnz);

    int agg_blocks = (Nego + 63) / 64;
    // agg1: leaky((ego+side)@W1 + b1) -> out
    mma_gemm_kernel<128, 128><<<agg_blocks, 256>>>(ego, -1, 1, 0u, 16384, b1,
                                                   -1, nullptr, nullptr, nullptr,
                                                   out, -1, Nego, 3);
    // agg2: += leaky((ego*side)@W2 + b2)
    mma_gemm_kernel<128, 128><<<agg_blocks, 256>>>(ego, -1, 2, 32768u, 16384, b2,
                                                   -1, nullptr, nullptr, nullptr,
                                                   out, -1, Nego, 4);

    // ---- transformer encoder ----
    const float* xin_ext = enc_in;
    int xin_id = -1;
    int gb = Mt / 64;   // 128

    for (int i = 0; i < NL; i++) {
        unsigned lbase = 65536u + (unsigned)i * 393216u;
        const float* bq_ = bq + i * D;
        const float* bk_ = bk + i * D;
        const float* bv_ = bv + i * D;
        const float* bo_ = bo + i * D;
        const float* g1_ = ln1_g + i * D;  const float* be1_ = ln1_b + i * D;
        const float* cb1_ = cb1 + i * DI;
        const float* cb2_ = cb2 + i * D;
        const float* g2_ = ln2_g + i * D;  const float* be2_ = ln2_b + i * D;

        // QKV (grid.y = 3)
        mma_qkv_kernel<<<dim3(gb, 3), 256>>>(xin_ext, xin_id, lbase, bq_, bk_, bv_, Mt);
        attn_kernel<<<B * 8, 256>>>(0);
        // wo + residual + LN1 -> BX1
        mma_gemm_kernel<128, 128><<<gb, 256>>>(nullptr, BO, 0, lbase + 3u * 32768u, 16384, bo_,
                                               xin_id, xin_ext, g1_, be1_, nullptr, BX1, Mt, 5);
        // FFN1 relu -> BH  (grid.y = 4 over N=512)
        mma_gemm_kernel<128, 512><<<dim3(gb, 4), 256>>>(nullptr, BX1, 0, lbase + 131072u, 65536, cb1_,
                                                        -1, nullptr, nullptr, nullptr, nullptr, BH, Mt, 1);
        // FFN2 + residual(BX1) + LN2 -> BX2 (or final out)
        bool last = (i == NL - 1);
        mma_gemm_kernel<512, 128><<<gb, 256>>>(nullptr, BH, 0, lbase + 262144u, 65536, cb2_,
                                               BX1, nullptr, g2_, be2_,
                                               last ? (out + (size_t)in_sizes[0]) : nullptr,
                                               BX2, Mt, 5);
        xin_ext = nullptr;
        xin_id = BX2;
    }
}

// round 11
// speedup vs baseline: 1.5735x; 1.1245x over previous
#include <cuda_runtime.h>
#include <cuda_bf16.h>
#include <math.h>

#define DEV_INLINE __device__ __forceinline__

static const int D    = 128;
static const int LSEQ = 256;
static const int DK   = 16;
static const int DI   = 512;

// ------------------------- scratch (device globals) -------------------------
__device__ float g_side[12800000];   // side = A_in @ ego
__device__ float g_q [1048576];
__device__ float g_k [1048576];
__device__ float g_v [1048576];
__device__ float g_o [1048576];
__device__ float g_x1[1048576];
__device__ float g_x2[1048576];
__device__ float g_h [4194304];      // 8192 x 512
__device__ __align__(16) __nv_bfloat16 g_wbf[1048576];  // weight bf16 hi/lo images, [n][k]

enum { BQ = 0, BK = 1, BV = 2, BO = 3, BX1 = 5, BX2 = 6, BH = 7 };

DEV_INLINE float* bufptr(int id) {
    switch (id) {
        case BQ:  return g_q;
        case BK:  return g_k;
        case BV:  return g_v;
        case BO:  return g_o;
        case BX1: return g_x1;
        case BX2: return g_x2;
        case BH:  return g_h;
    }
    return nullptr;
}

// ------------------------- f32x2 helpers (attention) -------------------------
DEV_INLINE unsigned long long pack2(float lo, float hi) {
    unsigned long long r;
    asm("mov.b64 %0, {%1, %2};" : "=l"(r) : "f"(lo), "f"(hi));
    return r;
}
DEV_INLINE void unpack2(unsigned long long v, float& lo, float& hi) {
    asm("mov.b64 {%0, %1}, %2;" : "=f"(lo), "=f"(hi) : "l"(v));
}
DEV_INLINE void ffma2(unsigned long long& d, unsigned long long a, unsigned long long b) {
    asm("fma.rn.f32x2 %0, %1, %2, %0;" : "+l"(d) : "l"(a), "l"(b));
}
DEV_INLINE void fmul2(unsigned long long& d, unsigned long long a, unsigned long long b) {
    asm("mul.rn.f32x2 %0, %1, %2;" : "=l"(d) : "l"(a), "l"(b));
}
DEV_INLINE void fadd2(unsigned long long& d, unsigned long long a, unsigned long long b) {
    asm("add.rn.f32x2 %0, %1, %2;" : "=l"(d) : "l"(a), "l"(b));
}

// ------------------------- mma helpers -------------------------
DEV_INLINE unsigned smem_u32(const void* p) {
    unsigned a;
    asm("{ .reg .u64 t; cvta.to.shared.u64 t, %1; cvt.u32.u64 %0, t; }" : "=r"(a) : "l"(p));
    return a;
}
DEV_INLINE void ldsm4(unsigned* r, unsigned addr) {
    asm volatile("ldmatrix.sync.aligned.m8n8.x4.shared.b16 {%0,%1,%2,%3}, [%4];"
        : "=r"(r[0]), "=r"(r[1]), "=r"(r[2]), "=r"(r[3]) : "r"(addr));
}
DEV_INLINE void mma_bf16(float* c, const unsigned* a, const unsigned* b) {
    asm volatile(
        "mma.sync.aligned.m16n8k16.row.col.f32.bf16.bf16.f32 "
        "{%0,%1,%2,%3}, {%4,%5,%6,%7}, {%8,%9}, {%0,%1,%2,%3};"
        : "+f"(c[0]), "+f"(c[1]), "+f"(c[2]), "+f"(c[3])
        : "r"(a[0]), "r"(a[1]), "r"(a[2]), "r"(a[3]), "r"(b[0]), "r"(b[1]));
}
DEV_INLINE void split2(float x, float y, unsigned& h, unsigned& l) {
    __nv_bfloat162 hv = __floats2bfloat162_rn(x, y);
    float lx = x - __bfloat162float(hv.x);
    float ly = y - __bfloat162float(hv.y);
    __nv_bfloat162 lv = __floats2bfloat162_rn(lx, ly);
    h = *reinterpret_cast<unsigned*>(&hv);
    l = *reinterpret_cast<unsigned*>(&lv);
}

// ------------------------------ zero side ------------------------------
__global__ void zero_side_kernel(int n4) {
    float4* p = reinterpret_cast<float4*>(g_side);
    int i = blockIdx.x * blockDim.x + threadIdx.x;
    int stride = gridDim.x * blockDim.x;
    float4 z = make_float4(0.f, 0.f, 0.f, 0.f);
    for (; i < n4; i += stride) p[i] = z;
}

// ------------------------------ SpMM (COO, rows sorted) ------------------------------
static const int EPW = 256;

DEV_INLINE void spmm_flush(int row, int lane, float4 acc) {
    float* p = &g_side[(size_t)row * 128 + lane * 4];
    atomicAdd(p + 0, acc.x);
    atomicAdd(p + 1, acc.y);
    atomicAdd(p + 2, acc.z);
    atomicAdd(p + 3, acc.w);
}

__global__ void __launch_bounds__(256) spmm_kernel(
    const float* __restrict__ ego, const float* __restrict__ vals,
    const int* __restrict__ rows, const int* __restrict__ cols, int nnz)
{
    int warp = (blockIdx.x * blockDim.x + threadIdx.x) >> 5;
    int lane = threadIdx.x & 31;
    long e0 = (long)warp * EPW;
    if (e0 >= nnz) return;
    long e1 = e0 + EPW; if (e1 > nnz) e1 = nnz;

    const float4* ego4 = reinterpret_cast<const float4*>(ego);
    float4 acc = make_float4(0.f, 0.f, 0.f, 0.f);
    int cur = rows[e0];
    for (long e = e0; e < e1; e++) {
        int r = rows[e];
        if (r != cur) {
            spmm_flush(cur, lane, acc);
            acc = make_float4(0.f, 0.f, 0.f, 0.f);
            cur = r;
        }
        float v  = vals[e];
        float4 g = ego4[(size_t)cols[e] * 32 + lane];
        acc.x += v * g.x; acc.y += v * g.y; acc.z += v * g.z; acc.w += v * g.w;
    }
    spmm_flush(cur, lane, acc);
}

// ------------------------------ prep: weight bf16 hi/lo images, [n][k] ------------------------------
__global__ void __launch_bounds__(256) prep_w_kernel(
    const float* __restrict__ W1, const float* __restrict__ W2,
    const float* __restrict__ wq, const float* __restrict__ wk,
    const float* __restrict__ wv, const float* __restrict__ wo,
    const float* __restrict__ cw1, const float* __restrict__ cw2, int NL)
{
    int y = blockIdx.y;
    const float* src; unsigned off; int Kd, Nd;
    if (y < 2) { src = y ? W2 : W1; off = (unsigned)y * 32768u; Kd = 128; Nd = 128; }
    else {
        int i = (y - 2) / 6, j = (y - 2) % 6;
        unsigned base = 65536u + (unsigned)i * 393216u;
        if (j < 4) {
            const float* p = (j == 0) ? wq : (j == 1) ? wk : (j == 2) ? wv : wo;
            src = p + (size_t)i * 16384; off = base + (unsigned)j * 32768u; Kd = 128; Nd = 128;
        } else if (j == 4) {
            src = cw1 + (size_t)i * 65536; off = base + 131072u; Kd = 128; Nd = 512;
        } else {
            src = cw2 + (size_t)i * 65536; off = base + 262144u; Kd = 512; Nd = 128;
        }
    }
    int tot = Kd * Nd;
    for (int idx = blockIdx.x * 256 + threadIdx.x; idx < tot; idx += gridDim.x * 256) {
        int n = idx / Kd, k = idx - n * Kd;
        float w = src[(size_t)k * Nd + n];
        __nv_bfloat16 h = __float2bfloat16(w);
        float l = w - __bfloat162float(h);
        g_wbf[off + (size_t)n * Kd + k] = h;
        g_wbf[off + (size_t)tot + (size_t)n * Kd + k] = __float2bfloat16(l);
    }
}

// ------------------------------ fused aggregator (bf16x3 mma, both GEMMs one pass) ------------------------------
// out = leaky((ego+side)@W1+b1) + leaky((ego*side)@W2+b2)
// CTA 256 thr (8 warps, 4m x 2n), tile 64m x 128n, dynamic smem.
// Dyn smem layout (bytes): Ah 0, Al 5120, Ph 10240, Pl 15360,
//                          B1h 20480, B1l 30720, B2h 40960, B2l 51200; total 61440.
__global__ void __launch_bounds__(256, 2) agg_mma_kernel(
    const float* __restrict__ ego,
    const float* __restrict__ b1, const float* __restrict__ b2,
    float* __restrict__ out, int M)
{
    extern __shared__ __align__(16) char dsm[];
    __nv_bfloat16* Ah  = reinterpret_cast<__nv_bfloat16*>(dsm);
    __nv_bfloat16* Al  = reinterpret_cast<__nv_bfloat16*>(dsm + 5120);
    __nv_bfloat16* Ph  = reinterpret_cast<__nv_bfloat16*>(dsm + 10240);
    __nv_bfloat16* Pl  = reinterpret_cast<__nv_bfloat16*>(dsm + 15360);
    __nv_bfloat16* B1h = reinterpret_cast<__nv_bfloat16*>(dsm + 20480);
    __nv_bfloat16* B1l = reinterpret_cast<__nv_bfloat16*>(dsm + 30720);
    __nv_bfloat16* B2h = reinterpret_cast<__nv_bfloat16*>(dsm + 40960);
    __nv_bfloat16* B2l = reinterpret_cast<__nv_bfloat16*>(dsm + 51200);

    int tid = threadIdx.x, lane = tid & 31, wy = tid >> 5;
    int wm = wy >> 1, wn = wy & 1;
    int row0 = blockIdx.x * 64;

    float c1[8][4], c2[8][4];
    #pragma unroll
    for (int t = 0; t < 8; t++)
        #pragma unroll
        for (int j = 0; j < 4; j++) { c1[t][j] = 0.f; c2[t][j] = 0.f; }

    // ldmatrix lane addresses (row stride 40 bf16 = 80 B)
    int arow = wm * 16 + (lane & 7) + ((lane >> 3) & 1) * 8;
    int akc  = (lane >> 4) * 8;
    unsigned aAh = smem_u32(&Ah[arow * 40 + akc]);
    unsigned aAl = smem_u32(&Al[arow * 40 + akc]);
    unsigned aPh = smem_u32(&Ph[arow * 40 + akc]);
    unsigned aPl = smem_u32(&Pl[arow * 40 + akc]);
    int bn = wn * 64 + (lane & 7) + ((lane >> 4) << 3);
    int bk = ((lane >> 3) & 1) * 8;
    unsigned aB1h = smem_u32(&B1h[bn * 40 + bk]);
    unsigned aB1l = smem_u32(&B1l[bn * 40 + bk]);
    unsigned aB2h = smem_u32(&B2h[bn * 40 + bk]);
    unsigned aB2l = smem_u32(&B2l[bn * 40 + bk]);

    const __nv_bfloat16* W1h = g_wbf;            // [128][128] hi
    const __nv_bfloat16* W1l = g_wbf + 16384;
    const __nv_bfloat16* W2h = g_wbf + 32768;
    const __nv_bfloat16* W2l = g_wbf + 49152;

    for (int ch = 0; ch < 4; ch++) {
        int k0 = ch * 32;
        // stage W1/W2 chunk: 128 n x 32 k (4 parts of 8)
        #pragma unroll
        for (int i = 0; i < 2; i++) {
            int idx = tid + i * 256;
            int n = idx >> 2, part = idx & 3;
            size_t go = (size_t)n * 128 + k0;
            *reinterpret_cast<uint4*>(&B1h[n * 40 + part * 8]) = reinterpret_cast<const uint4*>(W1h + go)[part];
            *reinterpret_cast<uint4*>(&B1l[n * 40 + part * 8]) = reinterpret_cast<const uint4*>(W1l + go)[part];
            *reinterpret_cast<uint4*>(&B2h[n * 40 + part * 8]) = reinterpret_cast<const uint4*>(W2h + go)[part];
            *reinterpret_cast<uint4*>(&B2l[n * 40 + part * 8]) = reinterpret_cast<const uint4*>(W2l + go)[part];
        }
        // stage A: sum & prod hi/lo
        #pragma unroll
        for (int i = 0; i < 2; i++) {
            int idx = tid + i * 256;
            int r = idx >> 3, kg = idx & 7;
            int rr = row0 + r;
            float4 e = make_float4(0.f, 0.f, 0.f, 0.f);
            float4 s = make_float4(0.f, 0.f, 0.f, 0.f);
            if (rr < M) {
                e = *reinterpret_cast<const float4*>(&ego   [(size_t)rr * 128 + k0 + kg * 4]);
                s = *reinterpret_cast<const float4*>(&g_side[(size_t)rr * 128 + k0 + kg * 4]);
            }
            float sx = e.x + s.x, sy = e.y + s.y, sz = e.z + s.z, sw = e.w + s.w;
            float px = e.x * s.x, py = e.y * s.y, pz = e.z * s.z, pw = e.w * s.w;
            unsigned h01, l01, h23, l23;
            split2(sx, sy, h01, l01); split2(sz, sw, h23, l23);
            *reinterpret_cast<uint2*>(&Ah[r * 40 + kg * 4]) = make_uint2(h01, h23);
            *reinterpret_cast<uint2*>(&Al[r * 40 + kg * 4]) = make_uint2(l01, l23);
            split2(px, py, h01, l01); split2(pz, pw, h23, l23);
            *reinterpret_cast<uint2*>(&Ph[r * 40 + kg * 4]) = make_uint2(h01, h23);
            *reinterpret_cast<uint2*>(&Pl[r * 40 + kg * 4]) = make_uint2(l01, l23);
        }
        __syncthreads();

        #pragma unroll
        for (int ks = 0; ks < 2; ks++) {
            unsigned sh[4], sl[4], ph[4], pl[4];
            ldsm4(sh, aAh + ks * 32);
            ldsm4(sl, aAl + ks * 32);
            ldsm4(ph, aPh + ks * 32);
            ldsm4(pl, aPl + ks * 32);
            #pragma unroll
            for (int np = 0; np < 4; np++) {
                unsigned b1h[4], b1l[4], b2h[4], b2l[4];
                ldsm4(b1h, aB1h + np * 1280 + ks * 32);
                ldsm4(b1l, aB1l + np * 1280 + ks * 32);
                ldsm4(b2h, aB2h + np * 1280 + ks * 32);
                ldsm4(b2l, aB2l + np * 1280 + ks * 32);
                mma_bf16(c1[2 * np],     sh, b1h);
                mma_bf16(c1[2 * np],     sh, b1l);
                mma_bf16(c1[2 * np],     sl, b1h);
                mma_bf16(c1[2 * np + 1], sh, b1h + 2);
                mma_bf16(c1[2 * np + 1], sh, b1l + 2);
                mma_bf16(c1[2 * np + 1], sl, b1h + 2);
                mma_bf16(c2[2 * np],     ph, b2h);
                mma_bf16(c2[2 * np],     ph, b2l);
                mma_bf16(c2[2 * np],     pl, b2h);
                mma_bf16(c2[2 * np + 1], ph, b2h + 2);
                mma_bf16(c2[2 * np + 1], ph, b2l + 2);
                mma_bf16(c2[2 * np + 1], pl, b2h + 2);
            }
        }
        __syncthreads();
    }

    // epilogue: out = leaky(c1+b1) + leaky(c2+b2)
    int colb = wn * 64 + (lane & 3) * 2;
    int r0g = row0 + wm * 16 + (lane >> 2);
    int r1g = r0g + 8;
    bool v0 = r0g < M, v1 = r1g < M;
    #pragma unroll
    for (int nt = 0; nt < 8; nt++) {
        int col = colb + nt * 8;
        float2 bv1 = *reinterpret_cast<const float2*>(&b1[col]);
        float2 bv2 = *reinterpret_cast<const float2*>(&b2[col]);
        float x0 = c1[nt][0] + bv1.x, x1 = c1[nt][1] + bv1.y;
        float x2 = c1[nt][2] + bv1.x, x3 = c1[nt][3] + bv1.y;
        float y0 = c2[nt][0] + bv2.x, y1 = c2[nt][1] + bv2.y;
        float y2 = c2[nt][2] + bv2.x, y3 = c2[nt][3] + bv2.y;
        x0 = (x0 > 0.f) ? x0 : 0.01f * x0;  y0 = (y0 > 0.f) ? y0 : 0.01f * y0;
        x1 = (x1 > 0.f) ? x1 : 0.01f * x1;  y1 = (y1 > 0.f) ? y1 : 0.01f * y1;
        x2 = (x2 > 0.f) ? x2 : 0.01f * x2;  y2 = (y2 > 0.f) ? y2 : 0.01f * y2;
        x3 = (x3 > 0.f) ? x3 : 0.01f * x3;  y3 = (y3 > 0.f) ? y3 : 0.01f * y3;
        if (v0) *reinterpret_cast<float2*>(&out[(size_t)r0g * 128 + col]) = make_float2(x0 + y0, x1 + y1);
        if (v1) *reinterpret_cast<float2*>(&out[(size_t)r1g * 128 + col]) = make_float2(x2 + y2, x3 + y3);
    }
}

// ------------------------------ bf16x3 mma GEMM core (256 thr, 8 warps 4m x 2n) ------------------------------
// modes: 0 +bias store, 1 +bias relu, 5 +bias +res +LN
template<int K, int NOUT>
DEV_INLINE void mma_core(const float* __restrict__ A,
                         const __nv_bfloat16* __restrict__ Whi, int loN,
                         const float* __restrict__ bias, const float* __restrict__ R,
                         const float* __restrict__ lnG, const float* __restrict__ lnB,
                         float* __restrict__ C, int M, int mode, int cb)
{
    __shared__ __align__(16) __nv_bfloat16 Ah[64][40];
    __shared__ __align__(16) __nv_bfloat16 Al[64][40];
    __shared__ __align__(16) __nv_bfloat16 Bh[128][40];
    __shared__ __align__(16) __nv_bfloat16 Bl[128][40];
    __shared__ float Sred[2][64], Qred[2][64];

    int tid = threadIdx.x, lane = tid & 31, wy = tid >> 5;
    int wm = wy >> 1, wn = wy & 1;
    int row0 = blockIdx.x * 64;

    float c[8][4];
    #pragma unroll
    for (int t = 0; t < 8; t++)
        #pragma unroll
        for (int j = 0; j < 4; j++) c[t][j] = 0.f;

    int arow = wm * 16 + (lane & 7) + ((lane >> 3) & 1) * 8;
    int akc  = (lane >> 4) * 8;
    unsigned aAh = smem_u32(&Ah[arow][akc]);
    unsigned aAl = smem_u32(&Al[arow][akc]);
    int bn = wn * 64 + (lane & 7) + ((lane >> 4) << 3);
    int bk = ((lane >> 3) & 1) * 8;
    unsigned aBh = smem_u32(&Bh[bn][bk]);
    unsigned aBl = smem_u32(&Bl[bn][bk]);

    for (int ch = 0; ch < K / 32; ch++) {
        int k0 = ch * 32;
        #pragma unroll
        for (int i = 0; i < 2; i++) {
            int idx = tid + i * 256;
            int n = idx >> 2, part = idx & 3;
            const uint4* sh = reinterpret_cast<const uint4*>(Whi + (size_t)(cb + n) * K + k0);
            const uint4* sl = reinterpret_cast<const uint4*>(Whi + loN + (size_t)(cb + n) * K + k0);
            *reinterpret_cast<uint4*>(&Bh[n][part * 8]) = sh[part];
            *reinterpret_cast<uint4*>(&Bl[n][part * 8]) = sl[part];
        }
        #pragma unroll
        for (int i = 0; i < 2; i++) {
            int idx = tid + i * 256;
            int r = idx >> 3, kg = idx & 7;
            int rr = row0 + r;
            float4 av = make_float4(0.f, 0.f, 0.f, 0.f);
            if (rr < M)
                av = *reinterpret_cast<const float4*>(&A[(size_t)rr * K + k0 + kg * 4]);
            unsigned h01, l01, h23, l23;
            split2(av.x, av.y, h01, l01);
            split2(av.z, av.w, h23, l23);
            *reinterpret_cast<uint2*>(&Ah[r][kg * 4]) = make_uint2(h01, h23);
            *reinterpret_cast<uint2*>(&Al[r][kg * 4]) = make_uint2(l01, l23);
        }
        __syncthreads();

        #pragma unroll
        for (int ks = 0; ks < 2; ks++) {
            unsigned ah[4], al[4];
            ldsm4(ah, aAh + ks * 32);
            ldsm4(al, aAl + ks * 32);
            #pragma unroll
            for (int np = 0; np < 4; np++) {
                unsigned bh[4], bl[4];
                ldsm4(bh, aBh + np * 1280 + ks * 32);
                ldsm4(bl, aBl + np * 1280 + ks * 32);
                mma_bf16(c[2 * np],     ah, bh);
                mma_bf16(c[2 * np],     ah, bl);
                mma_bf16(c[2 * np],     al, bh);
                mma_bf16(c[2 * np + 1], ah, bh + 2);
                mma_bf16(c[2 * np + 1], ah, bl + 2);
                mma_bf16(c[2 * np + 1], al, bh + 2);
            }
        }
        __syncthreads();
    }

    int colb = cb + wn * 64 + (lane & 3) * 2;
    int lr0 = wm * 16 + (lane >> 2);
    int r0g = row0 + lr0;
    int r1g = r0g + 8;
    bool v0 = r0g < M, v1 = r1g < M;

    if (mode == 5) {
        float s0 = 0.f, q0 = 0.f, s1 = 0.f, q1 = 0.f;
        #pragma unroll
        for (int nt = 0; nt < 8; nt++) {
            int col = colb + nt * 8;
            float2 bv = *reinterpret_cast<const float2*>(&bias[col]);
            float2 rA = v0 ? *reinterpret_cast<const float2*>(&R[(size_t)r0g * 128 + col]) : make_float2(0.f, 0.f);
            float2 rB = v1 ? *reinterpret_cast<const float2*>(&R[(size_t)r1g * 128 + col]) : make_float2(0.f, 0.f);
            c[nt][0] += bv.x + rA.x; c[nt][1] += bv.y + rA.y;
            c[nt][2] += bv.x + rB.x; c[nt][3] += bv.y + rB.y;
            s0 += c[nt][0] + c[nt][1]; q0 += c[nt][0] * c[nt][0] + c[nt][1] * c[nt][1];
            s1 += c[nt][2] + c[nt][3]; q1 += c[nt][2] * c[nt][2] + c[nt][3] * c[nt][3];
        }
        #pragma unroll
        for (int o = 1; o <= 2; o <<= 1) {
            s0 += __shfl_xor_sync(0xffffffff, s0, o);
            q0 += __shfl_xor_sync(0xffffffff, q0, o);
            s1 += __shfl_xor_sync(0xffffffff, s1, o);
            q1 += __shfl_xor_sync(0xffffffff, q1, o);
        }
        if ((lane & 3) == 0) {
            Sred[wn][lr0] = s0; Qred[wn][lr0] = q0;
            Sred[wn][lr0 + 8] = s1; Qred[wn][lr0 + 8] = q1;
        }
        __syncthreads();
        float S0 = Sred[0][lr0] + Sred[1][lr0];
        float Q0 = Qred[0][lr0] + Qred[1][lr0];
        float S1 = Sred[0][lr0 + 8] + Sred[1][lr0 + 8];
        float Q1 = Qred[0][lr0 + 8] + Qred[1][lr0 + 8];
        float m0 = S0 * (1.f / 128.f), var0 = Q0 * (1.f / 128.f) - m0 * m0;
        float m1 = S1 * (1.f / 128.f), var1 = Q1 * (1.f / 128.f) - m1 * m1;
        float rs0 = rsqrtf(var0 + 1e-5f), rs1 = rsqrtf(var1 + 1e-5f);
        #pragma unroll
        for (int nt = 0; nt < 8; nt++) {
            int col = colb + nt * 8;
            float2 g = *reinterpret_cast<const float2*>(&lnG[col]);
            float2 be = *reinterpret_cast<const float2*>(&lnB[col]);
            if (v0) {
                float2 o = make_float2((c[nt][0] - m0) * rs0 * g.x + be.x,
                                       (c[nt][1] - m0) * rs0 * g.y + be.y);
                *reinterpret_cast<float2*>(&C[(size_t)r0g * 128 + col]) = o;
            }
            if (v1) {
                float2 o = make_float2((c[nt][2] - m1) * rs1 * g.x + be.x,
                                       (c[nt][3] - m1) * rs1 * g.y + be.y);
                *reinterpret_cast<float2*>(&C[(size_t)r1g * 128 + col]) = o;
            }
        }
    } else {
        #pragma unroll
        for (int nt = 0; nt < 8; nt++) {
            int col = colb + nt * 8;
            float2 bv = *reinterpret_cast<const float2*>(&bias[col]);
            float x0 = c[nt][0] + bv.x, x1 = c[nt][1] + bv.y;
            float x2 = c[nt][2] + bv.x, x3 = c[nt][3] + bv.y;
            if (mode == 1) {
                x0 = fmaxf(x0, 0.f); x1 = fmaxf(x1, 0.f);
                x2 = fmaxf(x2, 0.f); x3 = fmaxf(x3, 0.f);
            }
            if (v0) *reinterpret_cast<float2*>(&C[(size_t)r0g * NOUT + col]) = make_float2(x0, x1);
            if (v1) *reinterpret_cast<float2*>(&C[(size_t)r1g * NOUT + col]) = make_float2(x2, x3);
        }
    }
}

template<int K, int NOUT>
__global__ void __launch_bounds__(256) mma_gemm_kernel(
    const float* __restrict__ Aext, int Aid,
    unsigned woff, int loN,
    const float* __restrict__ bias,
    int Rid, const float* __restrict__ Rext,
    const float* __restrict__ lnG, const float* __restrict__ lnB,
    float* __restrict__ Cext, int Cid, int M, int mode)
{
    const float* A = Aext ? Aext : bufptr(Aid);
    float*       C = Cext ? Cext : bufptr(Cid);
    const float* R = nullptr;
    if (mode == 5) R = Rext ? Rext : bufptr(Rid);
    int cb = (NOUT > 128) ? blockIdx.y * 128 : 0;
    mma_core<K, NOUT>(A, g_wbf + woff, loN, bias, R, lnG, lnB, C, M, mode, cb);
}

// qkv fused: grid.y selects q/k/v
__global__ void __launch_bounds__(256) mma_qkv_kernel(
    const float* __restrict__ Aext, int Aid, unsigned wbase,
    const float* __restrict__ bq, const float* __restrict__ bk,
    const float* __restrict__ bv, int M)
{
    int sel = blockIdx.y;
    const float* bias = (sel == 0) ? bq : (sel == 1) ? bk : bv;
    const float* A = Aext ? Aext : bufptr(Aid);
    mma_core<128, 128>(A, g_wbf + wbase + sel * 32768u, 16384,
                       bias, nullptr, nullptr, nullptr, bufptr(BQ + sel), M, 0, 0);
}

// ------------------------------ attention (f32x2) ------------------------------
__global__ void __launch_bounds__(256) attn_kernel(int unused)
{
    __shared__ __align__(16) float Ks[LSEQ * DK];
    __shared__ __align__(16) float Vs[LSEQ * DK];
    int b = blockIdx.x >> 3;
    int h = blockIdx.x & 7;
    int tid = threadIdx.x;
    int base = (b * LSEQ) * D + h * DK;

    for (int idx = tid; idx < LSEQ * DK; idx += 256) {
        int m = idx >> 4, j = idx & 15;
        Ks[idx] = g_k[base + m * D + j];
        Vs[idx] = g_v[base + m * D + j];
    }
    __syncthreads();

    unsigned long long q2[8];
    {
        const unsigned long long* qp = reinterpret_cast<const unsigned long long*>(g_q + base + tid * D);
        #pragma unroll
        for (int j = 0; j < 8; j++) q2[j] = qp[j];
    }

    unsigned long long acc[8];
    const unsigned long long z2 = pack2(0.f, 0.f);
    #pragma unroll
    for (int j = 0; j < 8; j++) acc[j] = z2;
    float mx = -3.0e38f, sum = 0.f;

    const unsigned long long* Ks2 = reinterpret_cast<const unsigned long long*>(Ks);
    const unsigned long long* Vs2 = reinterpret_cast<const unsigned long long*>(Vs);

    for (int m = 0; m < LSEQ; m++) {
        unsigned long long d2 = z2;
        #pragma unroll
        for (int j = 0; j < 8; j++)
            ffma2(d2, q2[j], Ks2[m * 8 + j]);
        float lo, hi;
        unpack2(d2, lo, hi);
        float s = (lo + hi) * 0.25f;

        if (s <= mx) {
            float pe = __expf(s - mx);
            sum += pe;
            unsigned long long pe2 = pack2(pe, pe);
            #pragma unroll
            for (int j = 0; j < 8; j++)
                ffma2(acc[j], Vs2[m * 8 + j], pe2);
        } else {
            float corr = __expf(mx - s);
            sum = sum * corr + 1.f;
            unsigned long long c2 = pack2(corr, corr);
            #pragma unroll
            for (int j = 0; j < 8; j++) {
                unsigned long long t;
                fmul2(t, acc[j], c2);
                fadd2(acc[j], t, Vs2[m * 8 + j]);
            }
            mx = s;
        }
    }

    float inv = 1.f / sum;
    float* op = g_o + base + tid * D;
    #pragma unroll
    for (int j = 0; j < 8; j++) {
        float lo, hi;
        unpack2(acc[j], lo, hi);
        op[j * 2 + 0] = lo * inv;
        op[j * 2 + 1] = hi * inv;
    }
}

// ------------------------------ launch ------------------------------
extern "C" void kernel_launch(void* const* d_in, const int* in_sizes, int n_in,
                              void* d_out, int out_size)
{
    const float* ego    = (const float*)d_in[0];
    const float* vals   = (const float*)d_in[1];
    const float* W1     = (const float*)d_in[2];
    const float* b1     = (const float*)d_in[3];
    const float* W2     = (const float*)d_in[4];
    const float* b2     = (const float*)d_in[5];
    const float* enc_in = (const float*)d_in[6];
    const float* wq     = (const float*)d_in[7];
    const float* bq     = (const float*)d_in[8];
    const float* wk     = (const float*)d_in[9];
    const float* bk     = (const float*)d_in[10];
    const float* wv     = (const float*)d_in[11];
    const float* bv     = (const float*)d_in[12];
    const float* wo     = (const float*)d_in[13];
    const float* bo     = (const float*)d_in[14];
    const float* ln1_g  = (const float*)d_in[15];
    const float* ln1_b  = (const float*)d_in[16];
    const float* cw1    = (const float*)d_in[17];
    const float* cb1    = (const float*)d_in[18];
    const float* cw2    = (const float*)d_in[19];
    const float* cb2    = (const float*)d_in[20];
    const float* ln2_g  = (const float*)d_in[21];
    const float* ln2_b  = (const float*)d_in[22];
    const int*   rows   = (const int*)d_in[23];
    const int*   cols   = (const int*)d_in[24];
    float* out = (float*)d_out;

    int Nego = in_sizes[0] / 128;       // 100000
    int nnz  = in_sizes[1];             // 2000000
    int Mt   = in_sizes[6] / 128;       // 8192
    int B    = Mt / LSEQ;               // 32
    int NL   = in_sizes[7] / (128 * 128);

    const int AGG_SMEM = 61440;
    cudaFuncSetAttribute(agg_mma_kernel, cudaFuncAttributeMaxDynamicSharedMemorySize, AGG_SMEM);

    // ---- weight images ----
    prep_w_kernel<<<dim3(64, 2 + 6 * NL), 256>>>(W1, W2, wq, wk, wv, wo, cw1, cw2, NL);

    // ---- graph side ----
    zero_side_kernel<<<1024, 256>>>((Nego * 128) / 4);
    int nwarps = (nnz + EPW - 1) / EPW;
    int spmm_blocks = (nwarps * 32 + 255) / 256;
    spmm_kernel<<<spmm_blocks, 256>>>(ego, vals, rows, cols, nnz);

    // fused aggregator (single pass)
    agg_mma_kernel<<<(Nego + 63) / 64, 256, AGG_SMEM>>>(ego, b1, b2, out, Nego);

    // ---- transformer encoder ----
    const float* xin_ext = enc_in;
    int xin_id = -1;
    int gb = Mt / 64;   // 128

    for (int i = 0; i < NL; i++) {
        unsigned lbase = 65536u + (unsigned)i * 393216u;
        const float* bq_ = bq + i * D;
        const float* bk_ = bk + i * D;
        const float* bv_ = bv + i * D;
        const float* bo_ = bo + i * D;
        const float* g1_ = ln1_g + i * D;  const float* be1_ = ln1_b + i * D;
        const float* cb1_ = cb1 + i * DI;
        const float* cb2_ = cb2 + i * D;
        const float* g2_ = ln2_g + i * D;  const float* be2_ = ln2_b + i * D;

        // QKV (grid.y = 3)
        mma_qkv_kernel<<<dim3(gb, 3), 256>>>(xin_ext, xin_id, lbase, bq_, bk_, bv_, Mt);
        attn_kernel<<<B * 8, 256>>>(0);
        // wo + residual + LN1 -> BX1
        mma_gemm_kernel<128, 128><<<gb, 256>>>(nullptr, BO, lbase + 3u * 32768u, 16384, bo_,
                                               xin_id, xin_ext, g1_, be1_, nullptr, BX1, Mt, 5);
        // FFN1 relu -> BH  (grid.y = 4 over N=512)
        mma_gemm_kernel<128, 512><<<dim3(gb, 4), 256>>>(nullptr, BX1, lbase + 131072u, 65536, cb1_,
                                                        -1, nullptr, nullptr, nullptr, nullptr, BH, Mt, 1);
        // FFN2 + residual(BX1) + LN2 -> BX2 (or final out)
        bool last = (i == NL - 1);
        mma_gemm_kernel<512, 128><<<gb, 256>>>(nullptr, BH, lbase + 262144u, 65536, cb2_,
                                               BX1, nullptr, g2_, be2_,
                                               last ? (out + (size_t)in_sizes[0]) : nullptr,
                                               BX2, Mt, 5);
        xin_ext = nullptr;
        xin_id = BX2;
    }
}

// round 12
// speedup vs baseline: 1.7206x; 1.0935x over previous
#include <cuda_runtime.h>
#include <cuda_bf16.h>
#include <math.h>

#define DEV_INLINE __device__ __forceinline__

static const int D    = 128;
static const int LSEQ = 256;
static const int DK   = 16;
static const int DI   = 512;

// ------------------------- scratch (device globals) -------------------------
__device__ float g_side[12800000];   // side = A_in @ ego
__device__ float g_q [1048576];
__device__ float g_k [1048576];
__device__ float g_v [1048576];
__device__ float g_o [1048576];
__device__ float g_x1[1048576];
__device__ float g_x2[1048576];
__device__ float g_h [4194304];      // 8192 x 512
__device__ __align__(16) __nv_bfloat16 g_wbf[1048576];  // weight bf16 hi/lo images, [n][k]

enum { BQ = 0, BK = 1, BV = 2, BO = 3, BX1 = 5, BX2 = 6, BH = 7 };

DEV_INLINE float* bufptr(int id) {
    switch (id) {
        case BQ:  return g_q;
        case BK:  return g_k;
        case BV:  return g_v;
        case BO:  return g_o;
        case BX1: return g_x1;
        case BX2: return g_x2;
        case BH:  return g_h;
    }
    return nullptr;
}

// ------------------------- f32x2 helpers (attention) -------------------------
DEV_INLINE unsigned long long pack2(float lo, float hi) {
    unsigned long long r;
    asm("mov.b64 %0, {%1, %2};" : "=l"(r) : "f"(lo), "f"(hi));
    return r;
}
DEV_INLINE void unpack2(unsigned long long v, float& lo, float& hi) {
    asm("mov.b64 {%0, %1}, %2;" : "=f"(lo), "=f"(hi) : "l"(v));
}
DEV_INLINE void ffma2(unsigned long long& d, unsigned long long a, unsigned long long b) {
    asm("fma.rn.f32x2 %0, %1, %2, %0;" : "+l"(d) : "l"(a), "l"(b));
}
DEV_INLINE void fmul2(unsigned long long& d, unsigned long long a, unsigned long long b) {
    asm("mul.rn.f32x2 %0, %1, %2;" : "=l"(d) : "l"(a), "l"(b));
}
DEV_INLINE void fadd2(unsigned long long& d, unsigned long long a, unsigned long long b) {
    asm("add.rn.f32x2 %0, %1, %2;" : "=l"(d) : "l"(a), "l"(b));
}

// ------------------------- mma helpers -------------------------
DEV_INLINE unsigned smem_u32(const void* p) {
    unsigned a;
    asm("{ .reg .u64 t; cvta.to.shared.u64 t, %1; cvt.u32.u64 %0, t; }" : "=r"(a) : "l"(p));
    return a;
}
DEV_INLINE void ldsm4(unsigned* r, unsigned addr) {
    asm volatile("ldmatrix.sync.aligned.m8n8.x4.shared.b16 {%0,%1,%2,%3}, [%4];"
        : "=r"(r[0]), "=r"(r[1]), "=r"(r[2]), "=r"(r[3]) : "r"(addr));
}
DEV_INLINE void mma_bf16(float* c, const unsigned* a, const unsigned* b) {
    asm volatile(
        "mma.sync.aligned.m16n8k16.row.col.f32.bf16.bf16.f32 "
        "{%0,%1,%2,%3}, {%4,%5,%6,%7}, {%8,%9}, {%0,%1,%2,%3};"
        : "+f"(c[0]), "+f"(c[1]), "+f"(c[2]), "+f"(c[3])
        : "r"(a[0]), "r"(a[1]), "r"(a[2]), "r"(a[3]), "r"(b[0]), "r"(b[1]));
}
DEV_INLINE void split2(float x, float y, unsigned& h, unsigned& l) {
    __nv_bfloat162 hv = __floats2bfloat162_rn(x, y);
    float lx = x - __bfloat162float(hv.x);
    float ly = y - __bfloat162float(hv.y);
    __nv_bfloat162 lv = __floats2bfloat162_rn(lx, ly);
    h = *reinterpret_cast<unsigned*>(&hv);
    l = *reinterpret_cast<unsigned*>(&lv);
}

// ------------------------------ zero side ------------------------------
__global__ void zero_side_kernel(int n4) {
    float4* p = reinterpret_cast<float4*>(g_side);
    int i = blockIdx.x * blockDim.x + threadIdx.x;
    int stride = gridDim.x * blockDim.x;
    float4 z = make_float4(0.f, 0.f, 0.f, 0.f);
    for (; i < n4; i += stride) p[i] = z;
}

// ------------------------------ SpMM (COO, rows sorted) ------------------------------
static const int EPW = 256;

DEV_INLINE void spmm_flush(int row, int lane, float4 acc) {
    float* p = &g_side[(size_t)row * 128 + lane * 4];
    atomicAdd(p + 0, acc.x);
    atomicAdd(p + 1, acc.y);
    atomicAdd(p + 2, acc.z);
    atomicAdd(p + 3, acc.w);
}

__global__ void __launch_bounds__(256) spmm_kernel(
    const float* __restrict__ ego, const float* __restrict__ vals,
    const int* __restrict__ rows, const int* __restrict__ cols, int nnz)
{
    int warp = (blockIdx.x * blockDim.x + threadIdx.x) >> 5;
    int lane = threadIdx.x & 31;
    long e0 = (long)warp * EPW;
    if (e0 >= nnz) return;
    long e1 = e0 + EPW; if (e1 > nnz) e1 = nnz;

    const float4* ego4 = reinterpret_cast<const float4*>(ego);
    float4 acc = make_float4(0.f, 0.f, 0.f, 0.f);
    int cur = rows[e0];
    for (long e = e0; e < e1; e++) {
        int r = rows[e];
        if (r != cur) {
            spmm_flush(cur, lane, acc);
            acc = make_float4(0.f, 0.f, 0.f, 0.f);
            cur = r;
        }
        float v  = vals[e];
        float4 g = ego4[(size_t)cols[e] * 32 + lane];
        acc.x += v * g.x; acc.y += v * g.y; acc.z += v * g.z; acc.w += v * g.w;
    }
    spmm_flush(cur, lane, acc);
}

// ------------------------------ prep: weight bf16 hi/lo images, [n][k] ------------------------------
__global__ void __launch_bounds__(256) prep_w_kernel(
    const float* __restrict__ W1, const float* __restrict__ W2,
    const float* __restrict__ wq, const float* __restrict__ wk,
    const float* __restrict__ wv, const float* __restrict__ wo,
    const float* __restrict__ cw1, const float* __restrict__ cw2, int NL)
{
    int y = blockIdx.y;
    const float* src; unsigned off; int Kd, Nd;
    if (y < 2) { src = y ? W2 : W1; off = (unsigned)y * 32768u; Kd = 128; Nd = 128; }
    else {
        int i = (y - 2) / 6, j = (y - 2) % 6;
        unsigned base = 65536u + (unsigned)i * 393216u;
        if (j < 4) {
            const float* p = (j == 0) ? wq : (j == 1) ? wk : (j == 2) ? wv : wo;
            src = p + (size_t)i * 16384; off = base + (unsigned)j * 32768u; Kd = 128; Nd = 128;
        } else if (j == 4) {
            src = cw1 + (size_t)i * 65536; off = base + 131072u; Kd = 128; Nd = 512;
        } else {
            src = cw2 + (size_t)i * 65536; off = base + 262144u; Kd = 512; Nd = 128;
        }
    }
    int tot = Kd * Nd;
    for (int idx = blockIdx.x * 256 + threadIdx.x; idx < tot; idx += gridDim.x * 256) {
        int n = idx / Kd, k = idx - n * Kd;
        float w = src[(size_t)k * Nd + n];
        __nv_bfloat16 h = __float2bfloat16(w);
        float l = w - __bfloat162float(h);
        g_wbf[off + (size_t)n * Kd + k] = h;
        g_wbf[off + (size_t)tot + (size_t)n * Kd + k] = __float2bfloat16(l);
    }
}

// ------------------------------ fused aggregator (bf16x3 mma, both GEMMs one pass) ------------------------------
__global__ void __launch_bounds__(256, 2) agg_mma_kernel(
    const float* __restrict__ ego,
    const float* __restrict__ b1, const float* __restrict__ b2,
    float* __restrict__ out, int M)
{
    extern __shared__ __align__(16) char dsm[];
    __nv_bfloat16* Ah  = reinterpret_cast<__nv_bfloat16*>(dsm);
    __nv_bfloat16* Al  = reinterpret_cast<__nv_bfloat16*>(dsm + 5120);
    __nv_bfloat16* Ph  = reinterpret_cast<__nv_bfloat16*>(dsm + 10240);
    __nv_bfloat16* Pl  = reinterpret_cast<__nv_bfloat16*>(dsm + 15360);
    __nv_bfloat16* B1h = reinterpret_cast<__nv_bfloat16*>(dsm + 20480);
    __nv_bfloat16* B1l = reinterpret_cast<__nv_bfloat16*>(dsm + 30720);
    __nv_bfloat16* B2h = reinterpret_cast<__nv_bfloat16*>(dsm + 40960);
    __nv_bfloat16* B2l = reinterpret_cast<__nv_bfloat16*>(dsm + 51200);

    int tid = threadIdx.x, lane = tid & 31, wy = tid >> 5;
    int wm = wy >> 1, wn = wy & 1;
    int row0 = blockIdx.x * 64;

    float c1[8][4], c2[8][4];
    #pragma unroll
    for (int t = 0; t < 8; t++)
        #pragma unroll
        for (int j = 0; j < 4; j++) { c1[t][j] = 0.f; c2[t][j] = 0.f; }

    int arow = wm * 16 + (lane & 7) + ((lane >> 3) & 1) * 8;
    int akc  = (lane >> 4) * 8;
    unsigned aAh = smem_u32(&Ah[arow * 40 + akc]);
    unsigned aAl = smem_u32(&Al[arow * 40 + akc]);
    unsigned aPh = smem_u32(&Ph[arow * 40 + akc]);
    unsigned aPl = smem_u32(&Pl[arow * 40 + akc]);
    int bn = wn * 64 + (lane & 7) + ((lane >> 4) << 3);
    int bk = ((lane >> 3) & 1) * 8;
    unsigned aB1h = smem_u32(&B1h[bn * 40 + bk]);
    unsigned aB1l = smem_u32(&B1l[bn * 40 + bk]);
    unsigned aB2h = smem_u32(&B2h[bn * 40 + bk]);
    unsigned aB2l = smem_u32(&B2l[bn * 40 + bk]);

    const __nv_bfloat16* W1h = g_wbf;
    const __nv_bfloat16* W1l = g_wbf + 16384;
    const __nv_bfloat16* W2h = g_wbf + 32768;
    const __nv_bfloat16* W2l = g_wbf + 49152;

    for (int ch = 0; ch < 4; ch++) {
        int k0 = ch * 32;
        #pragma unroll
        for (int i = 0; i < 2; i++) {
            int idx = tid + i * 256;
            int n = idx >> 2, part = idx & 3;
            size_t go = (size_t)n * 128 + k0;
            *reinterpret_cast<uint4*>(&B1h[n * 40 + part * 8]) = reinterpret_cast<const uint4*>(W1h + go)[part];
            *reinterpret_cast<uint4*>(&B1l[n * 40 + part * 8]) = reinterpret_cast<const uint4*>(W1l + go)[part];
            *reinterpret_cast<uint4*>(&B2h[n * 40 + part * 8]) = reinterpret_cast<const uint4*>(W2h + go)[part];
            *reinterpret_cast<uint4*>(&B2l[n * 40 + part * 8]) = reinterpret_cast<const uint4*>(W2l + go)[part];
        }
        #pragma unroll
        for (int i = 0; i < 2; i++) {
            int idx = tid + i * 256;
            int r = idx >> 3, kg = idx & 7;
            int rr = row0 + r;
            float4 e = make_float4(0.f, 0.f, 0.f, 0.f);
            float4 s = make_float4(0.f, 0.f, 0.f, 0.f);
            if (rr < M) {
                e = *reinterpret_cast<const float4*>(&ego   [(size_t)rr * 128 + k0 + kg * 4]);
                s = *reinterpret_cast<const float4*>(&g_side[(size_t)rr * 128 + k0 + kg * 4]);
            }
            float sx = e.x + s.x, sy = e.y + s.y, sz = e.z + s.z, sw = e.w + s.w;
            float px = e.x * s.x, py = e.y * s.y, pz = e.z * s.z, pw = e.w * s.w;
            unsigned h01, l01, h23, l23;
            split2(sx, sy, h01, l01); split2(sz, sw, h23, l23);
            *reinterpret_cast<uint2*>(&Ah[r * 40 + kg * 4]) = make_uint2(h01, h23);
            *reinterpret_cast<uint2*>(&Al[r * 40 + kg * 4]) = make_uint2(l01, l23);
            split2(px, py, h01, l01); split2(pz, pw, h23, l23);
            *reinterpret_cast<uint2*>(&Ph[r * 40 + kg * 4]) = make_uint2(h01, h23);
            *reinterpret_cast<uint2*>(&Pl[r * 40 + kg * 4]) = make_uint2(l01, l23);
        }
        __syncthreads();

        #pragma unroll
        for (int ks = 0; ks < 2; ks++) {
            unsigned sh[4], sl[4], ph[4], pl[4];
            ldsm4(sh, aAh + ks * 32);
            ldsm4(sl, aAl + ks * 32);
            ldsm4(ph, aPh + ks * 32);
            ldsm4(pl, aPl + ks * 32);
            #pragma unroll
            for (int np = 0; np < 4; np++) {
                unsigned b1h[4], b1l[4], b2h[4], b2l[4];
                ldsm4(b1h, aB1h + np * 1280 + ks * 32);
                ldsm4(b1l, aB1l + np * 1280 + ks * 32);
                ldsm4(b2h, aB2h + np * 1280 + ks * 32);
                ldsm4(b2l, aB2l + np * 1280 + ks * 32);
                mma_bf16(c1[2 * np],     sh, b1h);
                mma_bf16(c1[2 * np],     sh, b1l);
                mma_bf16(c1[2 * np],     sl, b1h);
                mma_bf16(c1[2 * np + 1], sh, b1h + 2);
                mma_bf16(c1[2 * np + 1], sh, b1l + 2);
                mma_bf16(c1[2 * np + 1], sl, b1h + 2);
                mma_bf16(c2[2 * np],     ph, b2h);
                mma_bf16(c2[2 * np],     ph, b2l);
                mma_bf16(c2[2 * np],     pl, b2h);
                mma_bf16(c2[2 * np + 1], ph, b2h + 2);
                mma_bf16(c2[2 * np + 1], ph, b2l + 2);
                mma_bf16(c2[2 * np + 1], pl, b2h + 2);
            }
        }
        __syncthreads();
    }

    int colb = wn * 64 + (lane & 3) * 2;
    int r0g = row0 + wm * 16 + (lane >> 2);
    int r1g = r0g + 8;
    bool v0 = r0g < M, v1 = r1g < M;
    #pragma unroll
    for (int nt = 0; nt < 8; nt++) {
        int col = colb + nt * 8;
        float2 bv1 = *reinterpret_cast<const float2*>(&b1[col]);
        float2 bv2 = *reinterpret_cast<const float2*>(&b2[col]);
        float x0 = c1[nt][0] + bv1.x, x1 = c1[nt][1] + bv1.y;
        float x2 = c1[nt][2] + bv1.x, x3 = c1[nt][3] + bv1.y;
        float y0 = c2[nt][0] + bv2.x, y1 = c2[nt][1] + bv2.y;
        float y2 = c2[nt][2] + bv2.x, y3 = c2[nt][3] + bv2.y;
        x0 = (x0 > 0.f) ? x0 : 0.01f * x0;  y0 = (y0 > 0.f) ? y0 : 0.01f * y0;
        x1 = (x1 > 0.f) ? x1 : 0.01f * x1;  y1 = (y1 > 0.f) ? y1 : 0.01f * y1;
        x2 = (x2 > 0.f) ? x2 : 0.01f * x2;  y2 = (y2 > 0.f) ? y2 : 0.01f * y2;
        x3 = (x3 > 0.f) ? x3 : 0.01f * x3;  y3 = (y3 > 0.f) ? y3 : 0.01f * y3;
        if (v0) *reinterpret_cast<float2*>(&out[(size_t)r0g * 128 + col]) = make_float2(x0 + y0, x1 + y1);
        if (v1) *reinterpret_cast<float2*>(&out[(size_t)r1g * 128 + col]) = make_float2(x2 + y2, x3 + y3);
    }
}

// ------------------------------ bf16x3 mma GEMM core (256 thr, 8 warps 4m x 2n) ------------------------------
template<int K, int NOUT>
DEV_INLINE void mma_core(const float* __restrict__ A,
                         const __nv_bfloat16* __restrict__ Whi, int loN,
                         const float* __restrict__ bias, const float* __restrict__ R,
                         const float* __restrict__ lnG, const float* __restrict__ lnB,
                         float* __restrict__ C, int M, int mode, int cb)
{
    __shared__ __align__(16) __nv_bfloat16 Ah[64][40];
    __shared__ __align__(16) __nv_bfloat16 Al[64][40];
    __shared__ __align__(16) __nv_bfloat16 Bh[128][40];
    __shared__ __align__(16) __nv_bfloat16 Bl[128][40];
    __shared__ float Sred[2][64], Qred[2][64];

    int tid = threadIdx.x, lane = tid & 31, wy = tid >> 5;
    int wm = wy >> 1, wn = wy & 1;
    int row0 = blockIdx.x * 64;

    float c[8][4];
    #pragma unroll
    for (int t = 0; t < 8; t++)
        #pragma unroll
        for (int j = 0; j < 4; j++) c[t][j] = 0.f;

    int arow = wm * 16 + (lane & 7) + ((lane >> 3) & 1) * 8;
    int akc  = (lane >> 4) * 8;
    unsigned aAh = smem_u32(&Ah[arow][akc]);
    unsigned aAl = smem_u32(&Al[arow][akc]);
    int bn = wn * 64 + (lane & 7) + ((lane >> 4) << 3);
    int bk = ((lane >> 3) & 1) * 8;
    unsigned aBh = smem_u32(&Bh[bn][bk]);
    unsigned aBl = smem_u32(&Bl[bn][bk]);

    for (int ch = 0; ch < K / 32; ch++) {
        int k0 = ch * 32;
        #pragma unroll
        for (int i = 0; i < 2; i++) {
            int idx = tid + i * 256;
            int n = idx >> 2, part = idx & 3;
            const uint4* sh = reinterpret_cast<const uint4*>(Whi + (size_t)(cb + n) * K + k0);
            const uint4* sl = reinterpret_cast<const uint4*>(Whi + loN + (size_t)(cb + n) * K + k0);
            *reinterpret_cast<uint4*>(&Bh[n][part * 8]) = sh[part];
            *reinterpret_cast<uint4*>(&Bl[n][part * 8]) = sl[part];
        }
        #pragma unroll
        for (int i = 0; i < 2; i++) {
            int idx = tid + i * 256;
            int r = idx >> 3, kg = idx & 7;
            int rr = row0 + r;
            float4 av = make_float4(0.f, 0.f, 0.f, 0.f);
            if (rr < M)
                av = *reinterpret_cast<const float4*>(&A[(size_t)rr * K + k0 + kg * 4]);
            unsigned h01, l01, h23, l23;
            split2(av.x, av.y, h01, l01);
            split2(av.z, av.w, h23, l23);
            *reinterpret_cast<uint2*>(&Ah[r][kg * 4]) = make_uint2(h01, h23);
            *reinterpret_cast<uint2*>(&Al[r][kg * 4]) = make_uint2(l01, l23);
        }
        __syncthreads();

        #pragma unroll
        for (int ks = 0; ks < 2; ks++) {
            unsigned ah[4], al[4];
            ldsm4(ah, aAh + ks * 32);
            ldsm4(al, aAl + ks * 32);
            #pragma unroll
            for (int np = 0; np < 4; np++) {
                unsigned bh[4], bl[4];
                ldsm4(bh, aBh + np * 1280 + ks * 32);
                ldsm4(bl, aBl + np * 1280 + ks * 32);
                mma_bf16(c[2 * np],     ah, bh);
                mma_bf16(c[2 * np],     ah, bl);
                mma_bf16(c[2 * np],     al, bh);
                mma_bf16(c[2 * np + 1], ah, bh + 2);
                mma_bf16(c[2 * np + 1], ah, bl + 2);
                mma_bf16(c[2 * np + 1], al, bh + 2);
            }
        }
        __syncthreads();
    }

    int colb = cb + wn * 64 + (lane & 3) * 2;
    int lr0 = wm * 16 + (lane >> 2);
    int r0g = row0 + lr0;
    int r1g = r0g + 8;
    bool v0 = r0g < M, v1 = r1g < M;

    if (mode == 5) {
        float s0 = 0.f, q0 = 0.f, s1 = 0.f, q1 = 0.f;
        #pragma unroll
        for (int nt = 0; nt < 8; nt++) {
            int col = colb + nt * 8;
            float2 bv = *reinterpret_cast<const float2*>(&bias[col]);
            float2 rA = v0 ? *reinterpret_cast<const float2*>(&R[(size_t)r0g * 128 + col]) : make_float2(0.f, 0.f);
            float2 rB = v1 ? *reinterpret_cast<const float2*>(&R[(size_t)r1g * 128 + col]) : make_float2(0.f, 0.f);
            c[nt][0] += bv.x + rA.x; c[nt][1] += bv.y + rA.y;
            c[nt][2] += bv.x + rB.x; c[nt][3] += bv.y + rB.y;
            s0 += c[nt][0] + c[nt][1]; q0 += c[nt][0] * c[nt][0] + c[nt][1] * c[nt][1];
            s1 += c[nt][2] + c[nt][3]; q1 += c[nt][2] * c[nt][2] + c[nt][3] * c[nt][3];
        }
        #pragma unroll
        for (int o = 1; o <= 2; o <<= 1) {
            s0 += __shfl_xor_sync(0xffffffff, s0, o);
            q0 += __shfl_xor_sync(0xffffffff, q0, o);
            s1 += __shfl_xor_sync(0xffffffff, s1, o);
            q1 += __shfl_xor_sync(0xffffffff, q1, o);
        }
        if ((lane & 3) == 0) {
            Sred[wn][lr0] = s0; Qred[wn][lr0] = q0;
            Sred[wn][lr0 + 8] = s1; Qred[wn][lr0 + 8] = q1;
        }
        __syncthreads();
        float S0 = Sred[0][lr0] + Sred[1][lr0];
        float Q0 = Qred[0][lr0] + Qred[1][lr0];
        float S1 = Sred[0][lr0 + 8] + Sred[1][lr0 + 8];
        float Q1 = Qred[0][lr0 + 8] + Qred[1][lr0 + 8];
        float m0 = S0 * (1.f / 128.f), var0 = Q0 * (1.f / 128.f) - m0 * m0;
        float m1 = S1 * (1.f / 128.f), var1 = Q1 * (1.f / 128.f) - m1 * m1;
        float rs0 = rsqrtf(var0 + 1e-5f), rs1 = rsqrtf(var1 + 1e-5f);
        #pragma unroll
        for (int nt = 0; nt < 8; nt++) {
            int col = colb + nt * 8;
            float2 g = *reinterpret_cast<const float2*>(&lnG[col]);
            float2 be = *reinterpret_cast<const float2*>(&lnB[col]);
            if (v0) {
                float2 o = make_float2((c[nt][0] - m0) * rs0 * g.x + be.x,
                                       (c[nt][1] - m0) * rs0 * g.y + be.y);
                *reinterpret_cast<float2*>(&C[(size_t)r0g * 128 + col]) = o;
            }
            if (v1) {
                float2 o = make_float2((c[nt][2] - m1) * rs1 * g.x + be.x,
                                       (c[nt][3] - m1) * rs1 * g.y + be.y);
                *reinterpret_cast<float2*>(&C[(size_t)r1g * 128 + col]) = o;
            }
        }
    } else {
        #pragma unroll
        for (int nt = 0; nt < 8; nt++) {
            int col = colb + nt * 8;
            float2 bv = *reinterpret_cast<const float2*>(&bias[col]);
            float x0 = c[nt][0] + bv.x, x1 = c[nt][1] + bv.y;
            float x2 = c[nt][2] + bv.x, x3 = c[nt][3] + bv.y;
            if (mode == 1) {
                x0 = fmaxf(x0, 0.f); x1 = fmaxf(x1, 0.f);
                x2 = fmaxf(x2, 0.f); x3 = fmaxf(x3, 0.f);
            }
            if (v0) *reinterpret_cast<float2*>(&C[(size_t)r0g * NOUT + col]) = make_float2(x0, x1);
            if (v1) *reinterpret_cast<float2*>(&C[(size_t)r1g * NOUT + col]) = make_float2(x2, x3);
        }
    }
}

template<int K, int NOUT>
__global__ void __launch_bounds__(256) mma_gemm_kernel(
    const float* __restrict__ Aext, int Aid,
    unsigned woff, int loN,
    const float* __restrict__ bias,
    int Rid, const float* __restrict__ Rext,
    const float* __restrict__ lnG, const float* __restrict__ lnB,
    float* __restrict__ Cext, int Cid, int M, int mode)
{
    const float* A = Aext ? Aext : bufptr(Aid);
    float*       C = Cext ? Cext : bufptr(Cid);
    const float* R = nullptr;
    if (mode == 5) R = Rext ? Rext : bufptr(Rid);
    int cb = (NOUT > 128) ? blockIdx.y * 128 : 0;
    mma_core<K, NOUT>(A, g_wbf + woff, loN, bias, R, lnG, lnB, C, M, mode, cb);
}

// qkv fused: grid.y selects q/k/v
__global__ void __launch_bounds__(256) mma_qkv_kernel(
    const float* __restrict__ Aext, int Aid, unsigned wbase,
    const float* __restrict__ bq, const float* __restrict__ bk,
    const float* __restrict__ bv, int M)
{
    int sel = blockIdx.y;
    const float* bias = (sel == 0) ? bq : (sel == 1) ? bk : bv;
    const float* A = Aext ? Aext : bufptr(Aid);
    mma_core<128, 128>(A, g_wbf + wbase + sel * 32768u, 16384,
                       bias, nullptr, nullptr, nullptr, bufptr(BQ + sel), M, 0, 0);
}

// ------------------------------ attention (f32x2) ------------------------------
__global__ void __launch_bounds__(256) attn_kernel(int unused)
{
    __shared__ __align__(16) float Ks[LSEQ * DK];
    __shared__ __align__(16) float Vs[LSEQ * DK];
    int b = blockIdx.x >> 3;
    int h = blockIdx.x & 7;
    int tid = threadIdx.x;
    int base = (b * LSEQ) * D + h * DK;

    for (int idx = tid; idx < LSEQ * DK; idx += 256) {
        int m = idx >> 4, j = idx & 15;
        Ks[idx] = g_k[base + m * D + j];
        Vs[idx] = g_v[base + m * D + j];
    }
    __syncthreads();

    unsigned long long q2[8];
    {
        const unsigned long long* qp = reinterpret_cast<const unsigned long long*>(g_q + base + tid * D);
        #pragma unroll
        for (int j = 0; j < 8; j++) q2[j] = qp[j];
    }

    unsigned long long acc[8];
    const unsigned long long z2 = pack2(0.f, 0.f);
    #pragma unroll
    for (int j = 0; j < 8; j++) acc[j] = z2;
    float mx = -3.0e38f, sum = 0.f;

    const unsigned long long* Ks2 = reinterpret_cast<const unsigned long long*>(Ks);
    const unsigned long long* Vs2 = reinterpret_cast<const unsigned long long*>(Vs);

    for (int m = 0; m < LSEQ; m++) {
        unsigned long long d2 = z2;
        #pragma unroll
        for (int j = 0; j < 8; j++)
            ffma2(d2, q2[j], Ks2[m * 8 + j]);
        float lo, hi;
        unpack2(d2, lo, hi);
        float s = (lo + hi) * 0.25f;

        if (s <= mx) {
            float pe = __expf(s - mx);
            sum += pe;
            unsigned long long pe2 = pack2(pe, pe);
            #pragma unroll
            for (int j = 0; j < 8; j++)
                ffma2(acc[j], Vs2[m * 8 + j], pe2);
        } else {
            float corr = __expf(mx - s);
            sum = sum * corr + 1.f;
            unsigned long long c2 = pack2(corr, corr);
            #pragma unroll
            for (int j = 0; j < 8; j++) {
                unsigned long long t;
                fmul2(t, acc[j], c2);
                fadd2(acc[j], t, Vs2[m * 8 + j]);
            }
            mx = s;
        }
    }

    float inv = 1.f / sum;
    float* op = g_o + base + tid * D;
    #pragma unroll
    for (int j = 0; j < 8; j++) {
        float lo, hi;
        unpack2(acc[j], lo, hi);
        op[j * 2 + 0] = lo * inv;
        op[j * 2 + 1] = hi * inv;
    }
}

// ------------------------------ launch ------------------------------
extern "C" void kernel_launch(void* const* d_in, const int* in_sizes, int n_in,
                              void* d_out, int out_size)
{
    const float* ego    = (const float*)d_in[0];
    const float* vals   = (const float*)d_in[1];
    const float* W1     = (const float*)d_in[2];
    const float* b1     = (const float*)d_in[3];
    const float* W2     = (const float*)d_in[4];
    const float* b2     = (const float*)d_in[5];
    const float* enc_in = (const float*)d_in[6];
    const float* wq     = (const float*)d_in[7];
    const float* bq     = (const float*)d_in[8];
    const float* wk     = (const float*)d_in[9];
    const float* bk     = (const float*)d_in[10];
    const float* wv     = (const float*)d_in[11];
    const float* bv     = (const float*)d_in[12];
    const float* wo     = (const float*)d_in[13];
    const float* bo     = (const float*)d_in[14];
    const float* ln1_g  = (const float*)d_in[15];
    const float* ln1_b  = (const float*)d_in[16];
    const float* cw1    = (const float*)d_in[17];
    const float* cb1    = (const float*)d_in[18];
    const float* cw2    = (const float*)d_in[19];
    const float* cb2    = (const float*)d_in[20];
    const float* ln2_g  = (const float*)d_in[21];
    const float* ln2_b  = (const float*)d_in[22];
    const int*   rows   = (const int*)d_in[23];
    const int*   cols   = (const int*)d_in[24];
    float* out = (float*)d_out;

    int Nego = in_sizes[0] / 128;       // 100000
    int nnz  = in_sizes[1];             // 2000000
    int Mt   = in_sizes[6] / 128;       // 8192
    int B    = Mt / LSEQ;               // 32
    int NL   = in_sizes[7] / (128 * 128);

    const int AGG_SMEM = 61440;
    cudaFuncSetAttribute(agg_mma_kernel, cudaFuncAttributeMaxDynamicSharedMemorySize, AGG_SMEM);

    // Side stream + fork/join events (host-side objects; created per call, no device memory)
    cudaStream_t s2;
    cudaEvent_t ev_fork, ev_join;
    cudaStreamCreateWithFlags(&s2, cudaStreamNonBlocking);
    cudaEventCreateWithFlags(&ev_fork, cudaEventDisableTiming);
    cudaEventCreateWithFlags(&ev_join, cudaEventDisableTiming);

    // ---- shared ancestor: weight images ----
    prep_w_kernel<<<dim3(64, 2 + 6 * NL), 256>>>(W1, W2, wq, wk, wv, wo, cw1, cw2, NL);

    // fork: graph side runs on s2 concurrently with the transformer on the main stream
    cudaEventRecord(ev_fork, 0);
    cudaStreamWaitEvent(s2, ev_fork, 0);

    // ---- graph side (stream s2) ----
    zero_side_kernel<<<1024, 256, 0, s2>>>((Nego * 128) / 4);
    int nwarps = (nnz + EPW - 1) / EPW;
    int spmm_blocks = (nwarps * 32 + 255) / 256;
    spmm_kernel<<<spmm_blocks, 256, 0, s2>>>(ego, vals, rows, cols, nnz);
    agg_mma_kernel<<<(Nego + 63) / 64, 256, AGG_SMEM, s2>>>(ego, b1, b2, out, Nego);

    // ---- transformer encoder (main stream) ----
    const float* xin_ext = enc_in;
    int xin_id = -1;
    int gb = Mt / 64;   // 128

    for (int i = 0; i < NL; i++) {
        unsigned lbase = 65536u + (unsigned)i * 393216u;
        const float* bq_ = bq + i * D;
        const float* bk_ = bk + i * D;
        const float* bv_ = bv + i * D;
        const float* bo_ = bo + i * D;
        const float* g1_ = ln1_g + i * D;  const float* be1_ = ln1_b + i * D;
        const float* cb1_ = cb1 + i * DI;
        const float* cb2_ = cb2 + i * D;
        const float* g2_ = ln2_g + i * D;  const float* be2_ = ln2_b + i * D;

        mma_qkv_kernel<<<dim3(gb, 3), 256>>>(xin_ext, xin_id, lbase, bq_, bk_, bv_, Mt);
        attn_kernel<<<B * 8, 256>>>(0);
        mma_gemm_kernel<128, 128><<<gb, 256>>>(nullptr, BO, lbase + 3u * 32768u, 16384, bo_,
                                               xin_id, xin_ext, g1_, be1_, nullptr, BX1, Mt, 5);
        mma_gemm_kernel<128, 512><<<dim3(gb, 4), 256>>>(nullptr, BX1, lbase + 131072u, 65536, cb1_,
                                                        -1, nullptr, nullptr, nullptr, nullptr, BH, Mt, 1);
        bool last = (i == NL - 1);
        mma_gemm_kernel<512, 128><<<gb, 256>>>(nullptr, BH, lbase + 262144u, 65536, cb2_,
                                               BX1, nullptr, g2_, be2_,
                                               last ? (out + (size_t)in_sizes[0]) : nullptr,
                                               BX2, Mt, 5);
        xin_ext = nullptr;
        xin_id = BX2;
    }

    // join: main stream completion depends on the graph-side branch
    cudaEventRecord(ev_join, s2);
    cudaStreamWaitEvent((cudaStream_t)0, ev_join, 0);
}

// round 13
// speedup vs baseline: 2.0531x; 1.1932x over previous
#include <cuda_runtime.h>
#include <cuda_bf16.h>
#include <math.h>

#define DEV_INLINE __device__ __forceinline__

static const int D    = 128;
static const int LSEQ = 256;
static const int DK   = 16;
static const int DI   = 512;

// ------------------------- scratch (device globals) -------------------------
__device__ float g_side[12800000];   // side = A_in @ ego
__device__ float g_q [1048576];
__device__ float g_k [1048576];
__device__ float g_v [1048576];
__device__ float g_o [1048576];
__device__ float g_x1[1048576];
__device__ float g_x2[1048576];
__device__ float g_h [4194304];      // 8192 x 512
__device__ __align__(16) __nv_bfloat16 g_wbf[1048576];  // weight bf16 hi/lo images, [n][k]

enum { BQ = 0, BK = 1, BV = 2, BO = 3, BX1 = 5, BX2 = 6, BH = 7 };

DEV_INLINE float* bufptr(int id) {
    switch (id) {
        case BQ:  return g_q;
        case BK:  return g_k;
        case BV:  return g_v;
        case BO:  return g_o;
        case BX1: return g_x1;
        case BX2: return g_x2;
        case BH:  return g_h;
    }
    return nullptr;
}

// ------------------------- f32x2 helpers (attention) -------------------------
DEV_INLINE unsigned long long pack2(float lo, float hi) {
    unsigned long long r;
    asm("mov.b64 %0, {%1, %2};" : "=l"(r) : "f"(lo), "f"(hi));
    return r;
}
DEV_INLINE void unpack2(unsigned long long v, float& lo, float& hi) {
    asm("mov.b64 {%0, %1}, %2;" : "=f"(lo), "=f"(hi) : "l"(v));
}
DEV_INLINE void ffma2(unsigned long long& d, unsigned long long a, unsigned long long b) {
    asm("fma.rn.f32x2 %0, %1, %2, %0;" : "+l"(d) : "l"(a), "l"(b));
}
DEV_INLINE void fmul2(unsigned long long& d, unsigned long long a, unsigned long long b) {
    asm("mul.rn.f32x2 %0, %1, %2;" : "=l"(d) : "l"(a), "l"(b));
}
DEV_INLINE void fadd2(unsigned long long& d, unsigned long long a, unsigned long long b) {
    asm("add.rn.f32x2 %0, %1, %2;" : "=l"(d) : "l"(a), "l"(b));
}

// ------------------------- mma helpers -------------------------
DEV_INLINE unsigned smem_u32(const void* p) {
    unsigned a;
    asm("{ .reg .u64 t; cvta.to.shared.u64 t, %1; cvt.u32.u64 %0, t; }" : "=r"(a) : "l"(p));
    return a;
}
DEV_INLINE void ldsm4(unsigned* r, unsigned addr) {
    asm volatile("ldmatrix.sync.aligned.m8n8.x4.shared.b16 {%0,%1,%2,%3}, [%4];"
        : "=r"(r[0]), "=r"(r[1]), "=r"(r[2]), "=r"(r[3]) : "r"(addr));
}
DEV_INLINE void mma_bf16(float* c, const unsigned* a, const unsigned* b) {
    asm volatile(
        "mma.sync.aligned.m16n8k16.row.col.f32.bf16.bf16.f32 "
        "{%0,%1,%2,%3}, {%4,%5,%6,%7}, {%8,%9}, {%0,%1,%2,%3};"
        : "+f"(c[0]), "+f"(c[1]), "+f"(c[2]), "+f"(c[3])
        : "r"(a[0]), "r"(a[1]), "r"(a[2]), "r"(a[3]), "r"(b[0]), "r"(b[1]));
}
DEV_INLINE void split2(float x, float y, unsigned& h, unsigned& l) {
    __nv_bfloat162 hv = __floats2bfloat162_rn(x, y);
    float lx = x - __bfloat162float(hv.x);
    float ly = y - __bfloat162float(hv.y);
    __nv_bfloat162 lv = __floats2bfloat162_rn(lx, ly);
    h = *reinterpret_cast<unsigned*>(&hv);
    l = *reinterpret_cast<unsigned*>(&lv);
}

// ------------------------------ zero side ------------------------------
__global__ void zero_side_kernel(int n4) {
    float4* p = reinterpret_cast<float4*>(g_side);
    int i = blockIdx.x * blockDim.x + threadIdx.x;
    int stride = gridDim.x * blockDim.x;
    float4 z = make_float4(0.f, 0.f, 0.f, 0.f);
    for (; i < n4; i += stride) p[i] = z;
}

// ------------------------------ SpMM (COO, rows sorted, 8-edge batched MLP) ------------------------------
static const int EPW = 256;   // multiple of 8

DEV_INLINE void spmm_flush(int row, int lane, float4 acc) {
    float* p = &g_side[(size_t)row * 128 + lane * 4];
    atomicAdd(p + 0, acc.x);
    atomicAdd(p + 1, acc.y);
    atomicAdd(p + 2, acc.z);
    atomicAdd(p + 3, acc.w);
}

__global__ void __launch_bounds__(256) spmm_kernel(
    const float* __restrict__ ego, const float* __restrict__ vals,
    const int* __restrict__ rows, const int* __restrict__ cols, int nnz)
{
    int warp = (blockIdx.x * blockDim.x + threadIdx.x) >> 5;
    int lane = threadIdx.x & 31;
    long e0 = (long)warp * EPW;
    if (e0 >= nnz) return;
    long e1 = e0 + EPW; if (e1 > nnz) e1 = nnz;

    const float4* ego4 = reinterpret_cast<const float4*>(ego);
    float4 acc = make_float4(0.f, 0.f, 0.f, 0.f);
    int cur = rows[e0];

    for (long e = e0; e < e1; e += 8) {
        int nb = (int)((e1 - e < 8) ? (e1 - e) : 8);
        // vector index/value loads (e is 8-aligned within the 256-aligned chunk)
        int4  r4a = *reinterpret_cast<const int4*>(&rows[e]);
        int4  r4b = *reinterpret_cast<const int4*>(&rows[e + 4]);
        int4  c4a = *reinterpret_cast<const int4*>(&cols[e]);
        int4  c4b = *reinterpret_cast<const int4*>(&cols[e + 4]);
        float4 v4a = *reinterpret_cast<const float4*>(&vals[e]);
        float4 v4b = *reinterpret_cast<const float4*>(&vals[e + 4]);
        int   r[8] = {r4a.x, r4a.y, r4a.z, r4a.w, r4b.x, r4b.y, r4b.z, r4b.w};
        int   c[8] = {c4a.x, c4a.y, c4a.z, c4a.w, c4b.x, c4b.y, c4b.z, c4b.w};
        float v[8] = {v4a.x, v4a.y, v4a.z, v4a.w, v4b.x, v4b.y, v4b.z, v4b.w};
        // 8 independent gathers in flight (MLP = 8)
        float4 g[8];
        #pragma unroll
        for (int j = 0; j < 8; j++)
            g[j] = ego4[(size_t)c[j] * 32 + lane];
        #pragma unroll
        for (int j = 0; j < 8; j++) {
            if (j >= nb) break;
            if (r[j] != cur) {
                spmm_flush(cur, lane, acc);
                acc = make_float4(0.f, 0.f, 0.f, 0.f);
                cur = r[j];
            }
            acc.x += v[j] * g[j].x;
            acc.y += v[j] * g[j].y;
            acc.z += v[j] * g[j].z;
            acc.w += v[j] * g[j].w;
        }
    }
    spmm_flush(cur, lane, acc);
}

// ------------------------------ prep: weight bf16 hi/lo images, [n][k] ------------------------------
__global__ void __launch_bounds__(256) prep_w_kernel(
    const float* __restrict__ W1, const float* __restrict__ W2,
    const float* __restrict__ wq, const float* __restrict__ wk,
    const float* __restrict__ wv, const float* __restrict__ wo,
    const float* __restrict__ cw1, const float* __restrict__ cw2, int NL)
{
    int y = blockIdx.y;
    const float* src; unsigned off; int Kd, Nd;
    if (y < 2) { src = y ? W2 : W1; off = (unsigned)y * 32768u; Kd = 128; Nd = 128; }
    else {
        int i = (y - 2) / 6, j = (y - 2) % 6;
        unsigned base = 65536u + (unsigned)i * 393216u;
        if (j < 4) {
            const float* p = (j == 0) ? wq : (j == 1) ? wk : (j == 2) ? wv : wo;
            src = p + (size_t)i * 16384; off = base + (unsigned)j * 32768u; Kd = 128; Nd = 128;
        } else if (j == 4) {
            src = cw1 + (size_t)i * 65536; off = base + 131072u; Kd = 128; Nd = 512;
        } else {
            src = cw2 + (size_t)i * 65536; off = base + 262144u; Kd = 512; Nd = 128;
        }
    }
    int tot = Kd * Nd;
    for (int idx = blockIdx.x * 256 + threadIdx.x; idx < tot; idx += gridDim.x * 256) {
        int n = idx / Kd, k = idx - n * Kd;
        float w = src[(size_t)k * Nd + n];
        __nv_bfloat16 h = __float2bfloat16(w);
        float l = w - __bfloat162float(h);
        g_wbf[off + (size_t)n * Kd + k] = h;
        g_wbf[off + (size_t)tot + (size_t)n * Kd + k] = __float2bfloat16(l);
    }
}

// ------------------------------ fused aggregator (bf16x3 mma, both GEMMs one pass) ------------------------------
__global__ void __launch_bounds__(256, 2) agg_mma_kernel(
    const float* __restrict__ ego,
    const float* __restrict__ b1, const float* __restrict__ b2,
    float* __restrict__ out, int M)
{
    extern __shared__ __align__(16) char dsm[];
    __nv_bfloat16* Ah  = reinterpret_cast<__nv_bfloat16*>(dsm);
    __nv_bfloat16* Al  = reinterpret_cast<__nv_bfloat16*>(dsm + 5120);
    __nv_bfloat16* Ph  = reinterpret_cast<__nv_bfloat16*>(dsm + 10240);
    __nv_bfloat16* Pl  = reinterpret_cast<__nv_bfloat16*>(dsm + 15360);
    __nv_bfloat16* B1h = reinterpret_cast<__nv_bfloat16*>(dsm + 20480);
    __nv_bfloat16* B1l = reinterpret_cast<__nv_bfloat16*>(dsm + 30720);
    __nv_bfloat16* B2h = reinterpret_cast<__nv_bfloat16*>(dsm + 40960);
    __nv_bfloat16* B2l = reinterpret_cast<__nv_bfloat16*>(dsm + 51200);

    int tid = threadIdx.x, lane = tid & 31, wy = tid >> 5;
    int wm = wy >> 1, wn = wy & 1;
    int row0 = blockIdx.x * 64;

    float c1[8][4], c2[8][4];
    #pragma unroll
    for (int t = 0; t < 8; t++)
        #pragma unroll
        for (int j = 0; j < 4; j++) { c1[t][j] = 0.f; c2[t][j] = 0.f; }

    int arow = wm * 16 + (lane & 7) + ((lane >> 3) & 1) * 8;
    int akc  = (lane >> 4) * 8;
    unsigned aAh = smem_u32(&Ah[arow * 40 + akc]);
    unsigned aAl = smem_u32(&Al[arow * 40 + akc]);
    unsigned aPh = smem_u32(&Ph[arow * 40 + akc]);
    unsigned aPl = smem_u32(&Pl[arow * 40 + akc]);
    int bn = wn * 64 + (lane & 7) + ((lane >> 4) << 3);
    int bk = ((lane >> 3) & 1) * 8;
    unsigned aB1h = smem_u32(&B1h[bn * 40 + bk]);
    unsigned aB1l = smem_u32(&B1l[bn * 40 + bk]);
    unsigned aB2h = smem_u32(&B2h[bn * 40 + bk]);
    unsigned aB2l = smem_u32(&B2l[bn * 40 + bk]);

    const __nv_bfloat16* W1h = g_wbf;
    const __nv_bfloat16* W1l = g_wbf + 16384;
    const __nv_bfloat16* W2h = g_wbf + 32768;
    const __nv_bfloat16* W2l = g_wbf + 49152;

    for (int ch = 0; ch < 4; ch++) {
        int k0 = ch * 32;
        #pragma unroll
        for (int i = 0; i < 2; i++) {
            int idx = tid + i * 256;
            int n = idx >> 2, part = idx & 3;
            size_t go = (size_t)n * 128 + k0;
            *reinterpret_cast<uint4*>(&B1h[n * 40 + part * 8]) = reinterpret_cast<const uint4*>(W1h + go)[part];
            *reinterpret_cast<uint4*>(&B1l[n * 40 + part * 8]) = reinterpret_cast<const uint4*>(W1l + go)[part];
            *reinterpret_cast<uint4*>(&B2h[n * 40 + part * 8]) = reinterpret_cast<const uint4*>(W2h + go)[part];
            *reinterpret_cast<uint4*>(&B2l[n * 40 + part * 8]) = reinterpret_cast<const uint4*>(W2l + go)[part];
        }
        #pragma unroll
        for (int i = 0; i < 2; i++) {
            int idx = tid + i * 256;
            int r = idx >> 3, kg = idx & 7;
            int rr = row0 + r;
            float4 e = make_float4(0.f, 0.f, 0.f, 0.f);
            float4 s = make_float4(0.f, 0.f, 0.f, 0.f);
            if (rr < M) {
                e = *reinterpret_cast<const float4*>(&ego   [(size_t)rr * 128 + k0 + kg * 4]);
                s = *reinterpret_cast<const float4*>(&g_side[(size_t)rr * 128 + k0 + kg * 4]);
            }
            float sx = e.x + s.x, sy = e.y + s.y, sz = e.z + s.z, sw = e.w + s.w;
            float px = e.x * s.x, py = e.y * s.y, pz = e.z * s.z, pw = e.w * s.w;
            unsigned h01, l01, h23, l23;
            split2(sx, sy, h01, l01); split2(sz, sw, h23, l23);
            *reinterpret_cast<uint2*>(&Ah[r * 40 + kg * 4]) = make_uint2(h01, h23);
            *reinterpret_cast<uint2*>(&Al[r * 40 + kg * 4]) = make_uint2(l01, l23);
            split2(px, py, h01, l01); split2(pz, pw, h23, l23);
            *reinterpret_cast<uint2*>(&Ph[r * 40 + kg * 4]) = make_uint2(h01, h23);
            *reinterpret_cast<uint2*>(&Pl[r * 40 + kg * 4]) = make_uint2(l01, l23);
        }
        __syncthreads();

        #pragma unroll
        for (int ks = 0; ks < 2; ks++) {
            unsigned sh[4], sl[4], ph[4], pl[4];
            ldsm4(sh, aAh + ks * 32);
            ldsm4(sl, aAl + ks * 32);
            ldsm4(ph, aPh + ks * 32);
            ldsm4(pl, aPl + ks * 32);
            #pragma unroll
            for (int np = 0; np < 4; np++) {
                unsigned b1h[4], b1l[4], b2h[4], b2l[4];
                ldsm4(b1h, aB1h + np * 1280 + ks * 32);
                ldsm4(b1l, aB1l + np * 1280 + ks * 32);
                ldsm4(b2h, aB2h + np * 1280 + ks * 32);
                ldsm4(b2l, aB2l + np * 1280 + ks * 32);
                mma_bf16(c1[2 * np],     sh, b1h);
                mma_bf16(c1[2 * np],     sh, b1l);
                mma_bf16(c1[2 * np],     sl, b1h);
                mma_bf16(c1[2 * np + 1], sh, b1h + 2);
                mma_bf16(c1[2 * np + 1], sh, b1l + 2);
                mma_bf16(c1[2 * np + 1], sl, b1h + 2);
                mma_bf16(c2[2 * np],     ph, b2h);
                mma_bf16(c2[2 * np],     ph, b2l);
                mma_bf16(c2[2 * np],     pl, b2h);
                mma_bf16(c2[2 * np + 1], ph, b2h + 2);
                mma_bf16(c2[2 * np + 1], ph, b2l + 2);
                mma_bf16(c2[2 * np + 1], pl, b2h + 2);
            }
        }
        __syncthreads();
    }

    int colb = wn * 64 + (lane & 3) * 2;
    int r0g = row0 + wm * 16 + (lane >> 2);
    int r1g = r0g + 8;
    bool v0 = r0g < M, v1 = r1g < M;
    #pragma unroll
    for (int nt = 0; nt < 8; nt++) {
        int col = colb + nt * 8;
        float2 bv1 = *reinterpret_cast<const float2*>(&b1[col]);
        float2 bv2 = *reinterpret_cast<const float2*>(&b2[col]);
        float x0 = c1[nt][0] + bv1.x, x1 = c1[nt][1] + bv1.y;
        float x2 = c1[nt][2] + bv1.x, x3 = c1[nt][3] + bv1.y;
        float y0 = c2[nt][0] + bv2.x, y1 = c2[nt][1] + bv2.y;
        float y2 = c2[nt][2] + bv2.x, y3 = c2[nt][3] + bv2.y;
        x0 = (x0 > 0.f) ? x0 : 0.01f * x0;  y0 = (y0 > 0.f) ? y0 : 0.01f * y0;
        x1 = (x1 > 0.f) ? x1 : 0.01f * x1;  y1 = (y1 > 0.f) ? y1 : 0.01f * y1;
        x2 = (x2 > 0.f) ? x2 : 0.01f * x2;  y2 = (y2 > 0.f) ? y2 : 0.01f * y2;
        x3 = (x3 > 0.f) ? x3 : 0.01f * x3;  y3 = (y3 > 0.f) ? y3 : 0.01f * y3;
        if (v0) *reinterpret_cast<float2*>(&out[(size_t)r0g * 128 + col]) = make_float2(x0 + y0, x1 + y1);
        if (v1) *reinterpret_cast<float2*>(&out[(size_t)r1g * 128 + col]) = make_float2(x2 + y2, x3 + y3);
    }
}

// ------------------------------ bf16x3 mma GEMM core (256 thr, 8 warps 4m x 2n) ------------------------------
template<int K, int NOUT>
DEV_INLINE void mma_core(const float* __restrict__ A,
                         const __nv_bfloat16* __restrict__ Whi, int loN,
                         const float* __restrict__ bias, const float* __restrict__ R,
                         const float* __restrict__ lnG, const float* __restrict__ lnB,
                         float* __restrict__ C, int M, int mode, int cb)
{
    __shared__ __align__(16) __nv_bfloat16 Ah[64][40];
    __shared__ __align__(16) __nv_bfloat16 Al[64][40];
    __shared__ __align__(16) __nv_bfloat16 Bh[128][40];
    __shared__ __align__(16) __nv_bfloat16 Bl[128][40];
    __shared__ float Sred[2][64], Qred[2][64];

    int tid = threadIdx.x, lane = tid & 31, wy = tid >> 5;
    int wm = wy >> 1, wn = wy & 1;
    int row0 = blockIdx.x * 64;

    float c[8][4];
    #pragma unroll
    for (int t = 0; t < 8; t++)
        #pragma unroll
        for (int j = 0; j < 4; j++) c[t][j] = 0.f;

    int arow = wm * 16 + (lane & 7) + ((lane >> 3) & 1) * 8;
    int akc  = (lane >> 4) * 8;
    unsigned aAh = smem_u32(&Ah[arow][akc]);
    unsigned aAl = smem_u32(&Al[arow][akc]);
    int bn = wn * 64 + (lane & 7) + ((lane >> 4) << 3);
    int bk = ((lane >> 3) & 1) * 8;
    unsigned aBh = smem_u32(&Bh[bn][bk]);
    unsigned aBl = smem_u32(&Bl[bn][bk]);

    for (int ch = 0; ch < K / 32; ch++) {
        int k0 = ch * 32;
        #pragma unroll
        for (int i = 0; i < 2; i++) {
            int idx = tid + i * 256;
            int n = idx >> 2, part = idx & 3;
            const uint4* sh = reinterpret_cast<const uint4*>(Whi + (size_t)(cb + n) * K + k0);
            const uint4* sl = reinterpret_cast<const uint4*>(Whi + loN + (size_t)(cb + n) * K + k0);
            *reinterpret_cast<uint4*>(&Bh[n][part * 8]) = sh[part];
            *reinterpret_cast<uint4*>(&Bl[n][part * 8]) = sl[part];
        }
        #pragma unroll
        for (int i = 0; i < 2; i++) {
            int idx = tid + i * 256;
            int r = idx >> 3, kg = idx & 7;
            int rr = row0 + r;
            float4 av = make_float4(0.f, 0.f, 0.f, 0.f);
            if (rr < M)
                av = *reinterpret_cast<const float4*>(&A[(size_t)rr * K + k0 + kg * 4]);
            unsigned h01, l01, h23, l23;
            split2(av.x, av.y, h01, l01);
            split2(av.z, av.w, h23, l23);
            *reinterpret_cast<uint2*>(&Ah[r][kg * 4]) = make_uint2(h01, h23);
            *reinterpret_cast<uint2*>(&Al[r][kg * 4]) = make_uint2(l01, l23);
        }
        __syncthreads();

        #pragma unroll
        for (int ks = 0; ks < 2; ks++) {
            unsigned ah[4], al[4];
            ldsm4(ah, aAh + ks * 32);
            ldsm4(al, aAl + ks * 32);
            #pragma unroll
            for (int np = 0; np < 4; np++) {
                unsigned bh[4], bl[4];
                ldsm4(bh, aBh + np * 1280 + ks * 32);
                ldsm4(bl, aBl + np * 1280 + ks * 32);
                mma_bf16(c[2 * np],     ah, bh);
                mma_bf16(c[2 * np],     ah, bl);
                mma_bf16(c[2 * np],     al, bh);
                mma_bf16(c[2 * np + 1], ah, bh + 2);
                mma_bf16(c[2 * np + 1], ah, bl + 2);
                mma_bf16(c[2 * np + 1], al, bh + 2);
            }
        }
        __syncthreads();
    }

    int colb = cb + wn * 64 + (lane & 3) * 2;
    int lr0 = wm * 16 + (lane >> 2);
    int r0g = row0 + lr0;
    int r1g = r0g + 8;
    bool v0 = r0g < M, v1 = r1g < M;

    if (mode == 5) {
        float s0 = 0.f, q0 = 0.f, s1 = 0.f, q1 = 0.f;
        #pragma unroll
        for (int nt = 0; nt < 8; nt++) {
            int col = colb + nt * 8;
            float2 bv = *reinterpret_cast<const float2*>(&bias[col]);
            float2 rA = v0 ? *reinterpret_cast<const float2*>(&R[(size_t)r0g * 128 + col]) : make_float2(0.f, 0.f);
            float2 rB = v1 ? *reinterpret_cast<const float2*>(&R[(size_t)r1g * 128 + col]) : make_float2(0.f, 0.f);
            c[nt][0] += bv.x + rA.x; c[nt][1] += bv.y + rA.y;
            c[nt][2] += bv.x + rB.x; c[nt][3] += bv.y + rB.y;
            s0 += c[nt][0] + c[nt][1]; q0 += c[nt][0] * c[nt][0] + c[nt][1] * c[nt][1];
            s1 += c[nt][2] + c[nt][3]; q1 += c[nt][2] * c[nt][2] + c[nt][3] * c[nt][3];
        }
        #pragma unroll
        for (int o = 1; o <= 2; o <<= 1) {
            s0 += __shfl_xor_sync(0xffffffff, s0, o);
            q0 += __shfl_xor_sync(0xffffffff, q0, o);
            s1 += __shfl_xor_sync(0xffffffff, s1, o);
            q1 += __shfl_xor_sync(0xffffffff, q1, o);
        }
        if ((lane & 3) == 0) {
            Sred[wn][lr0] = s0; Qred[wn][lr0] = q0;
            Sred[wn][lr0 + 8] = s1; Qred[wn][lr0 + 8] = q1;
        }
        __syncthreads();
        float S0 = Sred[0][lr0] + Sred[1][lr0];
        float Q0 = Qred[0][lr0] + Qred[1][lr0];
        float S1 = Sred[0][lr0 + 8] + Sred[1][lr0 + 8];
        float Q1 = Qred[0][lr0 + 8] + Qred[1][lr0 + 8];
        float m0 = S0 * (1.f / 128.f), var0 = Q0 * (1.f / 128.f) - m0 * m0;
        float m1 = S1 * (1.f / 128.f), var1 = Q1 * (1.f / 128.f) - m1 * m1;
        float rs0 = rsqrtf(var0 + 1e-5f), rs1 = rsqrtf(var1 + 1e-5f);
        #pragma unroll
        for (int nt = 0; nt < 8; nt++) {
            int col = colb + nt * 8;
            float2 g = *reinterpret_cast<const float2*>(&lnG[col]);
            float2 be = *reinterpret_cast<const float2*>(&lnB[col]);
            if (v0) {
                float2 o = make_float2((c[nt][0] - m0) * rs0 * g.x + be.x,
                                       (c[nt][1] - m0) * rs0 * g.y + be.y);
                *reinterpret_cast<float2*>(&C[(size_t)r0g * 128 + col]) = o;
            }
            if (v1) {
                float2 o = make_float2((c[nt][2] - m1) * rs1 * g.x + be.x,
                                       (c[nt][3] - m1) * rs1 * g.y + be.y);
                *reinterpret_cast<float2*>(&C[(size_t)r1g * 128 + col]) = o;
            }
        }
    } else {
        #pragma unroll
        for (int nt = 0; nt < 8; nt++) {
            int col = colb + nt * 8;
            float2 bv = *reinterpret_cast<const float2*>(&bias[col]);
            float x0 = c[nt][0] + bv.x, x1 = c[nt][1] + bv.y;
            float x2 = c[nt][2] + bv.x, x3 = c[nt][3] + bv.y;
            if (mode == 1) {
                x0 = fmaxf(x0, 0.f); x1 = fmaxf(x1, 0.f);
                x2 = fmaxf(x2, 0.f); x3 = fmaxf(x3, 0.f);
            }
            if (v0) *reinterpret_cast<float2*>(&C[(size_t)r0g * NOUT + col]) = make_float2(x0, x1);
            if (v1) *reinterpret_cast<float2*>(&C[(size_t)r1g * NOUT + col]) = make_float2(x2, x3);
        }
    }
}

template<int K, int NOUT>
__global__ void __launch_bounds__(256) mma_gemm_kernel(
    const float* __restrict__ Aext, int Aid,
    unsigned woff, int loN,
    const float* __restrict__ bias,
    int Rid, const float* __restrict__ Rext,
    const float* __restrict__ lnG, const float* __restrict__ lnB,
    float* __restrict__ Cext, int Cid, int M, int mode)
{
    const float* A = Aext ? Aext : bufptr(Aid);
    float*       C = Cext ? Cext : bufptr(Cid);
    const float* R = nullptr;
    if (mode == 5) R = Rext ? Rext : bufptr(Rid);
    int cb = (NOUT > 128) ? blockIdx.y * 128 : 0;
    mma_core<K, NOUT>(A, g_wbf + woff, loN, bias, R, lnG, lnB, C, M, mode, cb);
}

// qkv fused: grid.y selects q/k/v
__global__ void __launch_bounds__(256) mma_qkv_kernel(
    const float* __restrict__ Aext, int Aid, unsigned wbase,
    const float* __restrict__ bq, const float* __restrict__ bk,
    const float* __restrict__ bv, int M)
{
    int sel = blockIdx.y;
    const float* bias = (sel == 0) ? bq : (sel == 1) ? bk : bv;
    const float* A = Aext ? Aext : bufptr(Aid);
    mma_core<128, 128>(A, g_wbf + wbase + sel * 32768u, 16384,
                       bias, nullptr, nullptr, nullptr, bufptr(BQ + sel), M, 0, 0);
}

// ------------------------------ attention (f32x2, split dot chain) ------------------------------
__global__ void __launch_bounds__(256) attn_kernel(int unused)
{
    __shared__ __align__(16) float Ks[LSEQ * DK];
    __shared__ __align__(16) float Vs[LSEQ * DK];
    int b = blockIdx.x >> 3;
    int h = blockIdx.x & 7;
    int tid = threadIdx.x;
    int base = (b * LSEQ) * D + h * DK;

    for (int idx = tid; idx < LSEQ * DK; idx += 256) {
        int m = idx >> 4, j = idx & 15;
        Ks[idx] = g_k[base + m * D + j];
        Vs[idx] = g_v[base + m * D + j];
    }
    __syncthreads();

    unsigned long long q2[8];
    {
        const unsigned long long* qp = reinterpret_cast<const unsigned long long*>(g_q + base + tid * D);
        #pragma unroll
        for (int j = 0; j < 8; j++) q2[j] = qp[j];
    }

    unsigned long long acc[8];
    const unsigned long long z2 = pack2(0.f, 0.f);
    #pragma unroll
    for (int j = 0; j < 8; j++) acc[j] = z2;
    float mx = -3.0e38f, sum = 0.f;

    const unsigned long long* Ks2 = reinterpret_cast<const unsigned long long*>(Ks);
    const unsigned long long* Vs2 = reinterpret_cast<const unsigned long long*>(Vs);

    for (int m = 0; m < LSEQ; m++) {
        unsigned long long d2a = z2, d2b = z2;   // two independent chains
        #pragma unroll
        for (int j = 0; j < 4; j++) {
            ffma2(d2a, q2[j],     Ks2[m * 8 + j]);
            ffma2(d2b, q2[j + 4], Ks2[m * 8 + j + 4]);
        }
        float la, ha, lb, hb;
        unpack2(d2a, la, ha);
        unpack2(d2b, lb, hb);
        float s = ((la + lb) + (ha + hb)) * 0.25f;

        if (s <= mx) {
            float pe = __expf(s - mx);
            sum += pe;
            unsigned long long pe2 = pack2(pe, pe);
            #pragma unroll
            for (int j = 0; j < 8; j++)
                ffma2(acc[j], Vs2[m * 8 + j], pe2);
        } else {
            float corr = __expf(mx - s);
            sum = sum * corr + 1.f;
            unsigned long long c2 = pack2(corr, corr);
            #pragma unroll
            for (int j = 0; j < 8; j++) {
                unsigned long long t;
                fmul2(t, acc[j], c2);
                fadd2(acc[j], t, Vs2[m * 8 + j]);
            }
            mx = s;
        }
    }

    float inv = 1.f / sum;
    float* op = g_o + base + tid * D;
    #pragma unroll
    for (int j = 0; j < 8; j++) {
        float lo, hi;
        unpack2(acc[j], lo, hi);
        op[j * 2 + 0] = lo * inv;
        op[j * 2 + 1] = hi * inv;
    }
}

// ------------------------------ launch ------------------------------
extern "C" void kernel_launch(void* const* d_in, const int* in_sizes, int n_in,
                              void* d_out, int out_size)
{
    const float* ego    = (const float*)d_in[0];
    const float* vals   = (const float*)d_in[1];
    const float* W1     = (const float*)d_in[2];
    const float* b1     = (const float*)d_in[3];
    const float* W2     = (const float*)d_in[4];
    const float* b2     = (const float*)d_in[5];
    const float* enc_in = (const float*)d_in[6];
    const float* wq     = (const float*)d_in[7];
    const float* bq     = (const float*)d_in[8];
    const float* wk     = (const float*)d_in[9];
    const float* bk     = (const float*)d_in[10];
    const float* wv     = (const float*)d_in[11];
    const float* bv     = (const float*)d_in[12];
    const float* wo     = (const float*)d_in[13];
    const float* bo     = (const float*)d_in[14];
    const float* ln1_g  = (const float*)d_in[15];
    const float* ln1_b  = (const float*)d_in[16];
    const float* cw1    = (const float*)d_in[17];
    const float* cb1    = (const float*)d_in[18];
    const float* cw2    = (const float*)d_in[19];
    const float* cb2    = (const float*)d_in[20];
    const float* ln2_g  = (const float*)d_in[21];
    const float* ln2_b  = (const float*)d_in[22];
    const int*   rows   = (const int*)d_in[23];
    const int*   cols   = (const int*)d_in[24];
    float* out = (float*)d_out;

    int Nego = in_sizes[0] / 128;       // 100000
    int nnz  = in_sizes[1];             // 2000000
    int Mt   = in_sizes[6] / 128;       // 8192
    int B    = Mt / LSEQ;               // 32
    int NL   = in_sizes[7] / (128 * 128);

    const int AGG_SMEM = 61440;
    cudaFuncSetAttribute(agg_mma_kernel, cudaFuncAttributeMaxDynamicSharedMemorySize, AGG_SMEM);

    // Side stream + events (host-side objects only)
    cudaStream_t s2;
    cudaEvent_t ev_prep, ev_join;
    cudaStreamCreateWithFlags(&s2, cudaStreamNonBlocking);
    cudaEventCreateWithFlags(&ev_prep, cudaEventDisableTiming);
    cudaEventCreateWithFlags(&ev_join, cudaEventDisableTiming);

    // ---- side branch starts immediately: zero + spmm (independent of prep) ----
    zero_side_kernel<<<1024, 256, 0, s2>>>((Nego * 128) / 4);
    int nwarps = (nnz + EPW - 1) / EPW;
    int spmm_blocks = (nwarps * 32 + 255) / 256;
    spmm_kernel<<<spmm_blocks, 256, 0, s2>>>(ego, vals, rows, cols, nnz);

    // ---- main: weight images; record event for agg's dependence on g_wbf ----
    prep_w_kernel<<<dim3(64, 2 + 6 * NL), 256>>>(W1, W2, wq, wk, wv, wo, cw1, cw2, NL);
    cudaEventRecord(ev_prep, 0);
    cudaStreamWaitEvent(s2, ev_prep, 0);

    // ---- side branch: fused aggregator ----
    agg_mma_kernel<<<(Nego + 63) / 64, 256, AGG_SMEM, s2>>>(ego, b1, b2, out, Nego);

    // ---- transformer encoder (main stream) ----
    const float* xin_ext = enc_in;
    int xin_id = -1;
    int gb = Mt / 64;   // 128

    for (int i = 0; i < NL; i++) {
        unsigned lbase = 65536u + (unsigned)i * 393216u;
        const float* bq_ = bq + i * D;
        const float* bk_ = bk + i * D;
        const float* bv_ = bv + i * D;
        const float* bo_ = bo + i * D;
        const float* g1_ = ln1_g + i * D;  const float* be1_ = ln1_b + i * D;
        const float* cb1_ = cb1 + i * DI;
        const float* cb2_ = cb2 + i * D;
        const float* g2_ = ln2_g + i * D;  const float* be2_ = ln2_b + i * D;

        mma_qkv_kernel<<<dim3(gb, 3), 256>>>(xin_ext, xin_id, lbase, bq_, bk_, bv_, Mt);
        attn_kernel<<<B * 8, 256>>>(0);
        mma_gemm_kernel<128, 128><<<gb, 256>>>(nullptr, BO, lbase + 3u * 32768u, 16384, bo_,
                                               xin_id, xin_ext, g1_, be1_, nullptr, BX1, Mt, 5);
        mma_gemm_kernel<128, 512><<<dim3(gb, 4), 256>>>(nullptr, BX1, lbase + 131072u, 65536, cb1_,
                                                        -1, nullptr, nullptr, nullptr, nullptr, BH, Mt, 1);
        bool last = (i == NL - 1);
        mma_gemm_kernel<512, 128><<<gb, 256>>>(nullptr, BH, lbase + 262144u, 65536, cb2_,
                                               BX1, nullptr, g2_, be2_,
                                               last ? (out + (size_t)in_sizes[0]) : nullptr,
                                               BX2, Mt, 5);
        xin_ext = nullptr;
        xin_id = BX2;
    }

    // join
    cudaEventRecord(ev_join, s2);
    cudaStreamWaitEvent((cudaStream_t)0, ev_join, 0);
}

// round 14
// speedup vs baseline: 2.1109x; 1.0282x over previous
#include <cuda_runtime.h>
#include <cuda_bf16.h>
#include <math.h>

#define DEV_INLINE __device__ __forceinline__

static const int D    = 128;
static const int LSEQ = 256;
static const int DK   = 16;
static const int DI   = 512;

// ------------------------- scratch (device globals) -------------------------
__device__ float g_side[12800000];   // side = A_in @ ego
__device__ float g_q [1048576];
__device__ float g_k [1048576];
__device__ float g_v [1048576];
__device__ float g_o [1048576];
__device__ float g_x1[1048576];
__device__ float g_x2[1048576];
__device__ float g_h [4194304];      // 8192 x 512
__device__ __align__(16) __nv_bfloat16 g_wbf[1048576];  // weight bf16 hi/lo images, [n][k]

enum { BQ = 0, BK = 1, BV = 2, BO = 3, BX1 = 5, BX2 = 6, BH = 7 };

DEV_INLINE float* bufptr(int id) {
    switch (id) {
        case BQ:  return g_q;
        case BK:  return g_k;
        case BV:  return g_v;
        case BO:  return g_o;
        case BX1: return g_x1;
        case BX2: return g_x2;
        case BH:  return g_h;
    }
    return nullptr;
}

// ------------------------- f32x2 helpers (attention) -------------------------
DEV_INLINE unsigned long long pack2(float lo, float hi) {
    unsigned long long r;
    asm("mov.b64 %0, {%1, %2};" : "=l"(r) : "f"(lo), "f"(hi));
    return r;
}
DEV_INLINE void unpack2(unsigned long long v, float& lo, float& hi) {
    asm("mov.b64 {%0, %1}, %2;" : "=f"(lo), "=f"(hi) : "l"(v));
}
DEV_INLINE void ffma2(unsigned long long& d, unsigned long long a, unsigned long long b) {
    asm("fma.rn.f32x2 %0, %1, %2, %0;" : "+l"(d) : "l"(a), "l"(b));
}
DEV_INLINE void fmul2(unsigned long long& d, unsigned long long a, unsigned long long b) {
    asm("mul.rn.f32x2 %0, %1, %2;" : "=l"(d) : "l"(a), "l"(b));
}
DEV_INLINE void fadd2(unsigned long long& d, unsigned long long a, unsigned long long b) {
    asm("add.rn.f32x2 %0, %1, %2;" : "=l"(d) : "l"(a), "l"(b));
}

// ------------------------- mma helpers -------------------------
DEV_INLINE unsigned smem_u32(const void* p) {
    unsigned a;
    asm("{ .reg .u64 t; cvta.to.shared.u64 t, %1; cvt.u32.u64 %0, t; }" : "=r"(a) : "l"(p));
    return a;
}
DEV_INLINE void ldsm4(unsigned* r, unsigned addr) {
    asm volatile("ldmatrix.sync.aligned.m8n8.x4.shared.b16 {%0,%1,%2,%3}, [%4];"
        : "=r"(r[0]), "=r"(r[1]), "=r"(r[2]), "=r"(r[3]) : "r"(addr));
}
DEV_INLINE void mma_bf16(float* c, const unsigned* a, const unsigned* b) {
    asm volatile(
        "mma.sync.aligned.m16n8k16.row.col.f32.bf16.bf16.f32 "
        "{%0,%1,%2,%3}, {%4,%5,%6,%7}, {%8,%9}, {%0,%1,%2,%3};"
        : "+f"(c[0]), "+f"(c[1]), "+f"(c[2]), "+f"(c[3])
        : "r"(a[0]), "r"(a[1]), "r"(a[2]), "r"(a[3]), "r"(b[0]), "r"(b[1]));
}
DEV_INLINE void split2(float x, float y, unsigned& h, unsigned& l) {
    __nv_bfloat162 hv = __floats2bfloat162_rn(x, y);
    float lx = x - __bfloat162float(hv.x);
    float ly = y - __bfloat162float(hv.y);
    __nv_bfloat162 lv = __floats2bfloat162_rn(lx, ly);
    h = *reinterpret_cast<unsigned*>(&hv);
    l = *reinterpret_cast<unsigned*>(&lv);
}

// ------------------------------ zero side ------------------------------
__global__ void zero_side_kernel(int n4) {
    float4* p = reinterpret_cast<float4*>(g_side);
    int i = blockIdx.x * blockDim.x + threadIdx.x;
    int stride = gridDim.x * blockDim.x;
    float4 z = make_float4(0.f, 0.f, 0.f, 0.f);
    for (; i < n4; i += stride) p[i] = z;
}

// ------------------------------ SpMM (COO, rows sorted, 8-edge batched MLP) ------------------------------
static const int EPW = 256;   // multiple of 8

DEV_INLINE void spmm_flush(int row, int lane, float4 acc) {
    float* p = &g_side[(size_t)row * 128 + lane * 4];
    atomicAdd(p + 0, acc.x);
    atomicAdd(p + 1, acc.y);
    atomicAdd(p + 2, acc.z);
    atomicAdd(p + 3, acc.w);
}

__global__ void __launch_bounds__(256) spmm_kernel(
    const float* __restrict__ ego, const float* __restrict__ vals,
    const int* __restrict__ rows, const int* __restrict__ cols, int nnz)
{
    int warp = (blockIdx.x * blockDim.x + threadIdx.x) >> 5;
    int lane = threadIdx.x & 31;
    long e0 = (long)warp * EPW;
    if (e0 >= nnz) return;
    long e1 = e0 + EPW; if (e1 > nnz) e1 = nnz;

    const float4* ego4 = reinterpret_cast<const float4*>(ego);
    float4 acc = make_float4(0.f, 0.f, 0.f, 0.f);
    int cur = rows[e0];

    for (long e = e0; e < e1; e += 8) {
        int nb = (int)((e1 - e < 8) ? (e1 - e) : 8);
        int4  r4a = *reinterpret_cast<const int4*>(&rows[e]);
        int4  r4b = *reinterpret_cast<const int4*>(&rows[e + 4]);
        int4  c4a = *reinterpret_cast<const int4*>(&cols[e]);
        int4  c4b = *reinterpret_cast<const int4*>(&cols[e + 4]);
        float4 v4a = *reinterpret_cast<const float4*>(&vals[e]);
        float4 v4b = *reinterpret_cast<const float4*>(&vals[e + 4]);
        int   r[8] = {r4a.x, r4a.y, r4a.z, r4a.w, r4b.x, r4b.y, r4b.z, r4b.w};
        int   c[8] = {c4a.x, c4a.y, c4a.z, c4a.w, c4b.x, c4b.y, c4b.z, c4b.w};
        float v[8] = {v4a.x, v4a.y, v4a.z, v4a.w, v4b.x, v4b.y, v4b.z, v4b.w};
        float4 g[8];
        #pragma unroll
        for (int j = 0; j < 8; j++)
            g[j] = ego4[(size_t)c[j] * 32 + lane];
        #pragma unroll
        for (int j = 0; j < 8; j++) {
            if (j >= nb) break;
            if (r[j] != cur) {
                spmm_flush(cur, lane, acc);
                acc = make_float4(0.f, 0.f, 0.f, 0.f);
                cur = r[j];
            }
            acc.x += v[j] * g[j].x;
            acc.y += v[j] * g[j].y;
            acc.z += v[j] * g[j].z;
            acc.w += v[j] * g[j].w;
        }
    }
    spmm_flush(cur, lane, acc);
}

// ------------------------------ prep: weight bf16 hi/lo images, [n][k] ------------------------------
__global__ void __launch_bounds__(256) prep_w_kernel(
    const float* __restrict__ W1, const float* __restrict__ W2,
    const float* __restrict__ wq, const float* __restrict__ wk,
    const float* __restrict__ wv, const float* __restrict__ wo,
    const float* __restrict__ cw1, const float* __restrict__ cw2, int NL)
{
    int y = blockIdx.y;
    const float* src; unsigned off; int Kd, Nd;
    if (y < 2) { src = y ? W2 : W1; off = (unsigned)y * 32768u; Kd = 128; Nd = 128; }
    else {
        int i = (y - 2) / 6, j = (y - 2) % 6;
        unsigned base = 65536u + (unsigned)i * 393216u;
        if (j < 4) {
            const float* p = (j == 0) ? wq : (j == 1) ? wk : (j == 2) ? wv : wo;
            src = p + (size_t)i * 16384; off = base + (unsigned)j * 32768u; Kd = 128; Nd = 128;
        } else if (j == 4) {
            src = cw1 + (size_t)i * 65536; off = base + 131072u; Kd = 128; Nd = 512;
        } else {
            src = cw2 + (size_t)i * 65536; off = base + 262144u; Kd = 512; Nd = 128;
        }
    }
    int tot = Kd * Nd;
    for (int idx = blockIdx.x * 256 + threadIdx.x; idx < tot; idx += gridDim.x * 256) {
        int n = idx / Kd, k = idx - n * Kd;
        float w = src[(size_t)k * Nd + n];
        __nv_bfloat16 h = __float2bfloat16(w);
        float l = w - __bfloat162float(h);
        g_wbf[off + (size_t)n * Kd + k] = h;
        g_wbf[off + (size_t)tot + (size_t)n * Kd + k] = __float2bfloat16(l);
    }
}

// ------------------------------ fused aggregator (bf16x3 mma, both GEMMs one pass) ------------------------------
__global__ void __launch_bounds__(256, 2) agg_mma_kernel(
    const float* __restrict__ ego,
    const float* __restrict__ b1, const float* __restrict__ b2,
    float* __restrict__ out, int M)
{
    extern __shared__ __align__(16) char dsm[];
    __nv_bfloat16* Ah  = reinterpret_cast<__nv_bfloat16*>(dsm);
    __nv_bfloat16* Al  = reinterpret_cast<__nv_bfloat16*>(dsm + 5120);
    __nv_bfloat16* Ph  = reinterpret_cast<__nv_bfloat16*>(dsm + 10240);
    __nv_bfloat16* Pl  = reinterpret_cast<__nv_bfloat16*>(dsm + 15360);
    __nv_bfloat16* B1h = reinterpret_cast<__nv_bfloat16*>(dsm + 20480);
    __nv_bfloat16* B1l = reinterpret_cast<__nv_bfloat16*>(dsm + 30720);
    __nv_bfloat16* B2h = reinterpret_cast<__nv_bfloat16*>(dsm + 40960);
    __nv_bfloat16* B2l = reinterpret_cast<__nv_bfloat16*>(dsm + 51200);

    int tid = threadIdx.x, lane = tid & 31, wy = tid >> 5;
    int wm = wy >> 1, wn = wy & 1;
    int row0 = blockIdx.x * 64;

    float c1[8][4], c2[8][4];
    #pragma unroll
    for (int t = 0; t < 8; t++)
        #pragma unroll
        for (int j = 0; j < 4; j++) { c1[t][j] = 0.f; c2[t][j] = 0.f; }

    int arow = wm * 16 + (lane & 7) + ((lane >> 3) & 1) * 8;
    int akc  = (lane >> 4) * 8;
    unsigned aAh = smem_u32(&Ah[arow * 40 + akc]);
    unsigned aAl = smem_u32(&Al[arow * 40 + akc]);
    unsigned aPh = smem_u32(&Ph[arow * 40 + akc]);
    unsigned aPl = smem_u32(&Pl[arow * 40 + akc]);
    int bn = wn * 64 + (lane & 7) + ((lane >> 4) << 3);
    int bk = ((lane >> 3) & 1) * 8;
    unsigned aB1h = smem_u32(&B1h[bn * 40 + bk]);
    unsigned aB1l = smem_u32(&B1l[bn * 40 + bk]);
    unsigned aB2h = smem_u32(&B2h[bn * 40 + bk]);
    unsigned aB2l = smem_u32(&B2l[bn * 40 + bk]);

    const __nv_bfloat16* W1h = g_wbf;
    const __nv_bfloat16* W1l = g_wbf + 16384;
    const __nv_bfloat16* W2h = g_wbf + 32768;
    const __nv_bfloat16* W2l = g_wbf + 49152;

    for (int ch = 0; ch < 4; ch++) {
        int k0 = ch * 32;
        #pragma unroll
        for (int i = 0; i < 2; i++) {
            int idx = tid + i * 256;
            int n = idx >> 2, part = idx & 3;
            size_t go = (size_t)n * 128 + k0;
            *reinterpret_cast<uint4*>(&B1h[n * 40 + part * 8]) = reinterpret_cast<const uint4*>(W1h + go)[part];
            *reinterpret_cast<uint4*>(&B1l[n * 40 + part * 8]) = reinterpret_cast<const uint4*>(W1l + go)[part];
            *reinterpret_cast<uint4*>(&B2h[n * 40 + part * 8]) = reinterpret_cast<const uint4*>(W2h + go)[part];
            *reinterpret_cast<uint4*>(&B2l[n * 40 + part * 8]) = reinterpret_cast<const uint4*>(W2l + go)[part];
        }
        #pragma unroll
        for (int i = 0; i < 2; i++) {
            int idx = tid + i * 256;
            int r = idx >> 3, kg = idx & 7;
            int rr = row0 + r;
            float4 e = make_float4(0.f, 0.f, 0.f, 0.f);
            float4 s = make_float4(0.f, 0.f, 0.f, 0.f);
            if (rr < M) {
                e = *reinterpret_cast<const float4*>(&ego   [(size_t)rr * 128 + k0 + kg * 4]);
                s = *reinterpret_cast<const float4*>(&g_side[(size_t)rr * 128 + k0 + kg * 4]);
            }
            float sx = e.x + s.x, sy = e.y + s.y, sz = e.z + s.z, sw = e.w + s.w;
            float px = e.x * s.x, py = e.y * s.y, pz = e.z * s.z, pw = e.w * s.w;
            unsigned h01, l01, h23, l23;
            split2(sx, sy, h01, l01); split2(sz, sw, h23, l23);
            *reinterpret_cast<uint2*>(&Ah[r * 40 + kg * 4]) = make_uint2(h01, h23);
            *reinterpret_cast<uint2*>(&Al[r * 40 + kg * 4]) = make_uint2(l01, l23);
            split2(px, py, h01, l01); split2(pz, pw, h23, l23);
            *reinterpret_cast<uint2*>(&Ph[r * 40 + kg * 4]) = make_uint2(h01, h23);
            *reinterpret_cast<uint2*>(&Pl[r * 40 + kg * 4]) = make_uint2(l01, l23);
        }
        __syncthreads();

        #pragma unroll
        for (int ks = 0; ks < 2; ks++) {
            unsigned sh[4], sl[4], ph[4], pl[4];
            ldsm4(sh, aAh + ks * 32);
            ldsm4(sl, aAl + ks * 32);
            ldsm4(ph, aPh + ks * 32);
            ldsm4(pl, aPl + ks * 32);
            #pragma unroll
            for (int np = 0; np < 4; np++) {
                unsigned b1h[4], b1l[4], b2h[4], b2l[4];
                ldsm4(b1h, aB1h + np * 1280 + ks * 32);
                ldsm4(b1l, aB1l + np * 1280 + ks * 32);
                ldsm4(b2h, aB2h + np * 1280 + ks * 32);
                ldsm4(b2l, aB2l + np * 1280 + ks * 32);
                mma_bf16(c1[2 * np],     sh, b1h);
                mma_bf16(c1[2 * np],     sh, b1l);
                mma_bf16(c1[2 * np],     sl, b1h);
                mma_bf16(c1[2 * np + 1], sh, b1h + 2);
                mma_bf16(c1[2 * np + 1], sh, b1l + 2);
                mma_bf16(c1[2 * np + 1], sl, b1h + 2);
                mma_bf16(c2[2 * np],     ph, b2h);
                mma_bf16(c2[2 * np],     ph, b2l);
                mma_bf16(c2[2 * np],     pl, b2h);
                mma_bf16(c2[2 * np + 1], ph, b2h + 2);
                mma_bf16(c2[2 * np + 1], ph, b2l + 2);
                mma_bf16(c2[2 * np + 1], pl, b2h + 2);
            }
        }
        __syncthreads();
    }

    int colb = wn * 64 + (lane & 3) * 2;
    int r0g = row0 + wm * 16 + (lane >> 2);
    int r1g = r0g + 8;
    bool v0 = r0g < M, v1 = r1g < M;
    #pragma unroll
    for (int nt = 0; nt < 8; nt++) {
        int col = colb + nt * 8;
        float2 bv1 = *reinterpret_cast<const float2*>(&b1[col]);
        float2 bv2 = *reinterpret_cast<const float2*>(&b2[col]);
        float x0 = c1[nt][0] + bv1.x, x1 = c1[nt][1] + bv1.y;
        float x2 = c1[nt][2] + bv1.x, x3 = c1[nt][3] + bv1.y;
        float y0 = c2[nt][0] + bv2.x, y1 = c2[nt][1] + bv2.y;
        float y2 = c2[nt][2] + bv2.x, y3 = c2[nt][3] + bv2.y;
        x0 = (x0 > 0.f) ? x0 : 0.01f * x0;  y0 = (y0 > 0.f) ? y0 : 0.01f * y0;
        x1 = (x1 > 0.f) ? x1 : 0.01f * x1;  y1 = (y1 > 0.f) ? y1 : 0.01f * y1;
        x2 = (x2 > 0.f) ? x2 : 0.01f * x2;  y2 = (y2 > 0.f) ? y2 : 0.01f * y2;
        x3 = (x3 > 0.f) ? x3 : 0.01f * x3;  y3 = (y3 > 0.f) ? y3 : 0.01f * y3;
        if (v0) *reinterpret_cast<float2*>(&out[(size_t)r0g * 128 + col]) = make_float2(x0 + y0, x1 + y1);
        if (v1) *reinterpret_cast<float2*>(&out[(size_t)r1g * 128 + col]) = make_float2(x2 + y2, x3 + y3);
    }
}

// ------------------------------ bf16x3 mma GEMM core, 128m x 128n tile (8 warps x 16m) ------------------------------
// modes: 0 +bias store, 1 +bias relu. Row fully inside one warp.
template<int K, int NOUT>
DEV_INLINE void mma_core2(const float* __restrict__ A,
                          const __nv_bfloat16* __restrict__ Whi, int loN,
                          const float* __restrict__ bias,
                          float* __restrict__ C, int M, int mode, int cb)
{
    __shared__ __align__(16) __nv_bfloat16 Ah[128][40];
    __shared__ __align__(16) __nv_bfloat16 Al[128][40];
    __shared__ __align__(16) __nv_bfloat16 Bh[128][40];
    __shared__ __align__(16) __nv_bfloat16 Bl[128][40];

    int tid = threadIdx.x, lane = tid & 31, wy = tid >> 5;
    int row0 = blockIdx.x * 128;

    float c[16][4];
    #pragma unroll
    for (int t = 0; t < 16; t++)
        #pragma unroll
        for (int j = 0; j < 4; j++) c[t][j] = 0.f;

    int arow = wy * 16 + (lane & 7) + ((lane >> 3) & 1) * 8;
    int akc  = (lane >> 4) * 8;
    unsigned aAh = smem_u32(&Ah[arow][akc]);
    unsigned aAl = smem_u32(&Al[arow][akc]);
    int bn = (lane & 7) + ((lane >> 4) << 3);
    int bk = ((lane >> 3) & 1) * 8;
    unsigned aBh = smem_u32(&Bh[bn][bk]);
    unsigned aBl = smem_u32(&Bl[bn][bk]);

    for (int ch = 0; ch < K / 32; ch++) {
        int k0 = ch * 32;
        // stage B: 128n x 32k (4 parts of 8), 2 iters
        #pragma unroll
        for (int i = 0; i < 2; i++) {
            int idx = tid + i * 256;
            int n = idx >> 2, part = idx & 3;
            const uint4* sh = reinterpret_cast<const uint4*>(Whi + (size_t)(cb + n) * K + k0);
            const uint4* sl = reinterpret_cast<const uint4*>(Whi + loN + (size_t)(cb + n) * K + k0);
            *reinterpret_cast<uint4*>(&Bh[n][part * 8]) = sh[part];
            *reinterpret_cast<uint4*>(&Bl[n][part * 8]) = sl[part];
        }
        // stage A: 128r x 8kg, 4 iters
        #pragma unroll
        for (int i = 0; i < 4; i++) {
            int idx = tid + i * 256;
            int r = idx >> 3, kg = idx & 7;
            int rr = row0 + r;
            float4 av = make_float4(0.f, 0.f, 0.f, 0.f);
            if (rr < M)
                av = *reinterpret_cast<const float4*>(&A[(size_t)rr * K + k0 + kg * 4]);
            unsigned h01, l01, h23, l23;
            split2(av.x, av.y, h01, l01);
            split2(av.z, av.w, h23, l23);
            *reinterpret_cast<uint2*>(&Ah[r][kg * 4]) = make_uint2(h01, h23);
            *reinterpret_cast<uint2*>(&Al[r][kg * 4]) = make_uint2(l01, l23);
        }
        __syncthreads();

        #pragma unroll
        for (int ks = 0; ks < 2; ks++) {
            unsigned ah[4], al[4];
            ldsm4(ah, aAh + ks * 32);
            ldsm4(al, aAl + ks * 32);
            #pragma unroll
            for (int np = 0; np < 8; np++) {
                unsigned bh[4], bl[4];
                ldsm4(bh, aBh + np * 1280 + ks * 32);
                ldsm4(bl, aBl + np * 1280 + ks * 32);
                mma_bf16(c[2 * np],     ah, bh);
                mma_bf16(c[2 * np],     ah, bl);
                mma_bf16(c[2 * np],     al, bh);
                mma_bf16(c[2 * np + 1], ah, bh + 2);
                mma_bf16(c[2 * np + 1], ah, bl + 2);
                mma_bf16(c[2 * np + 1], al, bh + 2);
            }
        }
        __syncthreads();
    }

    int colb = cb + (lane & 3) * 2;
    int r0g = row0 + wy * 16 + (lane >> 2);
    int r1g = r0g + 8;
    bool v0 = r0g < M, v1 = r1g < M;
    #pragma unroll
    for (int nt = 0; nt < 16; nt++) {
        int col = colb + nt * 8;
        float2 bv = *reinterpret_cast<const float2*>(&bias[col]);
        float x0 = c[nt][0] + bv.x, x1 = c[nt][1] + bv.y;
        float x2 = c[nt][2] + bv.x, x3 = c[nt][3] + bv.y;
        if (mode == 1) {
            x0 = fmaxf(x0, 0.f); x1 = fmaxf(x1, 0.f);
            x2 = fmaxf(x2, 0.f); x3 = fmaxf(x3, 0.f);
        }
        if (v0) *reinterpret_cast<float2*>(&C[(size_t)r0g * NOUT + col]) = make_float2(x0, x1);
        if (v1) *reinterpret_cast<float2*>(&C[(size_t)r1g * NOUT + col]) = make_float2(x2, x3);
    }
}

// qkv fused: grid.y selects q/k/v (128m core)
__global__ void __launch_bounds__(256, 2) mma_qkv_kernel(
    const float* __restrict__ Aext, int Aid, unsigned wbase,
    const float* __restrict__ bq, const float* __restrict__ bk,
    const float* __restrict__ bv, int M)
{
    int sel = blockIdx.y;
    const float* bias = (sel == 0) ? bq : (sel == 1) ? bk : bv;
    const float* A = Aext ? Aext : bufptr(Aid);
    mma_core2<128, 128>(A, g_wbf + wbase + sel * 32768u, 16384,
                        bias, bufptr(BQ + sel), M, 0, 0);
}

// ffn1 relu (128m core, grid.y over N=512)
__global__ void __launch_bounds__(256, 2) mma_ffn1_kernel(
    int Aid, unsigned woff, const float* __restrict__ bias, int M)
{
    mma_core2<128, 512>(bufptr(Aid), g_wbf + woff, 65536,
                        bias, bufptr(BH), M, 1, blockIdx.y * 128);
}

// ------------------------------ bf16x3 mma GEMM core (64m, 8 warps 4m x 2n) — wo/ffn2 with LN ------------------------------
template<int K, int NOUT>
DEV_INLINE void mma_core(const float* __restrict__ A,
                         const __nv_bfloat16* __restrict__ Whi, int loN,
                         const float* __restrict__ bias, const float* __restrict__ R,
                         const float* __restrict__ lnG, const float* __restrict__ lnB,
                         float* __restrict__ C, int M, int mode, int cb)
{
    __shared__ __align__(16) __nv_bfloat16 Ah[64][40];
    __shared__ __align__(16) __nv_bfloat16 Al[64][40];
    __shared__ __align__(16) __nv_bfloat16 Bh[128][40];
    __shared__ __align__(16) __nv_bfloat16 Bl[128][40];
    __shared__ float Sred[2][64], Qred[2][64];

    int tid = threadIdx.x, lane = tid & 31, wy = tid >> 5;
    int wm = wy >> 1, wn = wy & 1;
    int row0 = blockIdx.x * 64;

    float c[8][4];
    #pragma unroll
    for (int t = 0; t < 8; t++)
        #pragma unroll
        for (int j = 0; j < 4; j++) c[t][j] = 0.f;

    int arow = wm * 16 + (lane & 7) + ((lane >> 3) & 1) * 8;
    int akc  = (lane >> 4) * 8;
    unsigned aAh = smem_u32(&Ah[arow][akc]);
    unsigned aAl = smem_u32(&Al[arow][akc]);
    int bn = wn * 64 + (lane & 7) + ((lane >> 4) << 3);
    int bk = ((lane >> 3) & 1) * 8;
    unsigned aBh = smem_u32(&Bh[bn][bk]);
    unsigned aBl = smem_u32(&Bl[bn][bk]);

    for (int ch = 0; ch < K / 32; ch++) {
        int k0 = ch * 32;
        #pragma unroll
        for (int i = 0; i < 2; i++) {
            int idx = tid + i * 256;
            int n = idx >> 2, part = idx & 3;
            const uint4* sh = reinterpret_cast<const uint4*>(Whi + (size_t)(cb + n) * K + k0);
            const uint4* sl = reinterpret_cast<const uint4*>(Whi + loN + (size_t)(cb + n) * K + k0);
            *reinterpret_cast<uint4*>(&Bh[n][part * 8]) = sh[part];
            *reinterpret_cast<uint4*>(&Bl[n][part * 8]) = sl[part];
        }
        #pragma unroll
        for (int i = 0; i < 2; i++) {
            int idx = tid + i * 256;
            int r = idx >> 3, kg = idx & 7;
            int rr = row0 + r;
            float4 av = make_float4(0.f, 0.f, 0.f, 0.f);
            if (rr < M)
                av = *reinterpret_cast<const float4*>(&A[(size_t)rr * K + k0 + kg * 4]);
            unsigned h01, l01, h23, l23;
            split2(av.x, av.y, h01, l01);
            split2(av.z, av.w, h23, l23);
            *reinterpret_cast<uint2*>(&Ah[r][kg * 4]) = make_uint2(h01, h23);
            *reinterpret_cast<uint2*>(&Al[r][kg * 4]) = make_uint2(l01, l23);
        }
        __syncthreads();

        #pragma unroll
        for (int ks = 0; ks < 2; ks++) {
            unsigned ah[4], al[4];
            ldsm4(ah, aAh + ks * 32);
            ldsm4(al, aAl + ks * 32);
            #pragma unroll
            for (int np = 0; np < 4; np++) {
                unsigned bh[4], bl[4];
                ldsm4(bh, aBh + np * 1280 + ks * 32);
                ldsm4(bl, aBl + np * 1280 + ks * 32);
                mma_bf16(c[2 * np],     ah, bh);
                mma_bf16(c[2 * np],     ah, bl);
                mma_bf16(c[2 * np],     al, bh);
                mma_bf16(c[2 * np + 1], ah, bh + 2);
                mma_bf16(c[2 * np + 1], ah, bl + 2);
                mma_bf16(c[2 * np + 1], al, bh + 2);
            }
        }
        __syncthreads();
    }

    int colb = cb + wn * 64 + (lane & 3) * 2;
    int lr0 = wm * 16 + (lane >> 2);
    int r0g = row0 + lr0;
    int r1g = r0g + 8;
    bool v0 = r0g < M, v1 = r1g < M;

    if (mode == 5) {
        float s0 = 0.f, q0 = 0.f, s1 = 0.f, q1 = 0.f;
        #pragma unroll
        for (int nt = 0; nt < 8; nt++) {
            int col = colb + nt * 8;
            float2 bv = *reinterpret_cast<const float2*>(&bias[col]);
            float2 rA = v0 ? *reinterpret_cast<const float2*>(&R[(size_t)r0g * 128 + col]) : make_float2(0.f, 0.f);
            float2 rB = v1 ? *reinterpret_cast<const float2*>(&R[(size_t)r1g * 128 + col]) : make_float2(0.f, 0.f);
            c[nt][0] += bv.x + rA.x; c[nt][1] += bv.y + rA.y;
            c[nt][2] += bv.x + rB.x; c[nt][3] += bv.y + rB.y;
            s0 += c[nt][0] + c[nt][1]; q0 += c[nt][0] * c[nt][0] + c[nt][1] * c[nt][1];
            s1 += c[nt][2] + c[nt][3]; q1 += c[nt][2] * c[nt][2] + c[nt][3] * c[nt][3];
        }
        #pragma unroll
        for (int o = 1; o <= 2; o <<= 1) {
            s0 += __shfl_xor_sync(0xffffffff, s0, o);
            q0 += __shfl_xor_sync(0xffffffff, q0, o);
            s1 += __shfl_xor_sync(0xffffffff, s1, o);
            q1 += __shfl_xor_sync(0xffffffff, q1, o);
        }
        if ((lane & 3) == 0) {
            Sred[wn][lr0] = s0; Qred[wn][lr0] = q0;
            Sred[wn][lr0 + 8] = s1; Qred[wn][lr0 + 8] = q1;
        }
        __syncthreads();
        float S0 = Sred[0][lr0] + Sred[1][lr0];
        float Q0 = Qred[0][lr0] + Qred[1][lr0];
        float S1 = Sred[0][lr0 + 8] + Sred[1][lr0 + 8];
        float Q1 = Qred[0][lr0 + 8] + Qred[1][lr0 + 8];
        float m0 = S0 * (1.f / 128.f), var0 = Q0 * (1.f / 128.f) - m0 * m0;
        float m1 = S1 * (1.f / 128.f), var1 = Q1 * (1.f / 128.f) - m1 * m1;
        float rs0 = rsqrtf(var0 + 1e-5f), rs1 = rsqrtf(var1 + 1e-5f);
        #pragma unroll
        for (int nt = 0; nt < 8; nt++) {
            int col = colb + nt * 8;
            float2 g = *reinterpret_cast<const float2*>(&lnG[col]);
            float2 be = *reinterpret_cast<const float2*>(&lnB[col]);
            if (v0) {
                float2 o = make_float2((c[nt][0] - m0) * rs0 * g.x + be.x,
                                       (c[nt][1] - m0) * rs0 * g.y + be.y);
                *reinterpret_cast<float2*>(&C[(size_t)r0g * 128 + col]) = o;
            }
            if (v1) {
                float2 o = make_float2((c[nt][2] - m1) * rs1 * g.x + be.x,
                                       (c[nt][3] - m1) * rs1 * g.y + be.y);
                *reinterpret_cast<float2*>(&C[(size_t)r1g * 128 + col]) = o;
            }
        }
    } else {
        #pragma unroll
        for (int nt = 0; nt < 8; nt++) {
            int col = colb + nt * 8;
            float2 bv = *reinterpret_cast<const float2*>(&bias[col]);
            float x0 = c[nt][0] + bv.x, x1 = c[nt][1] + bv.y;
            float x2 = c[nt][2] + bv.x, x3 = c[nt][3] + bv.y;
            if (mode == 1) {
                x0 = fmaxf(x0, 0.f); x1 = fmaxf(x1, 0.f);
                x2 = fmaxf(x2, 0.f); x3 = fmaxf(x3, 0.f);
            }
            if (v0) *reinterpret_cast<float2*>(&C[(size_t)r0g * NOUT + col]) = make_float2(x0, x1);
            if (v1) *reinterpret_cast<float2*>(&C[(size_t)r1g * NOUT + col]) = make_float2(x2, x3);
        }
    }
}

template<int K, int NOUT>
__global__ void __launch_bounds__(256) mma_gemm_kernel(
    const float* __restrict__ Aext, int Aid,
    unsigned woff, int loN,
    const float* __restrict__ bias,
    int Rid, const float* __restrict__ Rext,
    const float* __restrict__ lnG, const float* __restrict__ lnB,
    float* __restrict__ Cext, int Cid, int M, int mode)
{
    const float* A = Aext ? Aext : bufptr(Aid);
    float*       C = Cext ? Cext : bufptr(Cid);
    const float* R = nullptr;
    if (mode == 5) R = Rext ? Rext : bufptr(Rid);
    int cb = (NOUT > 128) ? blockIdx.y * 128 : 0;
    mma_core<K, NOUT>(A, g_wbf + woff, loN, bias, R, lnG, lnB, C, M, mode, cb);
}

// ------------------------------ attention (f32x2, split dot chain) ------------------------------
__global__ void __launch_bounds__(256) attn_kernel(int unused)
{
    __shared__ __align__(16) float Ks[LSEQ * DK];
    __shared__ __align__(16) float Vs[LSEQ * DK];
    int b = blockIdx.x >> 3;
    int h = blockIdx.x & 7;
    int tid = threadIdx.x;
    int base = (b * LSEQ) * D + h * DK;

    for (int idx = tid; idx < LSEQ * DK; idx += 256) {
        int m = idx >> 4, j = idx & 15;
        Ks[idx] = g_k[base + m * D + j];
        Vs[idx] = g_v[base + m * D + j];
    }
    __syncthreads();

    unsigned long long q2[8];
    {
        const unsigned long long* qp = reinterpret_cast<const unsigned long long*>(g_q + base + tid * D);
        #pragma unroll
        for (int j = 0; j < 8; j++) q2[j] = qp[j];
    }

    unsigned long long acc[8];
    const unsigned long long z2 = pack2(0.f, 0.f);
    #pragma unroll
    for (int j = 0; j < 8; j++) acc[j] = z2;
    float mx = -3.0e38f, sum = 0.f;

    const unsigned long long* Ks2 = reinterpret_cast<const unsigned long long*>(Ks);
    const unsigned long long* Vs2 = reinterpret_cast<const unsigned long long*>(Vs);

    for (int m = 0; m < LSEQ; m++) {
        unsigned long long d2a = z2, d2b = z2;
        #pragma unroll
        for (int j = 0; j < 4; j++) {
            ffma2(d2a, q2[j],     Ks2[m * 8 + j]);
            ffma2(d2b, q2[j + 4], Ks2[m * 8 + j + 4]);
        }
        float la, ha, lb, hb;
        unpack2(d2a, la, ha);
        unpack2(d2b, lb, hb);
        float s = ((la + lb) + (ha + hb)) * 0.25f;

        if (s <= mx) {
            float pe = __expf(s - mx);
            sum += pe;
            unsigned long long pe2 = pack2(pe, pe);
            #pragma unroll
            for (int j = 0; j < 8; j++)
                ffma2(acc[j], Vs2[m * 8 + j], pe2);
        } else {
            float corr = __expf(mx - s);
            sum = sum * corr + 1.f;
            unsigned long long c2 = pack2(corr, corr);
            #pragma unroll
            for (int j = 0; j < 8; j++) {
                unsigned long long t;
                fmul2(t, acc[j], c2);
                fadd2(acc[j], t, Vs2[m * 8 + j]);
            }
            mx = s;
        }
    }

    float inv = 1.f / sum;
    float* op = g_o + base + tid * D;
    #pragma unroll
    for (int j = 0; j < 8; j++) {
        float lo, hi;
        unpack2(acc[j], lo, hi);
        op[j * 2 + 0] = lo * inv;
        op[j * 2 + 1] = hi * inv;
    }
}

// ------------------------------ launch ------------------------------
extern "C" void kernel_launch(void* const* d_in, const int* in_sizes, int n_in,
                              void* d_out, int out_size)
{
    const float* ego    = (const float*)d_in[0];
    const float* vals   = (const float*)d_in[1];
    const float* W1     = (const float*)d_in[2];
    const float* b1     = (const float*)d_in[3];
    const float* W2     = (const float*)d_in[4];
    const float* b2     = (const float*)d_in[5];
    const float* enc_in = (const float*)d_in[6];
    const float* wq     = (const float*)d_in[7];
    const float* bq     = (const float*)d_in[8];
    const float* wk     = (const float*)d_in[9];
    const float* bk     = (const float*)d_in[10];
    const float* wv     = (const float*)d_in[11];
    const float* bv     = (const float*)d_in[12];
    const float* wo     = (const float*)d_in[13];
    const float* bo     = (const float*)d_in[14];
    const float* ln1_g  = (const float*)d_in[15];
    const float* ln1_b  = (const float*)d_in[16];
    const float* cw1    = (const float*)d_in[17];
    const float* cb1    = (const float*)d_in[18];
    const float* cw2    = (const float*)d_in[19];
    const float* cb2    = (const float*)d_in[20];
    const float* ln2_g  = (const float*)d_in[21];
    const float* ln2_b  = (const float*)d_in[22];
    const int*   rows   = (const int*)d_in[23];
    const int*   cols   = (const int*)d_in[24];
    float* out = (float*)d_out;

    int Nego = in_sizes[0] / 128;       // 100000
    int nnz  = in_sizes[1];             // 2000000
    int Mt   = in_sizes[6] / 128;       // 8192
    int B    = Mt / LSEQ;               // 32
    int NL   = in_sizes[7] / (128 * 128);

    const int AGG_SMEM = 61440;
    cudaFuncSetAttribute(agg_mma_kernel, cudaFuncAttributeMaxDynamicSharedMemorySize, AGG_SMEM);

    cudaStream_t s2;
    cudaEvent_t ev_prep, ev_join;
    cudaStreamCreateWithFlags(&s2, cudaStreamNonBlocking);
    cudaEventCreateWithFlags(&ev_prep, cudaEventDisableTiming);
    cudaEventCreateWithFlags(&ev_join, cudaEventDisableTiming);

    // ---- side branch: zero + spmm (independent of prep) ----
    zero_side_kernel<<<1024, 256, 0, s2>>>((Nego * 128) / 4);
    int nwarps = (nnz + EPW - 1) / EPW;
    int spmm_blocks = (nwarps * 32 + 255) / 256;
    spmm_kernel<<<spmm_blocks, 256, 0, s2>>>(ego, vals, rows, cols, nnz);

    // ---- main: weight images; agg depends on g_wbf ----
    prep_w_kernel<<<dim3(64, 2 + 6 * NL), 256>>>(W1, W2, wq, wk, wv, wo, cw1, cw2, NL);
    cudaEventRecord(ev_prep, 0);
    cudaStreamWaitEvent(s2, ev_prep, 0);

    // ---- side branch: fused aggregator ----
    agg_mma_kernel<<<(Nego + 63) / 64, 256, AGG_SMEM, s2>>>(ego, b1, b2, out, Nego);

    // ---- transformer encoder (main stream) ----
    const float* xin_ext = enc_in;
    int xin_id = -1;
    int gb  = Mt / 64;    // 128
    int gb2 = Mt / 128;   // 64

    for (int i = 0; i < NL; i++) {
        unsigned lbase = 65536u + (unsigned)i * 393216u;
        const float* bq_ = bq + i * D;
        const float* bk_ = bk + i * D;
        const float* bv_ = bv + i * D;
        const float* bo_ = bo + i * D;
        const float* g1_ = ln1_g + i * D;  const float* be1_ = ln1_b + i * D;
        const float* cb1_ = cb1 + i * DI;
        const float* cb2_ = cb2 + i * D;
        const float* g2_ = ln2_g + i * D;  const float* be2_ = ln2_b + i * D;

        // QKV (128m core, grid.y = 3)
        mma_qkv_kernel<<<dim3(gb2, 3), 256>>>(xin_ext, xin_id, lbase, bq_, bk_, bv_, Mt);
        attn_kernel<<<B * 8, 256>>>(0);
        // wo + residual + LN1 -> BX1 (64m core)
        mma_gemm_kernel<128, 128><<<gb, 256>>>(nullptr, BO, lbase + 3u * 32768u, 16384, bo_,
                                               xin_id, xin_ext, g1_, be1_, nullptr, BX1, Mt, 5);
        // FFN1 relu -> BH (128m core, grid.y = 4)
        mma_ffn1_kernel<<<dim3(gb2, 4), 256>>>(BX1, lbase + 131072u, cb1_, Mt);
        // FFN2 + residual(BX1) + LN2 -> BX2 (64m core)
        bool last = (i == NL - 1);
        mma_gemm_kernel<512, 128><<<gb, 256>>>(nullptr, BH, lbase + 262144u, 65536, cb2_,
                                               BX1, nullptr, g2_, be2_,
                                               last ? (out + (size_t)in_sizes[0]) : nullptr,
                                               BX2, Mt, 5);
        xin_ext = nullptr;
        xin_id = BX2;
    }

    // join
    cudaEventRecord(ev_join, s2);
    cudaStreamWaitEvent((cudaStream_t)0, ev_join, 0);
}